// round 1
// baseline (speedup 1.0000x reference)
#include <cuda_runtime.h>
#include <cstddef>

#define NN 50000
#define NE 400000
#define HH 128
#define H2 256
#define BN_EPS 1e-5f

// ---------------- scratch (static device allocations; allowed) ----------------
static __device__ float g_S [(size_t)NN * HH];   // node accumulator (S, then edge2node)
static __device__ float g_X0[(size_t)NE * H2];   // concat input for e0 MLP
static __device__ float g_Hb[(size_t)NE * H2];   // hidden buffer (raw, pre-BN)
static __device__ float g_EN[(size_t)NE * HH];   // edge_new
static __device__ float g_Y [(size_t)NE * HH];   // second-layer raw output (pre-BN)
static __device__ float g_NI[(size_t)NN * HH];   // node_in
static __device__ float g_sum[H2];
static __device__ float g_ss [H2];
static __device__ float g_scale[H2];
static __device__ float g_shift[H2];

static inline long cdivl(long a, long b) { return (a + b - 1) / b; }

// ---------------- misc kernels ----------------
__global__ void zero_f4(float4* p, int n4) {
    int i = blockIdx.x * blockDim.x + threadIdx.x;
    if (i < n4) p[i] = make_float4(0.f, 0.f, 0.f, 0.f);
}

__global__ void zero_stats() {
    int c = threadIdx.x;
    g_sum[c] = 0.f;
    g_ss[c]  = 0.f;
}

// scatter: S[n] += edge_rep over src and dst endpoints
__global__ void scatter_edge(const float* __restrict__ edge_rep,
                             const int* __restrict__ src,
                             const int* __restrict__ dst,
                             float* __restrict__ S) {
    int tid = blockIdx.x * blockDim.x + threadIdx.x;   // NE*32 threads
    if (tid >= NE * 32) return;
    int e = tid >> 5, q = tid & 31;
    float4 v = reinterpret_cast<const float4*>(edge_rep)[(size_t)e * 32 + q];
    int s = src[e], d = dst[e];
    float* ps = S + (size_t)s * HH + q * 4;
    atomicAdd(ps + 0, v.x); atomicAdd(ps + 1, v.y);
    atomicAdd(ps + 2, v.z); atomicAdd(ps + 3, v.w);
    float* pd = S + (size_t)d * HH + q * 4;
    atomicAdd(pd + 0, v.x); atomicAdd(pd + 1, v.y);
    atomicAdd(pd + 2, v.z); atomicAdd(pd + 3, v.w);
}

// X0[e] = [ node_rep[src]+node_rep[dst] , S[src]+S[dst] ]
__global__ void build_x0(const float* __restrict__ node_rep,
                         const float* __restrict__ S,
                         const int* __restrict__ src,
                         const int* __restrict__ dst,
                         float* __restrict__ X0) {
    int tid = blockIdx.x * blockDim.x + threadIdx.x;   // NE*32 threads
    if (tid >= NE * 32) return;
    int e = tid >> 5, q = tid & 31;
    int s = src[e], d = dst[e];
    const float4* nr4 = reinterpret_cast<const float4*>(node_rep);
    const float4* S4  = reinterpret_cast<const float4*>(S);
    float4 a0 = nr4[(size_t)s * 32 + q], a1 = nr4[(size_t)d * 32 + q];
    float4 b0 = S4 [(size_t)s * 32 + q], b1 = S4 [(size_t)d * 32 + q];
    float4 a = make_float4(a0.x + a1.x, a0.y + a1.y, a0.z + a1.z, a0.w + a1.w);
    float4 b = make_float4(b0.x + b1.x, b0.y + b1.y, b0.z + b1.z, b0.w + b1.w);
    float4* X4 = reinterpret_cast<float4*>(X0);
    X4[(size_t)e * 64 + q]      = a;
    X4[(size_t)e * 64 + 32 + q] = b;
}

// ---------------- GEMM: C[R,Ncols] = op(A)[R,K] @ W[K,Ncols] ----------------
// op(A) = relu(A*scale+shift) when applyA (BN+ReLU of previous layer fused).
// 128x128 tile, BK=16, 256 threads, 8x8 per thread.
__global__ void __launch_bounds__(256, 2)
gemm_bn(const float* __restrict__ A, const float* __restrict__ W,
        float* __restrict__ C, int R, int K, int Ncols, int applyA) {
    __shared__ float As[16][128];
    __shared__ float Ws[16][128];
    const int tid = threadIdx.x;
    const int bm = blockIdx.y * 128;
    const int bn = blockIdx.x * 128;
    const int ty = tid >> 4, tx = tid & 15;

    float acc[8][8];
#pragma unroll
    for (int i = 0; i < 8; i++)
#pragma unroll
        for (int j = 0; j < 8; j++) acc[i][j] = 0.f;

    for (int k0 = 0; k0 < K; k0 += 16) {
#pragma unroll
        for (int j = 0; j < 2; j++) {
            int i = tid + j * 256;
            int row = i >> 2, kv = (i & 3) << 2;
            int gr = bm + row;
            float4 v = make_float4(0.f, 0.f, 0.f, 0.f);
            if (gr < R) v = *reinterpret_cast<const float4*>(A + (size_t)gr * K + k0 + kv);
            if (applyA) {
                v.x = fmaxf(0.f, fmaf(v.x, g_scale[k0 + kv + 0], g_shift[k0 + kv + 0]));
                v.y = fmaxf(0.f, fmaf(v.y, g_scale[k0 + kv + 1], g_shift[k0 + kv + 1]));
                v.z = fmaxf(0.f, fmaf(v.z, g_scale[k0 + kv + 2], g_shift[k0 + kv + 2]));
                v.w = fmaxf(0.f, fmaf(v.w, g_scale[k0 + kv + 3], g_shift[k0 + kv + 3]));
            }
            As[kv + 0][row] = v.x; As[kv + 1][row] = v.y;
            As[kv + 2][row] = v.z; As[kv + 3][row] = v.w;
        }
#pragma unroll
        for (int j = 0; j < 2; j++) {
            int i = tid + j * 256;
            int kk = i >> 5, nv = (i & 31) << 2;
            *reinterpret_cast<float4*>(&Ws[kk][nv]) =
                *reinterpret_cast<const float4*>(W + (size_t)(k0 + kk) * Ncols + bn + nv);
        }
        __syncthreads();
#pragma unroll
        for (int kk = 0; kk < 16; kk++) {
            float a[8], b[8];
            *reinterpret_cast<float4*>(a)     = *reinterpret_cast<const float4*>(&As[kk][ty * 8]);
            *reinterpret_cast<float4*>(a + 4) = *reinterpret_cast<const float4*>(&As[kk][ty * 8 + 4]);
            *reinterpret_cast<float4*>(b)     = *reinterpret_cast<const float4*>(&Ws[kk][tx * 8]);
            *reinterpret_cast<float4*>(b + 4) = *reinterpret_cast<const float4*>(&Ws[kk][tx * 8 + 4]);
#pragma unroll
            for (int i = 0; i < 8; i++)
#pragma unroll
                for (int j = 0; j < 8; j++) acc[i][j] = fmaf(a[i], b[j], acc[i][j]);
        }
        __syncthreads();
    }
#pragma unroll
    for (int i = 0; i < 8; i++) {
        int gr = bm + ty * 8 + i;
        if (gr < R) {
            float* cp = C + (size_t)gr * Ncols + bn + tx * 8;
            *reinterpret_cast<float4*>(cp)     = make_float4(acc[i][0], acc[i][1], acc[i][2], acc[i][3]);
            *reinterpret_cast<float4*>(cp + 4) = make_float4(acc[i][4], acc[i][5], acc[i][6], acc[i][7]);
        }
    }
}

// ---------------- BN statistics ----------------
// one thread per column; each block reduces 256 rows then atomically folds in
__global__ void colstats(const float* __restrict__ M, int R, int C) {
    int c  = threadIdx.x;
    int r0 = blockIdx.x * 256;
    int r1 = min(R, r0 + 256);
    float s0 = 0.f, s1 = 0.f, q0 = 0.f, q1 = 0.f;
    int r = r0;
    for (; r + 1 < r1; r += 2) {
        float v0 = M[(size_t)r * C + c];
        float v1 = M[(size_t)(r + 1) * C + c];
        s0 += v0; q0 = fmaf(v0, v0, q0);
        s1 += v1; q1 = fmaf(v1, v1, q1);
    }
    if (r < r1) {
        float v = M[(size_t)r * C + c];
        s0 += v; q0 = fmaf(v, v, q0);
    }
    atomicAdd(&g_sum[c], s0 + s1);
    atomicAdd(&g_ss[c],  q0 + q1);
}

__global__ void bn_finalize(const float* __restrict__ G, const float* __restrict__ B,
                            float Rinv) {
    int c = threadIdx.x;
    float mean = g_sum[c] * Rinv;
    float var  = g_ss[c] * Rinv - mean * mean;
    float s    = G[c] / sqrtf(var + BN_EPS);
    g_scale[c] = s;
    g_shift[c] = fmaf(-mean, s, B[c]);
}

// ---------------- epilogue / elementwise kernels ----------------
// edge_new = (1+eps1)*edge_rep + relu(Y*s+t)
__global__ void make_edge_new(const float* __restrict__ edge_rep,
                              const float* __restrict__ Y,
                              const float* __restrict__ eps1,
                              float* __restrict__ out) {
    int i = blockIdx.x * blockDim.x + threadIdx.x;   // NE*32
    if (i >= NE * 32) return;
    int h = (i & 31) * 4;
    float c = 1.f + eps1[0];
    float4 y = reinterpret_cast<const float4*>(Y)[i];
    float4 e = reinterpret_cast<const float4*>(edge_rep)[i];
    float4 o;
    o.x = fmaf(c, e.x, fmaxf(0.f, fmaf(y.x, g_scale[h + 0], g_shift[h + 0])));
    o.y = fmaf(c, e.y, fmaxf(0.f, fmaf(y.y, g_scale[h + 1], g_shift[h + 1])));
    o.z = fmaf(c, e.z, fmaxf(0.f, fmaf(y.z, g_scale[h + 2], g_shift[h + 2])));
    o.w = fmaf(c, e.w, fmaxf(0.f, fmaf(y.w, g_scale[h + 3], g_shift[h + 3])));
    reinterpret_cast<float4*>(out)[i] = o;
}

// out = relu(Y*s+t)
__global__ void apply_out(const float* __restrict__ Y, float* __restrict__ out, int nvec) {
    int i = blockIdx.x * blockDim.x + threadIdx.x;
    if (i >= nvec) return;
    int h = (i & 31) * 4;
    float4 y = reinterpret_cast<const float4*>(Y)[i];
    float4 o;
    o.x = fmaxf(0.f, fmaf(y.x, g_scale[h + 0], g_shift[h + 0]));
    o.y = fmaxf(0.f, fmaf(y.y, g_scale[h + 1], g_shift[h + 1]));
    o.z = fmaxf(0.f, fmaf(y.z, g_scale[h + 2], g_shift[h + 2]));
    o.w = fmaxf(0.f, fmaf(y.w, g_scale[h + 3], g_shift[h + 3]));
    reinterpret_cast<float4*>(out)[i] = o;
}

// S[n] += relu(Y*s+t) at src and dst  (e2 output never materialized)
__global__ void scatter_bnrelu(const float* __restrict__ Y,
                               const int* __restrict__ src,
                               const int* __restrict__ dst,
                               float* __restrict__ S) {
    int tid = blockIdx.x * blockDim.x + threadIdx.x;   // NE*32
    if (tid >= NE * 32) return;
    int e = tid >> 5, q = tid & 31;
    int h = q * 4;
    float4 y = reinterpret_cast<const float4*>(Y)[(size_t)e * 32 + q];
    float v0 = fmaxf(0.f, fmaf(y.x, g_scale[h + 0], g_shift[h + 0]));
    float v1 = fmaxf(0.f, fmaf(y.y, g_scale[h + 1], g_shift[h + 1]));
    float v2 = fmaxf(0.f, fmaf(y.z, g_scale[h + 2], g_shift[h + 2]));
    float v3 = fmaxf(0.f, fmaf(y.w, g_scale[h + 3], g_shift[h + 3]));
    int s = src[e], d = dst[e];
    float* ps = S + (size_t)s * HH + h;
    atomicAdd(ps + 0, v0); atomicAdd(ps + 1, v1);
    atomicAdd(ps + 2, v2); atomicAdd(ps + 3, v3);
    float* pd = S + (size_t)d * HH + h;
    atomicAdd(pd + 0, v0); atomicAdd(pd + 1, v1);
    atomicAdd(pd + 2, v2); atomicAdd(pd + 3, v3);
}

// node_in = (1+eps2-degree)*node_rep + S
__global__ void make_node_in(const float* __restrict__ node_rep,
                             const float* __restrict__ degree,
                             const float* __restrict__ S,
                             const float* __restrict__ eps2,
                             float* __restrict__ out) {
    int i = blockIdx.x * blockDim.x + threadIdx.x;   // NN*32
    if (i >= NN * 32) return;
    int n = i >> 5;
    float c = 1.f + eps2[0] - degree[n];
    float4 a = reinterpret_cast<const float4*>(node_rep)[i];
    float4 s = reinterpret_cast<const float4*>(S)[i];
    reinterpret_cast<float4*>(out)[i] =
        make_float4(fmaf(c, a.x, s.x), fmaf(c, a.y, s.y),
                    fmaf(c, a.z, s.z), fmaf(c, a.w, s.w));
}

// ---------------- host orchestration ----------------
static void run_mlp(const float* X, int R, int K,
                    const float* W1, const float* G1, const float* B1,
                    const float* W2, const float* G2, const float* B2,
                    float* Hb, float* Y) {
    float Rinv = 1.0f / (float)R;
    // layer 1: Hb = X @ W1  (raw)
    zero_stats<<<1, H2>>>();
    {
        dim3 g(H2 / 128, (unsigned)cdivl(R, 128));
        gemm_bn<<<g, 256>>>(X, W1, Hb, R, K, H2, 0);
    }
    colstats<<<(unsigned)cdivl(R, 256), H2>>>(Hb, R, H2);
    bn_finalize<<<1, H2>>>(G1, B1, Rinv);
    // layer 2: Y = relu(BN(Hb)) @ W2  (BN+ReLU fused into A-load)
    zero_stats<<<1, H2>>>();
    {
        dim3 g(HH / 128, (unsigned)cdivl(R, 128));
        gemm_bn<<<g, 256>>>(Hb, W2, Y, R, H2, HH, 1);
    }
    colstats<<<(unsigned)cdivl(R, 256), HH>>>(Y, R, HH);
    bn_finalize<<<1, HH>>>(G2, B2, Rinv);
    // consumer applies relu(Y*g_scale+g_shift)
}

extern "C" void kernel_launch(void* const* d_in, const int* in_sizes, int n_in,
                              void* d_out, int out_size) {
    const float* node_rep = (const float*)d_in[0];
    const float* edge_rep = (const float*)d_in[1];
    const float* degree   = (const float*)d_in[2];
    const int*   src      = (const int*)  d_in[3];
    const int*   dst      = (const int*)  d_in[4];
    const float* eps1     = (const float*)d_in[5];
    const float* eps2     = (const float*)d_in[6];
    const float* nW1 = (const float*)d_in[7],  *nG1 = (const float*)d_in[8],  *nB1 = (const float*)d_in[9];
    const float* nW2 = (const float*)d_in[10], *nG2 = (const float*)d_in[11], *nB2 = (const float*)d_in[12];
    const float* e0W1 = (const float*)d_in[13], *e0G1 = (const float*)d_in[14], *e0B1 = (const float*)d_in[15];
    const float* e0W2 = (const float*)d_in[16], *e0G2 = (const float*)d_in[17], *e0B2 = (const float*)d_in[18];
    const float* e1W1 = (const float*)d_in[19], *e1G1 = (const float*)d_in[20], *e1B1 = (const float*)d_in[21];
    const float* e1W2 = (const float*)d_in[22], *e1G2 = (const float*)d_in[23], *e1B2 = (const float*)d_in[24];
    const float* e2W1 = (const float*)d_in[25], *e2G1 = (const float*)d_in[26], *e2B1 = (const float*)d_in[27];
    const float* e2W2 = (const float*)d_in[28], *e2G2 = (const float*)d_in[29], *e2B2 = (const float*)d_in[30];

    float* out_node = (float*)d_out;
    float* out_edge = out_node + (size_t)NN * HH;

    float *S, *X0, *Hb, *EN, *Y, *NI;
    cudaGetSymbolAddress((void**)&S,  g_S);
    cudaGetSymbolAddress((void**)&X0, g_X0);
    cudaGetSymbolAddress((void**)&Hb, g_Hb);
    cudaGetSymbolAddress((void**)&EN, g_EN);
    cudaGetSymbolAddress((void**)&Y,  g_Y);
    cudaGetSymbolAddress((void**)&NI, g_NI);

    const int EV = NE * 32;     // float4 lanes over [E,128]
    const int NV = NN * 32;     // float4 lanes over [N,128]

    // S = segsum(edge_rep, src) + segsum(edge_rep, dst)
    zero_f4<<<(unsigned)cdivl((long)NN * HH / 4, 256), 256>>>((float4*)S, NN * HH / 4);
    scatter_edge<<<(unsigned)cdivl(EV, 256), 256>>>(edge_rep, src, dst, S);
    // X0 = [node2edge | edge2edge]
    build_x0<<<(unsigned)cdivl(EV, 256), 256>>>(node_rep, S, src, dst, X0);

    // e0 MLP -> edge_new
    run_mlp(X0, NE, H2, e0W1, e0G1, e0B1, e0W2, e0G2, e0B2, Hb, Y);
    make_edge_new<<<(unsigned)cdivl(EV, 256), 256>>>(edge_rep, Y, eps1, EN);

    // e1 MLP -> edge_out
    run_mlp(EN, NE, HH, e1W1, e1G1, e1B1, e1W2, e1G2, e1B2, Hb, Y);
    apply_out<<<(unsigned)cdivl(EV, 256), 256>>>(Y, out_edge, EV);

    // e2 MLP -> scattered to nodes
    run_mlp(EN, NE, HH, e2W1, e2G1, e2B1, e2W2, e2G2, e2B2, Hb, Y);
    zero_f4<<<(unsigned)cdivl((long)NN * HH / 4, 256), 256>>>((float4*)S, NN * HH / 4);
    scatter_bnrelu<<<(unsigned)cdivl(EV, 256), 256>>>(Y, src, dst, S);

    // node_in, node MLP -> node_out
    make_node_in<<<(unsigned)cdivl(NV, 256), 256>>>(node_rep, degree, S, eps2, NI);
    run_mlp(NI, NN, HH, nW1, nG1, nB1, nW2, nG2, nB2, Hb, Y);
    apply_out<<<(unsigned)cdivl(NV, 256), 256>>>(Y, out_node, NV);
}

// round 3
// speedup vs baseline: 1.5799x; 1.5799x over previous
#include <cuda_runtime.h>
#include <cuda_bf16.h>
#include <cstdint>
#include <cstddef>

#define NN 50000
#define NE 400000
#define HH 128
#define H2 256
#define BN_EPS 1e-5f

// ---------------- scratch ----------------
static __device__ float g_S [(size_t)NN * HH];
static __device__ float g_X0[(size_t)NE * H2];
static __device__ float g_Hb[(size_t)NE * H2];
static __device__ float g_EN[(size_t)NE * HH];
static __device__ float g_Y [(size_t)NE * HH];
static __device__ float g_NI[(size_t)NN * HH];
static __device__ float g_sum[H2];
static __device__ float g_ss [H2];
static __device__ float g_scale[H2];
static __device__ float g_shift[H2];
static __device__ __nv_bfloat16 g_Whi[H2 * H2];   // transposed [N,K] bf16 hi
static __device__ __nv_bfloat16 g_Wlo[H2 * H2];   // transposed [N,K] bf16 lo

static inline long cdivl(long a, long b) { return (a + b - 1) / b; }

__device__ __forceinline__ uint32_t smem_to_u32(const void* p) {
    uint32_t a;
    asm("{ .reg .u64 t; cvta.to.shared.u64 t, %1; cvt.u32.u64 %0, t; }" : "=r"(a) : "l"(p));
    return a;
}

#define LDMX4(r, addr) \
    asm volatile("ldmatrix.sync.aligned.m8n8.x4.shared.b16 {%0,%1,%2,%3}, [%4];" \
        : "=r"((r)[0]), "=r"((r)[1]), "=r"((r)[2]), "=r"((r)[3]) : "r"(addr))

#define MMA16816(d, a, b0, b1) \
    asm volatile("mma.sync.aligned.m16n8k16.row.col.f32.bf16.bf16.f32 " \
        "{%0,%1,%2,%3},{%4,%5,%6,%7},{%8,%9},{%0,%1,%2,%3};" \
        : "+f"((d)[0]), "+f"((d)[1]), "+f"((d)[2]), "+f"((d)[3]) \
        : "r"((a)[0]), "r"((a)[1]), "r"((a)[2]), "r"((a)[3]), "r"(b0), "r"(b1))

// ---------------- misc kernels ----------------
__global__ void zero_f4(float4* p, int n4) {
    int i = blockIdx.x * blockDim.x + threadIdx.x;
    if (i < n4) p[i] = make_float4(0.f, 0.f, 0.f, 0.f);
}
__global__ void zero_stats() { int c = threadIdx.x; g_sum[c] = 0.f; g_ss[c] = 0.f; }

// weight split: W[K,N] fp32 -> transposed [N,K] bf16 hi/lo
__global__ void conv_w(const float* __restrict__ W, int K, int N) {
    int i = blockIdx.x * blockDim.x + threadIdx.x;
    if (i >= K * N) return;
    int k = i / N, n = i % N;
    float w = W[i];
    __nv_bfloat16 h = __float2bfloat16(w);
    __nv_bfloat16 l = __float2bfloat16(w - __bfloat162float(h));
    g_Whi[(size_t)n * K + k] = h;
    g_Wlo[(size_t)n * K + k] = l;
}

__global__ void scatter_edge(const float* __restrict__ edge_rep,
                             const int* __restrict__ src, const int* __restrict__ dst,
                             float* __restrict__ S) {
    int tid = blockIdx.x * blockDim.x + threadIdx.x;
    if (tid >= NE * 32) return;
    int e = tid >> 5, q = tid & 31;
    float4 v = reinterpret_cast<const float4*>(edge_rep)[(size_t)e * 32 + q];
    int s = src[e], d = dst[e];
    float* ps = S + (size_t)s * HH + q * 4;
    atomicAdd(ps + 0, v.x); atomicAdd(ps + 1, v.y);
    atomicAdd(ps + 2, v.z); atomicAdd(ps + 3, v.w);
    float* pd = S + (size_t)d * HH + q * 4;
    atomicAdd(pd + 0, v.x); atomicAdd(pd + 1, v.y);
    atomicAdd(pd + 2, v.z); atomicAdd(pd + 3, v.w);
}

__global__ void build_x0(const float* __restrict__ node_rep, const float* __restrict__ S,
                         const int* __restrict__ src, const int* __restrict__ dst,
                         float* __restrict__ X0) {
    int tid = blockIdx.x * blockDim.x + threadIdx.x;
    if (tid >= NE * 32) return;
    int e = tid >> 5, q = tid & 31;
    int s = src[e], d = dst[e];
    const float4* nr4 = reinterpret_cast<const float4*>(node_rep);
    const float4* S4  = reinterpret_cast<const float4*>(S);
    float4 a0 = nr4[(size_t)s * 32 + q], a1 = nr4[(size_t)d * 32 + q];
    float4 b0 = S4 [(size_t)s * 32 + q], b1 = S4 [(size_t)d * 32 + q];
    float4* X4 = reinterpret_cast<float4*>(X0);
    X4[(size_t)e * 64 + q]      = make_float4(a0.x + a1.x, a0.y + a1.y, a0.z + a1.z, a0.w + a1.w);
    X4[(size_t)e * 64 + 32 + q] = make_float4(b0.x + b1.x, b0.y + b1.y, b0.z + b1.z, b0.w + b1.w);
}

// ---------------- HMMA GEMM: C[R,Ncols] = op(A)[R,K] @ W   (bf16x3) ----------------
// CTA tile 128x128, BK=64. 8 warps (4m x 2n), warp tile 32x64, mma.m16n8k16.
// Fused: optional BN+ReLU on A during fp32->bf16 hi/lo conversion; BN column
// stats (sum, sumsq) of C accumulated into g_sum/g_ss via smem + red.global.
__global__ void __launch_bounds__(256, 2)
gemm_mma(const float* __restrict__ A, const __nv_bfloat16* __restrict__ Bhi,
         const __nv_bfloat16* __restrict__ Blo, float* __restrict__ C,
         int R, int K, int Ncols, int applyBN) {
    extern __shared__ __align__(128) char sm[];
    __shared__ float s_csum[128];
    __shared__ float s_css [128];
    char* sAhi = sm;
    char* sAlo = sm + 16384;
    char* sBhi = sm + 32768;
    char* sBlo = sm + 49152;
    const uint32_t uAhi = smem_to_u32(sAhi);
    const uint32_t uAlo = uAhi + 16384;
    const uint32_t uBhi = uAhi + 32768;
    const uint32_t uBlo = uAhi + 49152;

    const int tid  = threadIdx.x;
    const int wid  = tid >> 5;
    const int lane = tid & 31;
    const int m0   = blockIdx.y * 128;
    const int bn   = blockIdx.x * 128;
    const int warp_m = (wid & 3) * 32;
    const int warp_n = (wid >> 2) * 64;

    if (tid < 128) { s_csum[tid] = 0.f; s_css[tid] = 0.f; }

    float acc[2][8][4];
#pragma unroll
    for (int mt = 0; mt < 2; mt++)
#pragma unroll
        for (int nt = 0; nt < 8; nt++)
#pragma unroll
            for (int j = 0; j < 4; j++) acc[mt][nt][j] = 0.f;

    const int nchunks = K >> 6;
    for (int kc = 0; kc < nchunks; kc++) {
        __syncthreads();
        // ---- fill A hi/lo (fp32 -> bf16 split, optional BN+ReLU) ----
        {
            const int row = tid >> 1;
            const int cb  = (tid & 1) * 32;
            const int gr  = m0 + row;
            const float* arow = A + (size_t)gr * K + kc * 64 + cb;
#pragma unroll
            for (int f = 0; f < 8; f++) {
                float4 v = make_float4(0.f, 0.f, 0.f, 0.f);
                if (gr < R) v = *reinterpret_cast<const float4*>(arow + f * 4);
                if (applyBN) {
                    int k = kc * 64 + cb + f * 4;
                    v.x = fmaxf(0.f, fmaf(v.x, g_scale[k + 0], g_shift[k + 0]));
                    v.y = fmaxf(0.f, fmaf(v.y, g_scale[k + 1], g_shift[k + 1]));
                    v.z = fmaxf(0.f, fmaf(v.z, g_scale[k + 2], g_shift[k + 2]));
                    v.w = fmaxf(0.f, fmaf(v.w, g_scale[k + 3], g_shift[k + 3]));
                }
                __nv_bfloat162 hxy = __floats2bfloat162_rn(v.x, v.y);
                __nv_bfloat162 hzw = __floats2bfloat162_rn(v.z, v.w);
                __nv_bfloat162 lxy = __floats2bfloat162_rn(v.x - __low2float(hxy),
                                                           v.y - __high2float(hxy));
                __nv_bfloat162 lzw = __floats2bfloat162_rn(v.z - __low2float(hzw),
                                                           v.w - __high2float(hzw));
                uint32_t off = row * 128 + (cb + f * 4) * 2;
                uint32_t sw  = off ^ ((off >> 3) & 0x70);
                *reinterpret_cast<uint2*>(sAhi + sw) =
                    make_uint2(*reinterpret_cast<uint32_t*>(&hxy),
                               *reinterpret_cast<uint32_t*>(&hzw));
                *reinterpret_cast<uint2*>(sAlo + sw) =
                    make_uint2(*reinterpret_cast<uint32_t*>(&lxy),
                               *reinterpret_cast<uint32_t*>(&lzw));
            }
        }
        // ---- fill B hi/lo (pre-split transposed weights, [N][K]) ----
        {
            const int n    = tid >> 1;
            const int half = tid & 1;
            const int ng   = bn + n;
            const float4* sh = reinterpret_cast<const float4*>(Bhi + (size_t)ng * K + kc * 64);
            const float4* sl = reinterpret_cast<const float4*>(Blo + (size_t)ng * K + kc * 64);
#pragma unroll
            for (int j = 0; j < 4; j++) {
                uint32_t off = n * 128 + half * 64 + j * 16;
                uint32_t sw  = off ^ ((off >> 3) & 0x70);
                *reinterpret_cast<float4*>(sBhi + sw) = sh[half * 4 + j];
                *reinterpret_cast<float4*>(sBlo + sw) = sl[half * 4 + j];
            }
        }
        __syncthreads();

        // ---- MMA over 4 k16-steps ----
#pragma unroll
        for (int s = 0; s < 4; s++) {
            const uint32_t kb = s * 32 + ((lane >> 4) << 4);
            uint32_t ah[2][4], al[2][4];
#pragma unroll
            for (int mt = 0; mt < 2; mt++) {
                uint32_t off = (warp_m + mt * 16 + (lane & 15)) * 128 + kb;
                uint32_t sw  = off ^ ((off >> 3) & 0x70);
                LDMX4(ah[mt], uAhi + sw);
                LDMX4(al[mt], uAlo + sw);
            }
#pragma unroll
            for (int h = 0; h < 2; h++) {
                uint32_t bh[2][4], bl[2][4];
#pragma unroll
                for (int t = 0; t < 2; t++) {
                    uint32_t off = (warp_n + (h * 2 + t) * 16 + (lane & 15)) * 128 + kb;
                    uint32_t sw  = off ^ ((off >> 3) & 0x70);
                    LDMX4(bh[t], uBhi + sw);
                    LDMX4(bl[t], uBlo + sw);
                }
#pragma unroll
                for (int mt = 0; mt < 2; mt++)
#pragma unroll
                    for (int q = 0; q < 4; q++) {
                        int nt = h * 4 + q;
                        int t = q >> 1, sel = q & 1;
                        MMA16816(acc[mt][nt], ah[mt], bh[t][sel], bh[t][sel + 2]);
                        MMA16816(acc[mt][nt], al[mt], bh[t][sel], bh[t][sel + 2]);
                        MMA16816(acc[mt][nt], ah[mt], bl[t][sel], bl[t][sel + 2]);
                    }
            }
        }
    }

    // ---- epilogue: store C + fused column stats ----
#pragma unroll
    for (int mt = 0; mt < 2; mt++) {
        const int row0 = m0 + warp_m + mt * 16 + (lane >> 2);
#pragma unroll
        for (int nt = 0; nt < 8; nt++) {
            float c0 = acc[mt][nt][0], c1 = acc[mt][nt][1];
            float c2 = acc[mt][nt][2], c3 = acc[mt][nt][3];
            const int col = warp_n + nt * 8 + (lane & 3) * 2;
            if (row0 < R)
                *reinterpret_cast<float2*>(C + (size_t)row0 * Ncols + bn + col) =
                    make_float2(c0, c1);
            if (row0 + 8 < R)
                *reinterpret_cast<float2*>(C + (size_t)(row0 + 8) * Ncols + bn + col) =
                    make_float2(c2, c3);
            // stats: OOB rows have acc==0 -> contribute nothing
            float se = c0 + c2, so = c1 + c3;
            float qe = fmaf(c0, c0, c2 * c2), qo = fmaf(c1, c1, c3 * c3);
#pragma unroll
            for (int off = 16; off >= 4; off >>= 1) {
                se += __shfl_down_sync(0xffffffffu, se, off);
                so += __shfl_down_sync(0xffffffffu, so, off);
                qe += __shfl_down_sync(0xffffffffu, qe, off);
                qo += __shfl_down_sync(0xffffffffu, qo, off);
            }
            if (lane < 4) {
                int c = warp_n + nt * 8 + lane * 2;
                atomicAdd(&s_csum[c], se); atomicAdd(&s_csum[c + 1], so);
                atomicAdd(&s_css [c], qe); atomicAdd(&s_css [c + 1], qo);
            }
        }
    }
    __syncthreads();
    if (tid < 256) {
        int c = tid & 127;
        if (tid < 128) atomicAdd(&g_sum[bn + c], s_csum[c]);
        else           atomicAdd(&g_ss [bn + c], s_css [c]);
    }
}

__global__ void bn_finalize(const float* __restrict__ G, const float* __restrict__ B, float Rinv) {
    int c = threadIdx.x;
    float mean = g_sum[c] * Rinv;
    float var  = g_ss[c] * Rinv - mean * mean;
    float s    = G[c] / sqrtf(var + BN_EPS);
    g_scale[c] = s;
    g_shift[c] = fmaf(-mean, s, B[c]);
}

// ---------------- epilogue / elementwise ----------------
__global__ void make_edge_new(const float* __restrict__ edge_rep, const float* __restrict__ Y,
                              const float* __restrict__ eps1, float* __restrict__ out) {
    int i = blockIdx.x * blockDim.x + threadIdx.x;
    if (i >= NE * 32) return;
    int h = (i & 31) * 4;
    float c = 1.f + eps1[0];
    float4 y = reinterpret_cast<const float4*>(Y)[i];
    float4 e = reinterpret_cast<const float4*>(edge_rep)[i];
    float4 o;
    o.x = fmaf(c, e.x, fmaxf(0.f, fmaf(y.x, g_scale[h + 0], g_shift[h + 0])));
    o.y = fmaf(c, e.y, fmaxf(0.f, fmaf(y.y, g_scale[h + 1], g_shift[h + 1])));
    o.z = fmaf(c, e.z, fmaxf(0.f, fmaf(y.z, g_scale[h + 2], g_shift[h + 2])));
    o.w = fmaf(c, e.w, fmaxf(0.f, fmaf(y.w, g_scale[h + 3], g_shift[h + 3])));
    reinterpret_cast<float4*>(out)[i] = o;
}

__global__ void apply_out(const float* __restrict__ Y, float* __restrict__ out, int nvec) {
    int i = blockIdx.x * blockDim.x + threadIdx.x;
    if (i >= nvec) return;
    int h = (i & 31) * 4;
    float4 y = reinterpret_cast<const float4*>(Y)[i];
    float4 o;
    o.x = fmaxf(0.f, fmaf(y.x, g_scale[h + 0], g_shift[h + 0]));
    o.y = fmaxf(0.f, fmaf(y.y, g_scale[h + 1], g_shift[h + 1]));
    o.z = fmaxf(0.f, fmaf(y.z, g_scale[h + 2], g_shift[h + 2]));
    o.w = fmaxf(0.f, fmaf(y.w, g_scale[h + 3], g_shift[h + 3]));
    reinterpret_cast<float4*>(out)[i] = o;
}

__global__ void scatter_bnrelu(const float* __restrict__ Y, const int* __restrict__ src,
                               const int* __restrict__ dst, float* __restrict__ S) {
    int tid = blockIdx.x * blockDim.x + threadIdx.x;
    if (tid >= NE * 32) return;
    int e = tid >> 5, q = tid & 31;
    int h = q * 4;
    float4 y = reinterpret_cast<const float4*>(Y)[(size_t)e * 32 + q];
    float v0 = fmaxf(0.f, fmaf(y.x, g_scale[h + 0], g_shift[h + 0]));
    float v1 = fmaxf(0.f, fmaf(y.y, g_scale[h + 1], g_shift[h + 1]));
    float v2 = fmaxf(0.f, fmaf(y.z, g_scale[h + 2], g_shift[h + 2]));
    float v3 = fmaxf(0.f, fmaf(y.w, g_scale[h + 3], g_shift[h + 3]));
    int s = src[e], d = dst[e];
    float* ps = S + (size_t)s * HH + h;
    atomicAdd(ps + 0, v0); atomicAdd(ps + 1, v1);
    atomicAdd(ps + 2, v2); atomicAdd(ps + 3, v3);
    float* pd = S + (size_t)d * HH + h;
    atomicAdd(pd + 0, v0); atomicAdd(pd + 1, v1);
    atomicAdd(pd + 2, v2); atomicAdd(pd + 3, v3);
}

__global__ void make_node_in(const float* __restrict__ node_rep, const float* __restrict__ degree,
                             const float* __restrict__ S, const float* __restrict__ eps2,
                             float* __restrict__ out) {
    int i = blockIdx.x * blockDim.x + threadIdx.x;
    if (i >= NN * 32) return;
    int n = i >> 5;
    float c = 1.f + eps2[0] - degree[n];
    float4 a = reinterpret_cast<const float4*>(node_rep)[i];
    float4 s = reinterpret_cast<const float4*>(S)[i];
    reinterpret_cast<float4*>(out)[i] =
        make_float4(fmaf(c, a.x, s.x), fmaf(c, a.y, s.y), fmaf(c, a.z, s.z), fmaf(c, a.w, s.w));
}

// ---------------- host orchestration ----------------
#define GEMM_SMEM 65536

static void run_mlp(const float* X, int R, int K,
                    const float* W1, const float* G1, const float* B1,
                    const float* W2, const float* G2, const float* B2,
                    float* Hb, float* Y,
                    __nv_bfloat16* Whi, __nv_bfloat16* Wlo) {
    float Rinv = 1.0f / (float)R;
    unsigned gm = (unsigned)cdivl(R, 128);
    // layer 1: Hb = X @ W1 (raw), stats fused
    conv_w<<<(unsigned)cdivl((long)K * H2, 256), 256>>>(W1, K, H2);
    zero_stats<<<1, H2>>>();
    {
        dim3 g(H2 / 128, gm);
        gemm_mma<<<g, 256, GEMM_SMEM>>>(X, Whi, Wlo, Hb, R, K, H2, 0);
    }
    bn_finalize<<<1, H2>>>(G1, B1, Rinv);
    // layer 2: Y = relu(BN(Hb)) @ W2 (BN+ReLU fused into A conversion), stats fused
    conv_w<<<(unsigned)cdivl((long)H2 * HH, 256), 256>>>(W2, H2, HH);
    zero_stats<<<1, H2>>>();
    {
        dim3 g(HH / 128, gm);
        gemm_mma<<<g, 256, GEMM_SMEM>>>(Hb, Whi, Wlo, Y, R, H2, HH, 1);
    }
    bn_finalize<<<1, HH>>>(G2, B2, Rinv);
}

extern "C" void kernel_launch(void* const* d_in, const int* in_sizes, int n_in,
                              void* d_out, int out_size) {
    const float* node_rep = (const float*)d_in[0];
    const float* edge_rep = (const float*)d_in[1];
    const float* degree   = (const float*)d_in[2];
    const int*   src      = (const int*)  d_in[3];
    const int*   dst      = (const int*)  d_in[4];
    const float* eps1     = (const float*)d_in[5];
    const float* eps2     = (const float*)d_in[6];
    const float* nW1 = (const float*)d_in[7],  *nG1 = (const float*)d_in[8],  *nB1 = (const float*)d_in[9];
    const float* nW2 = (const float*)d_in[10], *nG2 = (const float*)d_in[11], *nB2 = (const float*)d_in[12];
    const float* e0W1 = (const float*)d_in[13], *e0G1 = (const float*)d_in[14], *e0B1 = (const float*)d_in[15];
    const float* e0W2 = (const float*)d_in[16], *e0G2 = (const float*)d_in[17], *e0B2 = (const float*)d_in[18];
    const float* e1W1 = (const float*)d_in[19], *e1G1 = (const float*)d_in[20], *e1B1 = (const float*)d_in[21];
    const float* e1W2 = (const float*)d_in[22], *e1G2 = (const float*)d_in[23], *e1B2 = (const float*)d_in[24];
    const float* e2W1 = (const float*)d_in[25], *e2G1 = (const float*)d_in[26], *e2B1 = (const float*)d_in[27];
    const float* e2W2 = (const float*)d_in[28], *e2G2 = (const float*)d_in[29], *e2B2 = (const float*)d_in[30];

    float* out_node = (float*)d_out;
    float* out_edge = out_node + (size_t)NN * HH;

    cudaFuncSetAttribute(gemm_mma, cudaFuncAttributeMaxDynamicSharedMemorySize, GEMM_SMEM);

    float *S, *X0, *Hb, *EN, *Y, *NI;
    __nv_bfloat16 *Whi, *Wlo;
    cudaGetSymbolAddress((void**)&S,  g_S);
    cudaGetSymbolAddress((void**)&X0, g_X0);
    cudaGetSymbolAddress((void**)&Hb, g_Hb);
    cudaGetSymbolAddress((void**)&EN, g_EN);
    cudaGetSymbolAddress((void**)&Y,  g_Y);
    cudaGetSymbolAddress((void**)&NI, g_NI);
    cudaGetSymbolAddress((void**)&Whi, g_Whi);
    cudaGetSymbolAddress((void**)&Wlo, g_Wlo);

    const int EV = NE * 32;
    const int NV = NN * 32;

    zero_f4<<<(unsigned)cdivl((long)NN * HH / 4, 256), 256>>>((float4*)S, NN * HH / 4);
    scatter_edge<<<(unsigned)cdivl(EV, 256), 256>>>(edge_rep, src, dst, S);
    build_x0<<<(unsigned)cdivl(EV, 256), 256>>>(node_rep, S, src, dst, X0);

    run_mlp(X0, NE, H2, e0W1, e0G1, e0B1, e0W2, e0G2, e0B2, Hb, Y, Whi, Wlo);
    make_edge_new<<<(unsigned)cdivl(EV, 256), 256>>>(edge_rep, Y, eps1, EN);

    run_mlp(EN, NE, HH, e1W1, e1G1, e1B1, e1W2, e1G2, e1B2, Hb, Y, Whi, Wlo);
    apply_out<<<(unsigned)cdivl(EV, 256), 256>>>(Y, out_edge, EV);

    run_mlp(EN, NE, HH, e2W1, e2G1, e2B1, e2W2, e2G2, e2B2, Hb, Y, Whi, Wlo);
    zero_f4<<<(unsigned)cdivl((long)NN * HH / 4, 256), 256>>>((float4*)S, NN * HH / 4);
    scatter_bnrelu<<<(unsigned)cdivl(EV, 256), 256>>>(Y, src, dst, S);

    make_node_in<<<(unsigned)cdivl(NV, 256), 256>>>(node_rep, degree, S, eps2, NI);
    run_mlp(NI, NN, HH, nW1, nG1, nB1, nW2, nG2, nB2, Hb, Y, Whi, Wlo);
    apply_out<<<(unsigned)cdivl(NV, 256), 256>>>(Y, out_node, NV);
}

// round 4
// speedup vs baseline: 1.6595x; 1.0504x over previous
#include <cuda_runtime.h>
#include <cuda_bf16.h>
#include <cstdint>
#include <cstddef>

#define NN 50000
#define NE 400000
#define HH 128
#define H2 256
#define BN_EPS 1e-5f

// ---------------- scratch ----------------
static __device__ float g_S [(size_t)NN * HH];
static __device__ float g_X0[(size_t)NE * H2];
static __device__ float g_Hb[(size_t)NE * H2];
static __device__ float g_EN[(size_t)NE * HH];
static __device__ float g_Y [(size_t)NE * HH];
static __device__ float g_NI[(size_t)NN * HH];
static __device__ float g_sum[H2];
static __device__ float g_ss [H2];
static __device__ float g_scale[H2];
static __device__ float g_shift[H2];
static __device__ __nv_bfloat16 g_Whi[H2 * H2];   // transposed [N,K] bf16 hi
static __device__ __nv_bfloat16 g_Wlo[H2 * H2];   // transposed [N,K] bf16 lo

static inline long cdivl(long a, long b) { return (a + b - 1) / b; }

__device__ __forceinline__ uint32_t smem_to_u32(const void* p) {
    uint32_t a;
    asm("{ .reg .u64 t; cvta.to.shared.u64 t, %1; cvt.u32.u64 %0, t; }" : "=r"(a) : "l"(p));
    return a;
}

#define LDMX4(r, addr) \
    asm volatile("ldmatrix.sync.aligned.m8n8.x4.shared.b16 {%0,%1,%2,%3}, [%4];" \
        : "=r"((r)[0]), "=r"((r)[1]), "=r"((r)[2]), "=r"((r)[3]) : "r"(addr))

#define MMA16816(d, a, b0, b1) \
    asm volatile("mma.sync.aligned.m16n8k16.row.col.f32.bf16.bf16.f32 " \
        "{%0,%1,%2,%3},{%4,%5,%6,%7},{%8,%9},{%0,%1,%2,%3};" \
        : "+f"((d)[0]), "+f"((d)[1]), "+f"((d)[2]), "+f"((d)[3]) \
        : "r"((a)[0]), "r"((a)[1]), "r"((a)[2]), "r"((a)[3]), "r"(b0), "r"(b1))

__device__ __forceinline__ void cp16(uint32_t dst, const void* src) {
    asm volatile("cp.async.cg.shared.global [%0], [%1], 16;" :: "r"(dst), "l"(src));
}
#define CP_COMMIT() asm volatile("cp.async.commit_group;" ::: "memory")
#define CP_WAIT0()  asm volatile("cp.async.wait_group 0;" ::: "memory")

__device__ __forceinline__ void red4(float* p, float a, float b, float c, float d) {
    asm volatile("red.global.add.v4.f32 [%0], {%1,%2,%3,%4};"
                 :: "l"(p), "f"(a), "f"(b), "f"(c), "f"(d) : "memory");
}

// ---------------- misc kernels ----------------
__global__ void zero_f4(float4* p, int n4) {
    int i = blockIdx.x * blockDim.x + threadIdx.x;
    if (i < n4) p[i] = make_float4(0.f, 0.f, 0.f, 0.f);
}
__global__ void zero_stats() { int c = threadIdx.x; g_sum[c] = 0.f; g_ss[c] = 0.f; }

// weight split: W[K,N] fp32 -> transposed [N,K] bf16 hi/lo
__global__ void conv_w(const float* __restrict__ W, int K, int N) {
    int i = blockIdx.x * blockDim.x + threadIdx.x;
    if (i >= K * N) return;
    int k = i / N, n = i % N;
    float w = W[i];
    __nv_bfloat16 h = __float2bfloat16(w);
    __nv_bfloat16 l = __float2bfloat16(w - __bfloat162float(h));
    g_Whi[(size_t)n * K + k] = h;
    g_Wlo[(size_t)n * K + k] = l;
}

__global__ void scatter_edge(const float* __restrict__ edge_rep,
                             const int* __restrict__ src, const int* __restrict__ dst,
                             float* __restrict__ S) {
    int tid = blockIdx.x * blockDim.x + threadIdx.x;
    if (tid >= NE * 32) return;
    int e = tid >> 5, q = tid & 31;
    float4 v = reinterpret_cast<const float4*>(edge_rep)[(size_t)e * 32 + q];
    int s = src[e], d = dst[e];
    red4(S + (size_t)s * HH + q * 4, v.x, v.y, v.z, v.w);
    red4(S + (size_t)d * HH + q * 4, v.x, v.y, v.z, v.w);
}

__global__ void build_x0(const float* __restrict__ node_rep, const float* __restrict__ S,
                         const int* __restrict__ src, const int* __restrict__ dst,
                         float* __restrict__ X0) {
    int tid = blockIdx.x * blockDim.x + threadIdx.x;
    if (tid >= NE * 32) return;
    int e = tid >> 5, q = tid & 31;
    int s = src[e], d = dst[e];
    const float4* nr4 = reinterpret_cast<const float4*>(node_rep);
    const float4* S4  = reinterpret_cast<const float4*>(S);
    float4 a0 = nr4[(size_t)s * 32 + q], a1 = nr4[(size_t)d * 32 + q];
    float4 b0 = S4 [(size_t)s * 32 + q], b1 = S4 [(size_t)d * 32 + q];
    float4* X4 = reinterpret_cast<float4*>(X0);
    X4[(size_t)e * 64 + q]      = make_float4(a0.x + a1.x, a0.y + a1.y, a0.z + a1.z, a0.w + a1.w);
    X4[(size_t)e * 64 + 32 + q] = make_float4(b0.x + b1.x, b0.y + b1.y, b0.z + b1.z, b0.w + b1.w);
}

// ---------------- HMMA GEMM, double-buffered pipeline (bf16x3) ----------------
// CTA tile 128x128, BK=64, 2 SMEM stages (64KB each). A: LDG->reg prefetch, fp32->
// bf16 hi/lo split (+ optional BN+ReLU) -> STS. B: cp.async from pre-split weights.
// One __syncthreads per chunk. Fused BN column stats into epilogue.
#define ST_AHI 0
#define ST_ALO 16384
#define ST_BHI 32768
#define ST_BLO 49152
#define STAGE  65536
#define GEMM_SMEM (2 * STAGE)

__global__ void __launch_bounds__(256, 1)
gemm_mma(const float* __restrict__ A, const __nv_bfloat16* __restrict__ Bhi,
         const __nv_bfloat16* __restrict__ Blo, float* __restrict__ C,
         int R, int K, int Ncols, int applyBN) {
    extern __shared__ __align__(128) char sm[];
    __shared__ float s_csum[128];
    __shared__ float s_css [128];
    const uint32_t uS = smem_to_u32(sm);

    const int tid  = threadIdx.x;
    const int wid  = tid >> 5;
    const int lane = tid & 31;
    const int m0   = blockIdx.y * 128;
    const int bn   = blockIdx.x * 128;
    const int warp_m = (wid & 3) * 32;
    const int warp_n = (wid >> 2) * 64;

    if (tid < 128) { s_csum[tid] = 0.f; s_css[tid] = 0.f; }

    float acc[2][8][4];
#pragma unroll
    for (int mt = 0; mt < 2; mt++)
#pragma unroll
        for (int nt = 0; nt < 8; nt++)
#pragma unroll
            for (int j = 0; j < 4; j++) acc[mt][nt][j] = 0.f;

    const int nchunks = K >> 6;
    // A prefetch registers (one 64-col chunk slice per thread: half a row)
    const int arow_i = tid >> 1;
    const int acb    = (tid & 1) * 32;
    const int agr    = m0 + arow_i;
    float4 areg[8];

    // ---- prologue: B[0] via cp.async, A[0] via LDG ----
    {
#pragma unroll
        for (int j = 0; j < 4; j++) {
            int p = tid + j * 256;             // 1024 x 16B pieces
            int n = p >> 3, f = p & 7;
            uint32_t off = n * 128 + f * 16;
            uint32_t sw  = off ^ ((off >> 3) & 0x70);
            cp16(uS + ST_BHI + sw, Bhi + (size_t)(bn + n) * K + f * 8);
            cp16(uS + ST_BLO + sw, Blo + (size_t)(bn + n) * K + f * 8);
        }
        CP_COMMIT();
        const float* ap = A + (size_t)agr * K + acb;
#pragma unroll
        for (int f = 0; f < 8; f++)
            areg[f] = (agr < R) ? *reinterpret_cast<const float4*>(ap + f * 4)
                                : make_float4(0.f, 0.f, 0.f, 0.f);
    }

    for (int kc = 0; kc < nchunks; kc++) {
        const int s = kc & 1;
        const uint32_t uStage = uS + s * STAGE;
        // ---- convert A regs -> smem stage s ----
#pragma unroll
        for (int f = 0; f < 8; f++) {
            float4 v = areg[f];
            if (applyBN) {
                int k = kc * 64 + acb + f * 4;
                v.x = fmaxf(0.f, fmaf(v.x, g_scale[k + 0], g_shift[k + 0]));
                v.y = fmaxf(0.f, fmaf(v.y, g_scale[k + 1], g_shift[k + 1]));
                v.z = fmaxf(0.f, fmaf(v.z, g_scale[k + 2], g_shift[k + 2]));
                v.w = fmaxf(0.f, fmaf(v.w, g_scale[k + 3], g_shift[k + 3]));
            }
            __nv_bfloat162 hxy = __floats2bfloat162_rn(v.x, v.y);
            __nv_bfloat162 hzw = __floats2bfloat162_rn(v.z, v.w);
            __nv_bfloat162 lxy = __floats2bfloat162_rn(v.x - __low2float(hxy),
                                                       v.y - __high2float(hxy));
            __nv_bfloat162 lzw = __floats2bfloat162_rn(v.z - __low2float(hzw),
                                                       v.w - __high2float(hzw));
            uint32_t off = arow_i * 128 + (acb + f * 4) * 2;
            uint32_t sw  = off ^ ((off >> 3) & 0x70);
            *reinterpret_cast<uint2*>(sm + s * STAGE + ST_AHI + sw) =
                make_uint2(*reinterpret_cast<uint32_t*>(&hxy),
                           *reinterpret_cast<uint32_t*>(&hzw));
            *reinterpret_cast<uint2*>(sm + s * STAGE + ST_ALO + sw) =
                make_uint2(*reinterpret_cast<uint32_t*>(&lxy),
                           *reinterpret_cast<uint32_t*>(&lzw));
        }
        // ---- prefetch next A chunk into regs (hidden behind MMA) ----
        if (kc + 1 < nchunks) {
            const float* ap = A + (size_t)agr * K + (kc + 1) * 64 + acb;
#pragma unroll
            for (int f = 0; f < 8; f++)
                areg[f] = (agr < R) ? *reinterpret_cast<const float4*>(ap + f * 4)
                                    : make_float4(0.f, 0.f, 0.f, 0.f);
        }
        CP_WAIT0();                 // B[kc] arrived
        __syncthreads();            // stage s fully built; prev readers done
        // ---- issue B[kc+1] into stage s^1 (after sync: prev MMA on s^1 done) ----
        if (kc + 1 < nchunks) {
            const uint32_t uN = uS + (s ^ 1) * STAGE;
#pragma unroll
            for (int j = 0; j < 4; j++) {
                int p = tid + j * 256;
                int n = p >> 3, f = p & 7;
                uint32_t off = n * 128 + f * 16;
                uint32_t sw  = off ^ ((off >> 3) & 0x70);
                const size_t gsrc = (size_t)(bn + n) * K + (kc + 1) * 64 + f * 8;
                cp16(uN + ST_BHI + sw, Bhi + gsrc);
                cp16(uN + ST_BLO + sw, Blo + gsrc);
            }
            CP_COMMIT();
        }
        // ---- MMA over 4 k16-steps on stage s ----
#pragma unroll
        for (int st = 0; st < 4; st++) {
            const uint32_t kb = st * 32 + ((lane >> 4) << 4);
            uint32_t ah[2][4], al[2][4];
#pragma unroll
            for (int mt = 0; mt < 2; mt++) {
                uint32_t off = (warp_m + mt * 16 + (lane & 15)) * 128 + kb;
                uint32_t sw  = off ^ ((off >> 3) & 0x70);
                LDMX4(ah[mt], uStage + ST_AHI + sw);
                LDMX4(al[mt], uStage + ST_ALO + sw);
            }
#pragma unroll
            for (int h = 0; h < 2; h++) {
                uint32_t bh[2][4], bl[2][4];
#pragma unroll
                for (int t = 0; t < 2; t++) {
                    uint32_t off = (warp_n + (h * 2 + t) * 16 + (lane & 15)) * 128 + kb;
                    uint32_t sw  = off ^ ((off >> 3) & 0x70);
                    LDMX4(bh[t], uStage + ST_BHI + sw);
                    LDMX4(bl[t], uStage + ST_BLO + sw);
                }
#pragma unroll
                for (int mt = 0; mt < 2; mt++)
#pragma unroll
                    for (int q = 0; q < 4; q++) {
                        int nt = h * 4 + q;
                        int t = q >> 1, sel = q & 1;
                        MMA16816(acc[mt][nt], ah[mt], bh[t][sel], bh[t][sel + 2]);
                        MMA16816(acc[mt][nt], al[mt], bh[t][sel], bh[t][sel + 2]);
                        MMA16816(acc[mt][nt], ah[mt], bl[t][sel], bl[t][sel + 2]);
                    }
            }
        }
    }

    // ---- epilogue: store C + fused column stats ----
#pragma unroll
    for (int mt = 0; mt < 2; mt++) {
        const int row0 = m0 + warp_m + mt * 16 + (lane >> 2);
#pragma unroll
        for (int nt = 0; nt < 8; nt++) {
            float c0 = acc[mt][nt][0], c1 = acc[mt][nt][1];
            float c2 = acc[mt][nt][2], c3 = acc[mt][nt][3];
            const int col = warp_n + nt * 8 + (lane & 3) * 2;
            if (row0 < R)
                *reinterpret_cast<float2*>(C + (size_t)row0 * Ncols + bn + col) =
                    make_float2(c0, c1);
            if (row0 + 8 < R)
                *reinterpret_cast<float2*>(C + (size_t)(row0 + 8) * Ncols + bn + col) =
                    make_float2(c2, c3);
            float se = c0 + c2, so = c1 + c3;
            float qe = fmaf(c0, c0, c2 * c2), qo = fmaf(c1, c1, c3 * c3);
#pragma unroll
            for (int off = 16; off >= 4; off >>= 1) {
                se += __shfl_down_sync(0xffffffffu, se, off);
                so += __shfl_down_sync(0xffffffffu, so, off);
                qe += __shfl_down_sync(0xffffffffu, qe, off);
                qo += __shfl_down_sync(0xffffffffu, qo, off);
            }
            if (lane < 4) {
                int c = warp_n + nt * 8 + lane * 2;
                atomicAdd(&s_csum[c], se); atomicAdd(&s_csum[c + 1], so);
                atomicAdd(&s_css [c], qe); atomicAdd(&s_css [c + 1], qo);
            }
        }
    }
    __syncthreads();
    if (tid < 256) {
        int c = tid & 127;
        if (tid < 128) atomicAdd(&g_sum[bn + c], s_csum[c]);
        else           atomicAdd(&g_ss [bn + c], s_css [c]);
    }
}

__global__ void bn_finalize(const float* __restrict__ G, const float* __restrict__ B, float Rinv) {
    int c = threadIdx.x;
    float mean = g_sum[c] * Rinv;
    float var  = g_ss[c] * Rinv - mean * mean;
    float s    = G[c] / sqrtf(var + BN_EPS);
    g_scale[c] = s;
    g_shift[c] = fmaf(-mean, s, B[c]);
}

// ---------------- epilogue / elementwise ----------------
__global__ void make_edge_new(const float* __restrict__ edge_rep, const float* __restrict__ Y,
                              const float* __restrict__ eps1, float* __restrict__ out) {
    int i = blockIdx.x * blockDim.x + threadIdx.x;
    if (i >= NE * 32) return;
    int h = (i & 31) * 4;
    float c = 1.f + eps1[0];
    float4 y = reinterpret_cast<const float4*>(Y)[i];
    float4 e = reinterpret_cast<const float4*>(edge_rep)[i];
    float4 o;
    o.x = fmaf(c, e.x, fmaxf(0.f, fmaf(y.x, g_scale[h + 0], g_shift[h + 0])));
    o.y = fmaf(c, e.y, fmaxf(0.f, fmaf(y.y, g_scale[h + 1], g_shift[h + 1])));
    o.z = fmaf(c, e.z, fmaxf(0.f, fmaf(y.z, g_scale[h + 2], g_shift[h + 2])));
    o.w = fmaf(c, e.w, fmaxf(0.f, fmaf(y.w, g_scale[h + 3], g_shift[h + 3])));
    reinterpret_cast<float4*>(out)[i] = o;
}

__global__ void apply_out(const float* __restrict__ Y, float* __restrict__ out, int nvec) {
    int i = blockIdx.x * blockDim.x + threadIdx.x;
    if (i >= nvec) return;
    int h = (i & 31) * 4;
    float4 y = reinterpret_cast<const float4*>(Y)[i];
    float4 o;
    o.x = fmaxf(0.f, fmaf(y.x, g_scale[h + 0], g_shift[h + 0]));
    o.y = fmaxf(0.f, fmaf(y.y, g_scale[h + 1], g_shift[h + 1]));
    o.z = fmaxf(0.f, fmaf(y.z, g_scale[h + 2], g_shift[h + 2]));
    o.w = fmaxf(0.f, fmaf(y.w, g_scale[h + 3], g_shift[h + 3]));
    reinterpret_cast<float4*>(out)[i] = o;
}

__global__ void scatter_bnrelu(const float* __restrict__ Y, const int* __restrict__ src,
                               const int* __restrict__ dst, float* __restrict__ S) {
    int tid = blockIdx.x * blockDim.x + threadIdx.x;
    if (tid >= NE * 32) return;
    int e = tid >> 5, q = tid & 31;
    int h = q * 4;
    float4 y = reinterpret_cast<const float4*>(Y)[(size_t)e * 32 + q];
    float v0 = fmaxf(0.f, fmaf(y.x, g_scale[h + 0], g_shift[h + 0]));
    float v1 = fmaxf(0.f, fmaf(y.y, g_scale[h + 1], g_shift[h + 1]));
    float v2 = fmaxf(0.f, fmaf(y.z, g_scale[h + 2], g_shift[h + 2]));
    float v3 = fmaxf(0.f, fmaf(y.w, g_scale[h + 3], g_shift[h + 3]));
    int s = src[e], d = dst[e];
    red4(S + (size_t)s * HH + h, v0, v1, v2, v3);
    red4(S + (size_t)d * HH + h, v0, v1, v2, v3);
}

__global__ void make_node_in(const float* __restrict__ node_rep, const float* __restrict__ degree,
                             const float* __restrict__ S, const float* __restrict__ eps2,
                             float* __restrict__ out) {
    int i = blockIdx.x * blockDim.x + threadIdx.x;
    if (i >= NN * 32) return;
    int n = i >> 5;
    float c = 1.f + eps2[0] - degree[n];
    float4 a = reinterpret_cast<const float4*>(node_rep)[i];
    float4 s = reinterpret_cast<const float4*>(S)[i];
    reinterpret_cast<float4*>(out)[i] =
        make_float4(fmaf(c, a.x, s.x), fmaf(c, a.y, s.y), fmaf(c, a.z, s.z), fmaf(c, a.w, s.w));
}

// ---------------- host orchestration ----------------
static void run_mlp(const float* X, int R, int K,
                    const float* W1, const float* G1, const float* B1,
                    const float* W2, const float* G2, const float* B2,
                    float* Hb, float* Y,
                    __nv_bfloat16* Whi, __nv_bfloat16* Wlo) {
    float Rinv = 1.0f / (float)R;
    unsigned gm = (unsigned)cdivl(R, 128);
    conv_w<<<(unsigned)cdivl((long)K * H2, 256), 256>>>(W1, K, H2);
    zero_stats<<<1, H2>>>();
    {
        dim3 g(H2 / 128, gm);
        gemm_mma<<<g, 256, GEMM_SMEM>>>(X, Whi, Wlo, Hb, R, K, H2, 0);
    }
    bn_finalize<<<1, H2>>>(G1, B1, Rinv);
    conv_w<<<(unsigned)cdivl((long)H2 * HH, 256), 256>>>(W2, H2, HH);
    zero_stats<<<1, H2>>>();
    {
        dim3 g(HH / 128, gm);
        gemm_mma<<<g, 256, GEMM_SMEM>>>(Hb, Whi, Wlo, Y, R, H2, HH, 1);
    }
    bn_finalize<<<1, HH>>>(G2, B2, Rinv);
}

extern "C" void kernel_launch(void* const* d_in, const int* in_sizes, int n_in,
                              void* d_out, int out_size) {
    const float* node_rep = (const float*)d_in[0];
    const float* edge_rep = (const float*)d_in[1];
    const float* degree   = (const float*)d_in[2];
    const int*   src      = (const int*)  d_in[3];
    const int*   dst      = (const int*)  d_in[4];
    const float* eps1     = (const float*)d_in[5];
    const float* eps2     = (const float*)d_in[6];
    const float* nW1 = (const float*)d_in[7],  *nG1 = (const float*)d_in[8],  *nB1 = (const float*)d_in[9];
    const float* nW2 = (const float*)d_in[10], *nG2 = (const float*)d_in[11], *nB2 = (const float*)d_in[12];
    const float* e0W1 = (const float*)d_in[13], *e0G1 = (const float*)d_in[14], *e0B1 = (const float*)d_in[15];
    const float* e0W2 = (const float*)d_in[16], *e0G2 = (const float*)d_in[17], *e0B2 = (const float*)d_in[18];
    const float* e1W1 = (const float*)d_in[19], *e1G1 = (const float*)d_in[20], *e1B1 = (const float*)d_in[21];
    const float* e1W2 = (const float*)d_in[22], *e1G2 = (const float*)d_in[23], *e1B2 = (const float*)d_in[24];
    const float* e2W1 = (const float*)d_in[25], *e2G1 = (const float*)d_in[26], *e2B1 = (const float*)d_in[27];
    const float* e2W2 = (const float*)d_in[28], *e2G2 = (const float*)d_in[29], *e2B2 = (const float*)d_in[30];

    float* out_node = (float*)d_out;
    float* out_edge = out_node + (size_t)NN * HH;

    cudaFuncSetAttribute(gemm_mma, cudaFuncAttributeMaxDynamicSharedMemorySize, GEMM_SMEM);

    float *S, *X0, *Hb, *EN, *Y, *NI;
    __nv_bfloat16 *Whi, *Wlo;
    cudaGetSymbolAddress((void**)&S,  g_S);
    cudaGetSymbolAddress((void**)&X0, g_X0);
    cudaGetSymbolAddress((void**)&Hb, g_Hb);
    cudaGetSymbolAddress((void**)&EN, g_EN);
    cudaGetSymbolAddress((void**)&Y,  g_Y);
    cudaGetSymbolAddress((void**)&NI, g_NI);
    cudaGetSymbolAddress((void**)&Whi, g_Whi);
    cudaGetSymbolAddress((void**)&Wlo, g_Wlo);

    const int EV = NE * 32;
    const int NV = NN * 32;

    zero_f4<<<(unsigned)cdivl((long)NN * HH / 4, 256), 256>>>((float4*)S, NN * HH / 4);
    scatter_edge<<<(unsigned)cdivl(EV, 256), 256>>>(edge_rep, src, dst, S);
    build_x0<<<(unsigned)cdivl(EV, 256), 256>>>(node_rep, S, src, dst, X0);

    run_mlp(X0, NE, H2, e0W1, e0G1, e0B1, e0W2, e0G2, e0B2, Hb, Y, Whi, Wlo);
    make_edge_new<<<(unsigned)cdivl(EV, 256), 256>>>(edge_rep, Y, eps1, EN);

    run_mlp(EN, NE, HH, e1W1, e1G1, e1B1, e1W2, e1G2, e1B2, Hb, Y, Whi, Wlo);
    apply_out<<<(unsigned)cdivl(EV, 256), 256>>>(Y, out_edge, EV);

    run_mlp(EN, NE, HH, e2W1, e2G1, e2B1, e2W2, e2G2, e2B2, Hb, Y, Whi, Wlo);
    zero_f4<<<(unsigned)cdivl((long)NN * HH / 4, 256), 256>>>((float4*)S, NN * HH / 4);
    scatter_bnrelu<<<(unsigned)cdivl(EV, 256), 256>>>(Y, src, dst, S);

    make_node_in<<<(unsigned)cdivl(NV, 256), 256>>>(node_rep, degree, S, eps2, NI);
    run_mlp(NI, NN, HH, nW1, nG1, nB1, nW2, nG2, nB2, Hb, Y, Whi, Wlo);
    apply_out<<<(unsigned)cdivl(NV, 256), 256>>>(Y, out_node, NV);
}

// round 5
// speedup vs baseline: 1.6993x; 1.0240x over previous
#include <cuda_runtime.h>
#include <cuda_bf16.h>
#include <cstdint>
#include <cstddef>

#define NN 50000
#define NE 400000
#define HH 128
#define H2 256
#define BN_EPS 1e-5f

// ---------------- scratch ----------------
static __device__ float g_S [(size_t)NN * HH];        // node accumulator
static __device__ float g_X0[(size_t)NE * H2];        // e0 input
static __device__ float g_Hb[(size_t)NE * 512];       // hidden (512-wide, ldc=512)
static __device__ float g_EN[(size_t)NE * HH];        // edge_new
static __device__ float g_Y [(size_t)NE * HH];        // L2 raw out (e0/e1/node)
static __device__ float g_Y2[(size_t)NE * HH];        // e2 L2 raw out
static __device__ float g_NI[(size_t)NN * HH];        // node_in
static __device__ float g_stats[8][2][256];           // per-gemm {sum, sumsq}
static __device__ __nv_bfloat16 g_Whi[294912];        // all weights, [N][K] bf16 hi
static __device__ __nv_bfloat16 g_Wlo[294912];        // lo

// weight segment table (K, N, elem offset); order: e0W1,e0W2,e1W1,e2W1,e1W2,e2W2,nW1,nW2
#define OFF_E0W1 0
#define OFF_E0W2 65536
#define OFF_E1W1 98304
#define OFF_E2W1 131072
#define OFF_E1W2 163840
#define OFF_E2W2 196608
#define OFF_NW1  229376
#define OFF_NW2  262144

static inline long cdivl(long a, long b) { return (a + b - 1) / b; }

__device__ __forceinline__ uint32_t smem_to_u32(const void* p) {
    uint32_t a;
    asm("{ .reg .u64 t; cvta.to.shared.u64 t, %1; cvt.u32.u64 %0, t; }" : "=r"(a) : "l"(p));
    return a;
}

#define LDMX4(r, addr) \
    asm volatile("ldmatrix.sync.aligned.m8n8.x4.shared.b16 {%0,%1,%2,%3}, [%4];" \
        : "=r"((r)[0]), "=r"((r)[1]), "=r"((r)[2]), "=r"((r)[3]) : "r"(addr))

#define MMA16816(d, a, b0, b1) \
    asm volatile("mma.sync.aligned.m16n8k16.row.col.f32.bf16.bf16.f32 " \
        "{%0,%1,%2,%3},{%4,%5,%6,%7},{%8,%9},{%0,%1,%2,%3};" \
        : "+f"((d)[0]), "+f"((d)[1]), "+f"((d)[2]), "+f"((d)[3]) \
        : "r"((a)[0]), "r"((a)[1]), "r"((a)[2]), "r"((a)[3]), "r"(b0), "r"(b1))

__device__ __forceinline__ void cp16(uint32_t dst, const void* src) {
    asm volatile("cp.async.cg.shared.global [%0], [%1], 16;" :: "r"(dst), "l"(src));
}
#define CP_COMMIT() asm volatile("cp.async.commit_group;" ::: "memory")
#define CP_WAIT0()  asm volatile("cp.async.wait_group 0;" ::: "memory")

__device__ __forceinline__ void red4(float* p, float a, float b, float c, float d) {
    asm volatile("red.global.add.v4.f32 [%0], {%1,%2,%3,%4};"
                 :: "l"(p), "f"(a), "f"(b), "f"(c), "f"(d) : "memory");
}

// ---------------- init: zero S + stats, convert/transpose/split all weights ----------------
#define NS4 ((NN * HH) / 4)
#define INIT_TOTAL (NS4 + 1024 + 294912)

__global__ void init_all(const float* w0, const float* w1, const float* w2, const float* w3,
                         const float* w4, const float* w5, const float* w6, const float* w7) {
    int gid = blockIdx.x * blockDim.x + threadIdx.x;
    if (gid < NS4) {
        reinterpret_cast<float4*>(g_S)[gid] = make_float4(0.f, 0.f, 0.f, 0.f);
        return;
    }
    gid -= NS4;
    if (gid < 1024) {
        reinterpret_cast<float4*>(g_stats)[gid] = make_float4(0.f, 0.f, 0.f, 0.f);
        return;
    }
    gid -= 1024;
    if (gid >= 294912) return;
    const float* ws[8] = {w0, w1, w2, w3, w4, w5, w6, w7};
    const int segSize[8] = {65536, 32768, 32768, 32768, 32768, 32768, 32768, 32768};
    const int segK[8]    = {256, 256, 128, 128, 256, 256, 128, 256};
    int seg = 0, base = 0, idx = gid;
#pragma unroll
    for (int s = 0; s < 8; s++) {
        if (idx < segSize[s]) { seg = s; break; }
        idx -= segSize[s];
        base += segSize[s];
    }
    int Kw = segK[seg];
    int Nw = segSize[seg] / Kw;
    int k = idx / Nw, n = idx % Nw;
    float w = ws[seg][idx];
    __nv_bfloat16 h = __float2bfloat16(w);
    __nv_bfloat16 l = __float2bfloat16(w - __bfloat162float(h));
    g_Whi[base + n * Kw + k] = h;
    g_Wlo[base + n * Kw + k] = l;
}

// ---------------- graph kernels ----------------
__global__ void zero_f4(float4* p, int n4) {
    int i = blockIdx.x * blockDim.x + threadIdx.x;
    if (i < n4) p[i] = make_float4(0.f, 0.f, 0.f, 0.f);
}

__global__ void scatter_edge(const float* __restrict__ edge_rep,
                             const int* __restrict__ src, const int* __restrict__ dst,
                             float* __restrict__ S) {
    int tid = blockIdx.x * blockDim.x + threadIdx.x;
    if (tid >= NE * 32) return;
    int e = tid >> 5, q = tid & 31;
    float4 v = reinterpret_cast<const float4*>(edge_rep)[(size_t)e * 32 + q];
    int s = src[e], d = dst[e];
    red4(S + (size_t)s * HH + q * 4, v.x, v.y, v.z, v.w);
    red4(S + (size_t)d * HH + q * 4, v.x, v.y, v.z, v.w);
}

__global__ void build_x0(const float* __restrict__ node_rep, const float* __restrict__ S,
                         const int* __restrict__ src, const int* __restrict__ dst,
                         float* __restrict__ X0) {
    int tid = blockIdx.x * blockDim.x + threadIdx.x;
    if (tid >= NE * 32) return;
    int e = tid >> 5, q = tid & 31;
    int s = src[e], d = dst[e];
    const float4* nr4 = reinterpret_cast<const float4*>(node_rep);
    const float4* S4  = reinterpret_cast<const float4*>(S);
    float4 a0 = nr4[(size_t)s * 32 + q], a1 = nr4[(size_t)d * 32 + q];
    float4 b0 = S4 [(size_t)s * 32 + q], b1 = S4 [(size_t)d * 32 + q];
    float4* X4 = reinterpret_cast<float4*>(X0);
    X4[(size_t)e * 64 + q]      = make_float4(a0.x + a1.x, a0.y + a1.y, a0.z + a1.z, a0.w + a1.w);
    X4[(size_t)e * 64 + 32 + q] = make_float4(b0.x + b1.x, b0.y + b1.y, b0.z + b1.z, b0.w + b1.w);
}

// ---------------- HMMA GEMM (bf16x3), CTA 128 x BN, warps 2m x 4n ----------------
// in-kernel BN scale prep (from stats slot of previous GEMM), fused BN+ReLU on A,
// fused column stats of C -> stats slot outSlotBase + columnBlock.
template<int BN>
__global__ void __launch_bounds__(256, 1)
gemm_mma(const float* __restrict__ A, int lda,
         const __nv_bfloat16* __restrict__ Bhi, const __nv_bfloat16* __restrict__ Blo,
         float* __restrict__ C, int ldc, int R, int K,
         int inSlot, int outSlotBase,
         const float* __restrict__ Gp, const float* __restrict__ Bp, float Rinv) {
    constexpr int WN   = BN / 4;          // warp n-width (64 or 32)
    constexpr int NT   = WN / 16;         // n16 tiles per warp (4 or 2)
    constexpr int BHIo = 32768;
    constexpr int BLOo = 32768 + BN * 128;
    constexpr int STG  = 32768 + 2 * BN * 128;

    extern __shared__ __align__(128) char sm[];
    __shared__ float s_scale[256], s_shift[256];
    __shared__ float s_csum[BN], s_css[BN];
    const uint32_t uS = smem_to_u32(sm);

    const int tid  = threadIdx.x;
    const int wid  = tid >> 5;
    const int lane = tid & 31;
    const int m0     = blockIdx.y * 128;
    const int bnBase = blockIdx.x * BN;
    const int wm = (wid & 1) * 64;
    const int wn = (wid >> 1) * WN;
    const bool applyBN = (inSlot >= 0);

    if (applyBN) {
        for (int c = tid; c < K; c += 256) {
            float mean = g_stats[inSlot][0][c] * Rinv;
            float var  = g_stats[inSlot][1][c] * Rinv - mean * mean;
            float s    = Gp[c] * rsqrtf(var + BN_EPS);
            s_scale[c] = s;
            s_shift[c] = fmaf(-mean, s, Bp[c]);
        }
    }
    for (int c = tid; c < BN; c += 256) { s_csum[c] = 0.f; s_css[c] = 0.f; }
    __syncthreads();

    float acc[4][2 * NT][4];
#pragma unroll
    for (int mt = 0; mt < 4; mt++)
#pragma unroll
        for (int nt = 0; nt < 2 * NT; nt++)
#pragma unroll
            for (int j = 0; j < 4; j++) acc[mt][nt][j] = 0.f;

    const int nchunks = K >> 6;
    const int arow_i = tid >> 1;              // 128 rows, 2 threads/row
    const int acb    = (tid & 1) * 32;
    const int agr    = m0 + arow_i;
    float4 areg[8];

    // prologue: B[0] cp.async + A[0] LDG
    {
#pragma unroll
        for (int j = 0; j < BN / 32; j++) {
            int p = tid + j * 256;
            int n = p >> 3, f = p & 7;
            uint32_t off = n * 128 + f * 16;
            uint32_t sw  = off ^ ((off >> 3) & 0x70);
            cp16(uS + BHIo + sw, Bhi + (size_t)(bnBase + n) * K + f * 8);
            cp16(uS + BLOo + sw, Blo + (size_t)(bnBase + n) * K + f * 8);
        }
        CP_COMMIT();
        const float* ap = A + (size_t)agr * lda + acb;
#pragma unroll
        for (int f = 0; f < 8; f++)
            areg[f] = (agr < R) ? *reinterpret_cast<const float4*>(ap + f * 4)
                                : make_float4(0.f, 0.f, 0.f, 0.f);
    }

    for (int kc = 0; kc < nchunks; kc++) {
        const int s = kc & 1;
        const uint32_t uStage = uS + s * STG;
        // convert A regs -> stage s
#pragma unroll
        for (int f = 0; f < 8; f++) {
            float4 v = areg[f];
            if (applyBN && agr < R) {
                int k = kc * 64 + acb + f * 4;
                v.x = fmaxf(0.f, fmaf(v.x, s_scale[k + 0], s_shift[k + 0]));
                v.y = fmaxf(0.f, fmaf(v.y, s_scale[k + 1], s_shift[k + 1]));
                v.z = fmaxf(0.f, fmaf(v.z, s_scale[k + 2], s_shift[k + 2]));
                v.w = fmaxf(0.f, fmaf(v.w, s_scale[k + 3], s_shift[k + 3]));
            }
            __nv_bfloat162 hxy = __floats2bfloat162_rn(v.x, v.y);
            __nv_bfloat162 hzw = __floats2bfloat162_rn(v.z, v.w);
            __nv_bfloat162 lxy = __floats2bfloat162_rn(v.x - __low2float(hxy),
                                                       v.y - __high2float(hxy));
            __nv_bfloat162 lzw = __floats2bfloat162_rn(v.z - __low2float(hzw),
                                                       v.w - __high2float(hzw));
            uint32_t off = arow_i * 128 + (acb + f * 4) * 2;
            uint32_t sw  = off ^ ((off >> 3) & 0x70);
            *reinterpret_cast<uint2*>(sm + s * STG + sw) =
                make_uint2(*reinterpret_cast<uint32_t*>(&hxy),
                           *reinterpret_cast<uint32_t*>(&hzw));
            *reinterpret_cast<uint2*>(sm + s * STG + 16384 + sw) =
                make_uint2(*reinterpret_cast<uint32_t*>(&lxy),
                           *reinterpret_cast<uint32_t*>(&lzw));
        }
        // prefetch next A chunk
        if (kc + 1 < nchunks) {
            const float* ap = A + (size_t)agr * lda + (kc + 1) * 64 + acb;
#pragma unroll
            for (int f = 0; f < 8; f++)
                areg[f] = (agr < R) ? *reinterpret_cast<const float4*>(ap + f * 4)
                                    : make_float4(0.f, 0.f, 0.f, 0.f);
        }
        CP_WAIT0();
        __syncthreads();
        // issue B[kc+1]
        if (kc + 1 < nchunks) {
            const uint32_t uN = uS + (s ^ 1) * STG;
#pragma unroll
            for (int j = 0; j < BN / 32; j++) {
                int p = tid + j * 256;
                int n = p >> 3, f = p & 7;
                uint32_t off = n * 128 + f * 16;
                uint32_t sw  = off ^ ((off >> 3) & 0x70);
                const size_t gsrc = (size_t)(bnBase + n) * K + (kc + 1) * 64 + f * 8;
                cp16(uN + BHIo + sw, Bhi + gsrc);
                cp16(uN + BLOo + sw, Blo + gsrc);
            }
            CP_COMMIT();
        }
        // MMA over 4 k16-steps
#pragma unroll
        for (int st = 0; st < 4; st++) {
            const uint32_t kb = st * 32 + ((lane >> 4) << 4);
            uint32_t ah[4][4], al[4][4];
#pragma unroll
            for (int mt = 0; mt < 4; mt++) {
                uint32_t off = (wm + mt * 16 + (lane & 15)) * 128 + kb;
                uint32_t sw  = off ^ ((off >> 3) & 0x70);
                LDMX4(ah[mt], uStage + sw);
                LDMX4(al[mt], uStage + 16384 + sw);
            }
            uint32_t bf[NT][4];
#pragma unroll
            for (int t = 0; t < NT; t++) {
                uint32_t off = (wn + t * 16 + (lane & 15)) * 128 + kb;
                uint32_t sw  = off ^ ((off >> 3) & 0x70);
                LDMX4(bf[t], uStage + BHIo + sw);
            }
#pragma unroll
            for (int mt = 0; mt < 4; mt++)
#pragma unroll
                for (int t = 0; t < NT; t++) {
                    MMA16816(acc[mt][t * 2 + 0], ah[mt], bf[t][0], bf[t][2]);
                    MMA16816(acc[mt][t * 2 + 1], ah[mt], bf[t][1], bf[t][3]);
                    MMA16816(acc[mt][t * 2 + 0], al[mt], bf[t][0], bf[t][2]);
                    MMA16816(acc[mt][t * 2 + 1], al[mt], bf[t][1], bf[t][3]);
                }
#pragma unroll
            for (int t = 0; t < NT; t++) {
                uint32_t off = (wn + t * 16 + (lane & 15)) * 128 + kb;
                uint32_t sw  = off ^ ((off >> 3) & 0x70);
                LDMX4(bf[t], uStage + BLOo + sw);
            }
#pragma unroll
            for (int mt = 0; mt < 4; mt++)
#pragma unroll
                for (int t = 0; t < NT; t++) {
                    MMA16816(acc[mt][t * 2 + 0], ah[mt], bf[t][0], bf[t][2]);
                    MMA16816(acc[mt][t * 2 + 1], ah[mt], bf[t][1], bf[t][3]);
                }
        }
    }

    // epilogue: store C + fused column stats
#pragma unroll
    for (int mt = 0; mt < 4; mt++) {
        const int row0 = m0 + wm + mt * 16 + (lane >> 2);
#pragma unroll
        for (int nt = 0; nt < 2 * NT; nt++) {
            float c0 = acc[mt][nt][0], c1 = acc[mt][nt][1];
            float c2 = acc[mt][nt][2], c3 = acc[mt][nt][3];
            const int cl = wn + nt * 8 + (lane & 3) * 2;
            if (row0 < R)
                *reinterpret_cast<float2*>(C + (size_t)row0 * ldc + bnBase + cl) =
                    make_float2(c0, c1);
            if (row0 + 8 < R)
                *reinterpret_cast<float2*>(C + (size_t)(row0 + 8) * ldc + bnBase + cl) =
                    make_float2(c2, c3);
            float se = c0 + c2, so = c1 + c3;
            float qe = fmaf(c0, c0, c2 * c2), qo = fmaf(c1, c1, c3 * c3);
#pragma unroll
            for (int off = 16; off >= 4; off >>= 1) {
                se += __shfl_down_sync(0xffffffffu, se, off);
                so += __shfl_down_sync(0xffffffffu, so, off);
                qe += __shfl_down_sync(0xffffffffu, qe, off);
                qo += __shfl_down_sync(0xffffffffu, qo, off);
            }
            if (lane < 4) {
                int c = wn + nt * 8 + lane * 2;
                atomicAdd(&s_csum[c], se); atomicAdd(&s_csum[c + 1], so);
                atomicAdd(&s_css [c], qe); atomicAdd(&s_css [c + 1], qo);
            }
        }
    }
    __syncthreads();
    for (int i = tid; i < 2 * BN; i += 256) {
        int c = (i < BN) ? i : i - BN;
        int colg = bnBase + c;
        int slot = outSlotBase + (colg >> 8);
        int colIn = colg & 255;
        if (i < BN) atomicAdd(&g_stats[slot][0][colIn], s_csum[c]);
        else        atomicAdd(&g_stats[slot][1][colIn], s_css[c]);
    }
}

// ---------------- consumers (inline BN finalize per block) ----------------
__device__ __forceinline__ void bn_prep128(float* sc, float* sh, int slot,
                                           const float* G, const float* B, float Rinv) {
    int t = threadIdx.x;
    if (t < 128) {
        float mean = g_stats[slot][0][t] * Rinv;
        float var  = g_stats[slot][1][t] * Rinv - mean * mean;
        float s    = G[t] * rsqrtf(var + BN_EPS);
        sc[t] = s;
        sh[t] = fmaf(-mean, s, B[t]);
    }
    __syncthreads();
}

__global__ void make_edge_new(const float* __restrict__ Y, const float* __restrict__ edge_rep,
                              const float* __restrict__ eps1, int slot,
                              const float* __restrict__ G, const float* __restrict__ B,
                              float Rinv, float* __restrict__ out) {
    __shared__ float sc[128], sh[128];
    bn_prep128(sc, sh, slot, G, B, Rinv);
    int i = blockIdx.x * 256 + threadIdx.x;
    if (i >= NE * 32) return;
    int h = (i & 31) * 4;
    float c = 1.f + eps1[0];
    float4 y = reinterpret_cast<const float4*>(Y)[i];
    float4 e = reinterpret_cast<const float4*>(edge_rep)[i];
    float4 o;
    o.x = fmaf(c, e.x, fmaxf(0.f, fmaf(y.x, sc[h + 0], sh[h + 0])));
    o.y = fmaf(c, e.y, fmaxf(0.f, fmaf(y.y, sc[h + 1], sh[h + 1])));
    o.z = fmaf(c, e.z, fmaxf(0.f, fmaf(y.z, sc[h + 2], sh[h + 2])));
    o.w = fmaf(c, e.w, fmaxf(0.f, fmaf(y.w, sc[h + 3], sh[h + 3])));
    reinterpret_cast<float4*>(out)[i] = o;
}

__global__ void apply_out(const float* __restrict__ Y, float* __restrict__ out, int nvec,
                          int slot, const float* __restrict__ G, const float* __restrict__ B,
                          float Rinv) {
    __shared__ float sc[128], sh[128];
    bn_prep128(sc, sh, slot, G, B, Rinv);
    int i = blockIdx.x * 256 + threadIdx.x;
    if (i >= nvec) return;
    int h = (i & 31) * 4;
    float4 y = reinterpret_cast<const float4*>(Y)[i];
    float4 o;
    o.x = fmaxf(0.f, fmaf(y.x, sc[h + 0], sh[h + 0]));
    o.y = fmaxf(0.f, fmaf(y.y, sc[h + 1], sh[h + 1]));
    o.z = fmaxf(0.f, fmaf(y.z, sc[h + 2], sh[h + 2]));
    o.w = fmaxf(0.f, fmaf(y.w, sc[h + 3], sh[h + 3]));
    reinterpret_cast<float4*>(out)[i] = o;
}

__global__ void scatter_bnrelu(const float* __restrict__ Y, const int* __restrict__ src,
                               const int* __restrict__ dst, float* __restrict__ S,
                               int slot, const float* __restrict__ G,
                               const float* __restrict__ B, float Rinv) {
    __shared__ float sc[128], sh[128];
    bn_prep128(sc, sh, slot, G, B, Rinv);
    int tid = blockIdx.x * 256 + threadIdx.x;
    if (tid >= NE * 32) return;
    int e = tid >> 5, q = tid & 31;
    int h = q * 4;
    float4 y = reinterpret_cast<const float4*>(Y)[(size_t)e * 32 + q];
    float v0 = fmaxf(0.f, fmaf(y.x, sc[h + 0], sh[h + 0]));
    float v1 = fmaxf(0.f, fmaf(y.y, sc[h + 1], sh[h + 1]));
    float v2 = fmaxf(0.f, fmaf(y.z, sc[h + 2], sh[h + 2]));
    float v3 = fmaxf(0.f, fmaf(y.w, sc[h + 3], sh[h + 3]));
    int s = src[e], d = dst[e];
    red4(S + (size_t)s * HH + h, v0, v1, v2, v3);
    red4(S + (size_t)d * HH + h, v0, v1, v2, v3);
}

__global__ void make_node_in(const float* __restrict__ node_rep, const float* __restrict__ degree,
                             const float* __restrict__ S, const float* __restrict__ eps2,
                             float* __restrict__ out) {
    int i = blockIdx.x * blockDim.x + threadIdx.x;
    if (i >= NN * 32) return;
    int n = i >> 5;
    float c = 1.f + eps2[0] - degree[n];
    float4 a = reinterpret_cast<const float4*>(node_rep)[i];
    float4 s = reinterpret_cast<const float4*>(S)[i];
    reinterpret_cast<float4*>(out)[i] =
        make_float4(fmaf(c, a.x, s.x), fmaf(c, a.y, s.y), fmaf(c, a.z, s.z), fmaf(c, a.w, s.w));
}

// ---------------- host ----------------
#define SMEM256 (2 * (32768 + 2 * 256 * 128))   // 196608
#define SMEM128 (2 * (32768 + 2 * 128 * 128))   // 131072

extern "C" void kernel_launch(void* const* d_in, const int* in_sizes, int n_in,
                              void* d_out, int out_size) {
    const float* node_rep = (const float*)d_in[0];
    const float* edge_rep = (const float*)d_in[1];
    const float* degree   = (const float*)d_in[2];
    const int*   src      = (const int*)  d_in[3];
    const int*   dst      = (const int*)  d_in[4];
    const float* eps1     = (const float*)d_in[5];
    const float* eps2     = (const float*)d_in[6];
    const float* nW1 = (const float*)d_in[7],  *nG1 = (const float*)d_in[8],  *nB1 = (const float*)d_in[9];
    const float* nW2 = (const float*)d_in[10], *nG2 = (const float*)d_in[11], *nB2 = (const float*)d_in[12];
    const float* e0W1 = (const float*)d_in[13], *e0G1 = (const float*)d_in[14], *e0B1 = (const float*)d_in[15];
    const float* e0W2 = (const float*)d_in[16], *e0G2 = (const float*)d_in[17], *e0B2 = (const float*)d_in[18];
    const float* e1W1 = (const float*)d_in[19], *e1G1 = (const float*)d_in[20], *e1B1 = (const float*)d_in[21];
    const float* e1W2 = (const float*)d_in[22], *e1G2 = (const float*)d_in[23], *e1B2 = (const float*)d_in[24];
    const float* e2W1 = (const float*)d_in[25], *e2G1 = (const float*)d_in[26], *e2B1 = (const float*)d_in[27];
    const float* e2W2 = (const float*)d_in[28], *e2G2 = (const float*)d_in[29], *e2B2 = (const float*)d_in[30];

    float* out_node = (float*)d_out;
    float* out_edge = out_node + (size_t)NN * HH;

    cudaFuncSetAttribute(gemm_mma<256>, cudaFuncAttributeMaxDynamicSharedMemorySize, SMEM256);
    cudaFuncSetAttribute(gemm_mma<128>, cudaFuncAttributeMaxDynamicSharedMemorySize, SMEM128);

    float *S, *X0, *Hb, *EN, *Y, *Y2, *NI;
    __nv_bfloat16 *Whi, *Wlo;
    cudaGetSymbolAddress((void**)&S,  g_S);
    cudaGetSymbolAddress((void**)&X0, g_X0);
    cudaGetSymbolAddress((void**)&Hb, g_Hb);
    cudaGetSymbolAddress((void**)&EN, g_EN);
    cudaGetSymbolAddress((void**)&Y,  g_Y);
    cudaGetSymbolAddress((void**)&Y2, g_Y2);
    cudaGetSymbolAddress((void**)&NI, g_NI);
    cudaGetSymbolAddress((void**)&Whi, g_Whi);
    cudaGetSymbolAddress((void**)&Wlo, g_Wlo);

    const int EV = NE * 32;
    const int NV = NN * 32;
    const float RinvE = 1.0f / (float)NE;
    const float RinvN = 1.0f / (float)NN;
    const unsigned gyE = (unsigned)cdivl(NE, 128);   // 3125
    const unsigned gyN = (unsigned)cdivl(NN, 128);   // 391

    // 1: init (S zero, stats zero, weight split)
    init_all<<<(unsigned)cdivl(INIT_TOTAL, 256), 256>>>(e0W1, e0W2, e1W1, e2W1,
                                                        e1W2, e2W2, nW1, nW2);
    // 2-3: graph gathers
    scatter_edge<<<(unsigned)cdivl(EV, 256), 256>>>(edge_rep, src, dst, S);
    build_x0<<<(unsigned)cdivl(EV, 256), 256>>>(node_rep, S, src, dst, X0);

    // 4: e0 L1  (X0[NE,256] @ W -> Hb[:,0:256]), stats slot 0
    gemm_mma<256><<<dim3(1, gyE), 256, SMEM256>>>(X0, H2, Whi + OFF_E0W1, Wlo + OFF_E0W1,
                                                  Hb, 512, NE, H2, -1, 0, e0G1, e0B1, RinvE);
    // 5: e0 L2  (BN(slot0) -> Y), stats slot 1
    gemm_mma<128><<<dim3(1, gyE), 256, SMEM128>>>(Hb, 512, Whi + OFF_E0W2, Wlo + OFF_E0W2,
                                                  Y, 128, NE, H2, 0, 1, e0G1, e0B1, RinvE);
    // 6: edge_new
    make_edge_new<<<(unsigned)cdivl(EV, 256), 256>>>(Y, edge_rep, eps1, 1, e0G2, e0B2,
                                                     RinvE, EN);
    // 7: merged e1L1+e2L1 (EN[NE,128] @ Wcat[512,128] -> Hb[:,0:512]), slots 2,3
    gemm_mma<256><<<dim3(2, gyE), 256, SMEM256>>>(EN, HH, Whi + OFF_E1W1, Wlo + OFF_E1W1,
                                                  Hb, 512, NE, HH, -1, 2, e1G1, e1B1, RinvE);
    // 8: e1 L2 (BN slot2 on Hb[:,0:256]) -> Y, slot 4
    gemm_mma<128><<<dim3(1, gyE), 256, SMEM128>>>(Hb, 512, Whi + OFF_E1W2, Wlo + OFF_E1W2,
                                                  Y, 128, NE, H2, 2, 4, e1G1, e1B1, RinvE);
    // 9: e2 L2 (BN slot3 on Hb[:,256:512]) -> Y2, slot 5
    gemm_mma<128><<<dim3(1, gyE), 256, SMEM128>>>(Hb + 256, 512, Whi + OFF_E2W2, Wlo + OFF_E2W2,
                                                  Y2, 128, NE, H2, 3, 5, e2G1, e2B1, RinvE);
    // 10: edge output
    apply_out<<<(unsigned)cdivl(EV, 256), 256>>>(Y, out_edge, EV, 4, e1G2, e1B2, RinvE);
    // 11-12: edge->node scatter of BN(Y2)
    zero_f4<<<(unsigned)cdivl((long)NN * HH / 4, 256), 256>>>((float4*)S, NN * HH / 4);
    scatter_bnrelu<<<(unsigned)cdivl(EV, 256), 256>>>(Y2, src, dst, S, 5, e2G2, e2B2, RinvE);
    // 13: node_in
    make_node_in<<<(unsigned)cdivl(NV, 256), 256>>>(node_rep, degree, S, eps2, NI);
    // 14: node L1 -> Hb[:,0:256], slot 6
    gemm_mma<256><<<dim3(1, gyN), 256, SMEM256>>>(NI, HH, Whi + OFF_NW1, Wlo + OFF_NW1,
                                                  Hb, 512, NN, HH, -1, 6, nG1, nB1, RinvN);
    // 15: node L2 (BN slot6) -> Y, slot 7
    gemm_mma<128><<<dim3(1, gyN), 256, SMEM128>>>(Hb, 512, Whi + OFF_NW2, Wlo + OFF_NW2,
                                                  Y, 128, NN, H2, 6, 7, nG1, nB1, RinvN);
    // 16: node output
    apply_out<<<(unsigned)cdivl(NV, 256), 256>>>(Y, out_node, NV, 7, nG2, nB2, RinvN);
}

// round 6
// speedup vs baseline: 1.9948x; 1.1739x over previous
#include <cuda_runtime.h>
#include <cuda_bf16.h>
#include <cstdint>
#include <cstddef>

#define NN 50000
#define NE 400000
#define HH 128
#define H2 256
#define BN_EPS 1e-5f

// ---------------- scratch ----------------
static __device__ float g_S [(size_t)NN * HH];
static __device__ float g_X0[(size_t)NE * H2];
static __device__ float g_Hb[(size_t)NE * 512];
static __device__ float g_EN[(size_t)NE * HH];
static __device__ float g_Y [(size_t)NE * HH];
static __device__ float g_Y2[(size_t)NE * HH];
static __device__ float g_NI[(size_t)NN * HH];
static __device__ float g_stats[8][2][256];
static __device__ __nv_bfloat16 g_Whi[294912];
static __device__ __nv_bfloat16 g_Wlo[294912];

#define OFF_E0W1 0
#define OFF_E0W2 65536
#define OFF_E1W1 98304
#define OFF_E2W1 131072
#define OFF_E1W2 163840
#define OFF_E2W2 196608
#define OFF_NW1  229376
#define OFF_NW2  262144

static inline long cdivl(long a, long b) { return (a + b - 1) / b; }

__device__ __forceinline__ uint32_t smem_to_u32(const void* p) {
    uint32_t a;
    asm("{ .reg .u64 t; cvta.to.shared.u64 t, %1; cvt.u32.u64 %0, t; }" : "=r"(a) : "l"(p));
    return a;
}

#define LDMX4(r, addr) \
    asm volatile("ldmatrix.sync.aligned.m8n8.x4.shared.b16 {%0,%1,%2,%3}, [%4];" \
        : "=r"((r)[0]), "=r"((r)[1]), "=r"((r)[2]), "=r"((r)[3]) : "r"(addr))

#define MMA16816(d, a, b0, b1) \
    asm volatile("mma.sync.aligned.m16n8k16.row.col.f32.bf16.bf16.f32 " \
        "{%0,%1,%2,%3},{%4,%5,%6,%7},{%8,%9},{%0,%1,%2,%3};" \
        : "+f"((d)[0]), "+f"((d)[1]), "+f"((d)[2]), "+f"((d)[3]) \
        : "r"((a)[0]), "r"((a)[1]), "r"((a)[2]), "r"((a)[3]), "r"(b0), "r"(b1))

__device__ __forceinline__ void cp16(uint32_t dst, const void* src) {
    asm volatile("cp.async.cg.shared.global [%0], [%1], 16;" :: "r"(dst), "l"(src));
}
#define CP_COMMIT() asm volatile("cp.async.commit_group;" ::: "memory")
#define CP_WAIT0()  asm volatile("cp.async.wait_group 0;" ::: "memory")

__device__ __forceinline__ void red4(float* p, float a, float b, float c, float d) {
    asm volatile("red.global.add.v4.f32 [%0], {%1,%2,%3,%4};"
                 :: "l"(p), "f"(a), "f"(b), "f"(c), "f"(d) : "memory");
}

// ---------------- init ----------------
#define NS4 ((NN * HH) / 4)
#define INIT_TOTAL (NS4 + 1024 + 294912)

__global__ void init_all(const float* w0, const float* w1, const float* w2, const float* w3,
                         const float* w4, const float* w5, const float* w6, const float* w7) {
    int gid = blockIdx.x * blockDim.x + threadIdx.x;
    if (gid < NS4) {
        reinterpret_cast<float4*>(g_S)[gid] = make_float4(0.f, 0.f, 0.f, 0.f);
        return;
    }
    gid -= NS4;
    if (gid < 1024) {
        reinterpret_cast<float4*>(g_stats)[gid] = make_float4(0.f, 0.f, 0.f, 0.f);
        return;
    }
    gid -= 1024;
    if (gid >= 294912) return;
    const float* ws[8] = {w0, w1, w2, w3, w4, w5, w6, w7};
    const int segSize[8] = {65536, 32768, 32768, 32768, 32768, 32768, 32768, 32768};
    const int segK[8]    = {256, 256, 128, 128, 256, 256, 128, 256};
    int seg = 0, base = 0, idx = gid;
#pragma unroll
    for (int s = 0; s < 8; s++) {
        if (idx < segSize[s]) { seg = s; break; }
        idx -= segSize[s];
        base += segSize[s];
    }
    int Kw = segK[seg];
    int Nw = segSize[seg] / Kw;
    int k = idx / Nw, n = idx % Nw;
    float w = ws[seg][idx];
    __nv_bfloat16 h = __float2bfloat16(w);
    __nv_bfloat16 l = __float2bfloat16(w - __bfloat162float(h));
    g_Whi[base + n * Kw + k] = h;
    g_Wlo[base + n * Kw + k] = l;
}

// ---------------- graph kernels ----------------
__global__ void zero_f4(float4* p, int n4) {
    int i = blockIdx.x * blockDim.x + threadIdx.x;
    if (i < n4) p[i] = make_float4(0.f, 0.f, 0.f, 0.f);
}

__global__ void scatter_edge(const float* __restrict__ edge_rep,
                             const int* __restrict__ src, const int* __restrict__ dst,
                             float* __restrict__ S) {
    int tid = blockIdx.x * blockDim.x + threadIdx.x;
    if (tid >= NE * 32) return;
    int e = tid >> 5, q = tid & 31;
    float4 v = reinterpret_cast<const float4*>(edge_rep)[(size_t)e * 32 + q];
    int s = src[e], d = dst[e];
    red4(S + (size_t)s * HH + q * 4, v.x, v.y, v.z, v.w);
    red4(S + (size_t)d * HH + q * 4, v.x, v.y, v.z, v.w);
}

__global__ void build_x0(const float* __restrict__ node_rep, const float* __restrict__ S,
                         const int* __restrict__ src, const int* __restrict__ dst,
                         float* __restrict__ X0) {
    int tid = blockIdx.x * blockDim.x + threadIdx.x;
    if (tid >= NE * 32) return;
    int e = tid >> 5, q = tid & 31;
    int s = src[e], d = dst[e];
    const float4* nr4 = reinterpret_cast<const float4*>(node_rep);
    const float4* S4  = reinterpret_cast<const float4*>(S);
    float4 a0 = nr4[(size_t)s * 32 + q], a1 = nr4[(size_t)d * 32 + q];
    float4 b0 = S4 [(size_t)s * 32 + q], b1 = S4 [(size_t)d * 32 + q];
    float4* X4 = reinterpret_cast<float4*>(X0);
    X4[(size_t)e * 64 + q]      = make_float4(a0.x + a1.x, a0.y + a1.y, a0.z + a1.z, a0.w + a1.w);
    X4[(size_t)e * 64 + 32 + q] = make_float4(b0.x + b1.x, b0.y + b1.y, b0.z + b1.z, b0.w + b1.w);
}

// ---------------- HMMA GEMM (bf16x3), 512 thr, CTA 128 x BN, warps 4m x 4n ----------------
template<int BN>
__global__ void __launch_bounds__(512, 1)
gemm_mma(const float* __restrict__ A, int lda,
         const __nv_bfloat16* __restrict__ Bhi, const __nv_bfloat16* __restrict__ Blo,
         float* __restrict__ C, int ldc, int R, int K,
         int inSlot, int outSlotBase,
         const float* __restrict__ Gp, const float* __restrict__ Bp, float Rinv) {
    constexpr int WN   = BN / 4;          // 64 or 32
    constexpr int NT16 = WN / 16;         // 4 or 2
    constexpr int BHIo = 32768;
    constexpr int BLOo = 32768 + BN * 128;
    constexpr int STG  = 32768 + 2 * BN * 128;

    extern __shared__ __align__(128) char sm[];
    __shared__ float s_scale[256], s_shift[256];
    __shared__ float s_csum[256], s_css[256];
    const uint32_t uS = smem_to_u32(sm);

    const int tid  = threadIdx.x;
    const int wid  = tid >> 5;
    const int lane = tid & 31;
    const int m0     = blockIdx.y * 128;
    const int bnBase = blockIdx.x * BN;
    const int wm = (wid & 3) * 32;
    const int wn = (wid >> 2) * WN;
    const bool applyBN = (inSlot >= 0);

    if (applyBN) {
        for (int c = tid; c < K; c += 512) {
            float mean = g_stats[inSlot][0][c] * Rinv;
            float var  = g_stats[inSlot][1][c] * Rinv - mean * mean;
            float s    = Gp[c] * rsqrtf(var + BN_EPS);
            s_scale[c] = s;
            s_shift[c] = fmaf(-mean, s, Bp[c]);
        }
    }
    for (int c = tid; c < BN; c += 512) { s_csum[c] = 0.f; s_css[c] = 0.f; }
    __syncthreads();

    float acc[2][2 * NT16][4];
#pragma unroll
    for (int mt = 0; mt < 2; mt++)
#pragma unroll
        for (int nt = 0; nt < 2 * NT16; nt++)
#pragma unroll
            for (int j = 0; j < 4; j++) acc[mt][nt][j] = 0.f;

    const int nchunks = K >> 6;
    const int arow_i = tid >> 2;              // 128 rows, 4 threads/row
    const int acb    = (tid & 3) * 16;
    const int agr    = m0 + arow_i;
    float4 areg[4];

    // prologue: B[0] cp.async + A[0] LDG
    {
#pragma unroll
        for (int j = 0; j < BN / 64; j++) {
            int p = tid + j * 512;
            int n = p >> 3, f = p & 7;
            uint32_t off = n * 128 + f * 16;
            uint32_t sw  = off ^ ((off >> 3) & 0x70);
            cp16(uS + BHIo + sw, Bhi + (size_t)(bnBase + n) * K + f * 8);
            cp16(uS + BLOo + sw, Blo + (size_t)(bnBase + n) * K + f * 8);
        }
        CP_COMMIT();
        const float* ap = A + (size_t)agr * lda + acb;
#pragma unroll
        for (int f = 0; f < 4; f++)
            areg[f] = (agr < R) ? *reinterpret_cast<const float4*>(ap + f * 4)
                                : make_float4(0.f, 0.f, 0.f, 0.f);
    }

    for (int kc = 0; kc < nchunks; kc++) {
        const int s = kc & 1;
        const uint32_t uStage = uS + s * STG;
        // convert A regs -> stage s
#pragma unroll
        for (int f = 0; f < 4; f++) {
            float4 v = areg[f];
            if (applyBN && agr < R) {
                int k = kc * 64 + acb + f * 4;
                v.x = fmaxf(0.f, fmaf(v.x, s_scale[k + 0], s_shift[k + 0]));
                v.y = fmaxf(0.f, fmaf(v.y, s_scale[k + 1], s_shift[k + 1]));
                v.z = fmaxf(0.f, fmaf(v.z, s_scale[k + 2], s_shift[k + 2]));
                v.w = fmaxf(0.f, fmaf(v.w, s_scale[k + 3], s_shift[k + 3]));
            }
            __nv_bfloat162 hxy = __floats2bfloat162_rn(v.x, v.y);
            __nv_bfloat162 hzw = __floats2bfloat162_rn(v.z, v.w);
            __nv_bfloat162 lxy = __floats2bfloat162_rn(v.x - __low2float(hxy),
                                                       v.y - __high2float(hxy));
            __nv_bfloat162 lzw = __floats2bfloat162_rn(v.z - __low2float(hzw),
                                                       v.w - __high2float(hzw));
            uint32_t off = arow_i * 128 + (acb + f * 4) * 2;
            uint32_t sw  = off ^ ((off >> 3) & 0x70);
            *reinterpret_cast<uint2*>(sm + s * STG + sw) =
                make_uint2(*reinterpret_cast<uint32_t*>(&hxy),
                           *reinterpret_cast<uint32_t*>(&hzw));
            *reinterpret_cast<uint2*>(sm + s * STG + 16384 + sw) =
                make_uint2(*reinterpret_cast<uint32_t*>(&lxy),
                           *reinterpret_cast<uint32_t*>(&lzw));
        }
        // prefetch next A chunk
        if (kc + 1 < nchunks) {
            const float* ap = A + (size_t)agr * lda + (kc + 1) * 64 + acb;
#pragma unroll
            for (int f = 0; f < 4; f++)
                areg[f] = (agr < R) ? *reinterpret_cast<const float4*>(ap + f * 4)
                                    : make_float4(0.f, 0.f, 0.f, 0.f);
        }
        CP_WAIT0();
        __syncthreads();
        // issue B[kc+1]
        if (kc + 1 < nchunks) {
            const uint32_t uN = uS + (s ^ 1) * STG;
#pragma unroll
            for (int j = 0; j < BN / 64; j++) {
                int p = tid + j * 512;
                int n = p >> 3, f = p & 7;
                uint32_t off = n * 128 + f * 16;
                uint32_t sw  = off ^ ((off >> 3) & 0x70);
                const size_t gsrc = (size_t)(bnBase + n) * K + (kc + 1) * 64 + f * 8;
                cp16(uN + BHIo + sw, Bhi + gsrc);
                cp16(uN + BLOo + sw, Blo + gsrc);
            }
            CP_COMMIT();
        }
        // MMA over 4 k16-steps
#pragma unroll
        for (int st = 0; st < 4; st++) {
            const uint32_t kb = st * 32 + ((lane >> 4) << 4);
            uint32_t ah[2][4], al[2][4];
#pragma unroll
            for (int mt = 0; mt < 2; mt++) {
                uint32_t off = (wm + mt * 16 + (lane & 15)) * 128 + kb;
                uint32_t sw  = off ^ ((off >> 3) & 0x70);
                LDMX4(ah[mt], uStage + sw);
                LDMX4(al[mt], uStage + 16384 + sw);
            }
            uint32_t bf[NT16][4];
#pragma unroll
            for (int t = 0; t < NT16; t++) {
                uint32_t off = (wn + t * 16 + (lane & 15)) * 128 + kb;
                uint32_t sw  = off ^ ((off >> 3) & 0x70);
                LDMX4(bf[t], uStage + BHIo + sw);
            }
#pragma unroll
            for (int mt = 0; mt < 2; mt++)
#pragma unroll
                for (int t = 0; t < NT16; t++) {
                    MMA16816(acc[mt][t * 2 + 0], ah[mt], bf[t][0], bf[t][2]);
                    MMA16816(acc[mt][t * 2 + 1], ah[mt], bf[t][1], bf[t][3]);
                    MMA16816(acc[mt][t * 2 + 0], al[mt], bf[t][0], bf[t][2]);
                    MMA16816(acc[mt][t * 2 + 1], al[mt], bf[t][1], bf[t][3]);
                }
#pragma unroll
            for (int t = 0; t < NT16; t++) {
                uint32_t off = (wn + t * 16 + (lane & 15)) * 128 + kb;
                uint32_t sw  = off ^ ((off >> 3) & 0x70);
                LDMX4(bf[t], uStage + BLOo + sw);
            }
#pragma unroll
            for (int mt = 0; mt < 2; mt++)
#pragma unroll
                for (int t = 0; t < NT16; t++) {
                    MMA16816(acc[mt][t * 2 + 0], ah[mt], bf[t][0], bf[t][2]);
                    MMA16816(acc[mt][t * 2 + 1], ah[mt], bf[t][1], bf[t][3]);
                }
        }
    }

    // epilogue: store C + fused column stats
#pragma unroll
    for (int mt = 0; mt < 2; mt++) {
        const int row0 = m0 + wm + mt * 16 + (lane >> 2);
#pragma unroll
        for (int nt = 0; nt < 2 * NT16; nt++) {
            float c0 = acc[mt][nt][0], c1 = acc[mt][nt][1];
            float c2 = acc[mt][nt][2], c3 = acc[mt][nt][3];
            const int cl = wn + nt * 8 + (lane & 3) * 2;
            if (row0 < R)
                *reinterpret_cast<float2*>(C + (size_t)row0 * ldc + bnBase + cl) =
                    make_float2(c0, c1);
            if (row0 + 8 < R)
                *reinterpret_cast<float2*>(C + (size_t)(row0 + 8) * ldc + bnBase + cl) =
                    make_float2(c2, c3);
            float se = c0 + c2, so = c1 + c3;
            float qe = fmaf(c0, c0, c2 * c2), qo = fmaf(c1, c1, c3 * c3);
#pragma unroll
            for (int off = 16; off >= 4; off >>= 1) {
                se += __shfl_down_sync(0xffffffffu, se, off);
                so += __shfl_down_sync(0xffffffffu, so, off);
                qe += __shfl_down_sync(0xffffffffu, qe, off);
                qo += __shfl_down_sync(0xffffffffu, qo, off);
            }
            if (lane < 4) {
                int c = wn + nt * 8 + lane * 2;
                atomicAdd(&s_csum[c], se); atomicAdd(&s_csum[c + 1], so);
                atomicAdd(&s_css [c], qe); atomicAdd(&s_css [c + 1], qo);
            }
        }
    }
    __syncthreads();
    for (int i = tid; i < 2 * BN; i += 512) {
        int c = (i < BN) ? i : i - BN;
        int colg = bnBase + c;
        int slot = outSlotBase + (colg >> 8);
        int colIn = colg & 255;
        if (i < BN) atomicAdd(&g_stats[slot][0][colIn], s_csum[c]);
        else        atomicAdd(&g_stats[slot][1][colIn], s_css[c]);
    }
}

// ---------------- consumers ----------------
__device__ __forceinline__ void bn_prep128(float* sc, float* sh, int slot,
                                           const float* G, const float* B, float Rinv) {
    int t = threadIdx.x;
    if (t < 128) {
        float mean = g_stats[slot][0][t] * Rinv;
        float var  = g_stats[slot][1][t] * Rinv - mean * mean;
        float s    = G[t] * rsqrtf(var + BN_EPS);
        sc[t] = s;
        sh[t] = fmaf(-mean, s, B[t]);
    }
    __syncthreads();
}

__global__ void make_edge_new(const float* __restrict__ Y, const float* __restrict__ edge_rep,
                              const float* __restrict__ eps1, int slot,
                              const float* __restrict__ G, const float* __restrict__ B,
                              float Rinv, float* __restrict__ out) {
    __shared__ float sc[128], sh[128];
    bn_prep128(sc, sh, slot, G, B, Rinv);
    int i = blockIdx.x * 256 + threadIdx.x;
    if (i >= NE * 32) return;
    int h = (i & 31) * 4;
    float c = 1.f + eps1[0];
    float4 y = reinterpret_cast<const float4*>(Y)[i];
    float4 e = reinterpret_cast<const float4*>(edge_rep)[i];
    float4 o;
    o.x = fmaf(c, e.x, fmaxf(0.f, fmaf(y.x, sc[h + 0], sh[h + 0])));
    o.y = fmaf(c, e.y, fmaxf(0.f, fmaf(y.y, sc[h + 1], sh[h + 1])));
    o.z = fmaf(c, e.z, fmaxf(0.f, fmaf(y.z, sc[h + 2], sh[h + 2])));
    o.w = fmaf(c, e.w, fmaxf(0.f, fmaf(y.w, sc[h + 3], sh[h + 3])));
    reinterpret_cast<float4*>(out)[i] = o;
}

__global__ void apply_out(const float* __restrict__ Y, float* __restrict__ out, int nvec,
                          int slot, const float* __restrict__ G, const float* __restrict__ B,
                          float Rinv) {
    __shared__ float sc[128], sh[128];
    bn_prep128(sc, sh, slot, G, B, Rinv);
    int i = blockIdx.x * 256 + threadIdx.x;
    if (i >= nvec) return;
    int h = (i & 31) * 4;
    float4 y = reinterpret_cast<const float4*>(Y)[i];
    float4 o;
    o.x = fmaxf(0.f, fmaf(y.x, sc[h + 0], sh[h + 0]));
    o.y = fmaxf(0.f, fmaf(y.y, sc[h + 1], sh[h + 1]));
    o.z = fmaxf(0.f, fmaf(y.z, sc[h + 2], sh[h + 2]));
    o.w = fmaxf(0.f, fmaf(y.w, sc[h + 3], sh[h + 3]));
    reinterpret_cast<float4*>(out)[i] = o;
}

__global__ void scatter_bnrelu(const float* __restrict__ Y, const int* __restrict__ src,
                               const int* __restrict__ dst, float* __restrict__ S,
                               int slot, const float* __restrict__ G,
                               const float* __restrict__ B, float Rinv) {
    __shared__ float sc[128], sh[128];
    bn_prep128(sc, sh, slot, G, B, Rinv);
    int tid = blockIdx.x * 256 + threadIdx.x;
    if (tid >= NE * 32) return;
    int e = tid >> 5, q = tid & 31;
    int h = q * 4;
    float4 y = reinterpret_cast<const float4*>(Y)[(size_t)e * 32 + q];
    float v0 = fmaxf(0.f, fmaf(y.x, sc[h + 0], sh[h + 0]));
    float v1 = fmaxf(0.f, fmaf(y.y, sc[h + 1], sh[h + 1]));
    float v2 = fmaxf(0.f, fmaf(y.z, sc[h + 2], sh[h + 2]));
    float v3 = fmaxf(0.f, fmaf(y.w, sc[h + 3], sh[h + 3]));
    int s = src[e], d = dst[e];
    red4(S + (size_t)s * HH + h, v0, v1, v2, v3);
    red4(S + (size_t)d * HH + h, v0, v1, v2, v3);
}

__global__ void make_node_in(const float* __restrict__ node_rep, const float* __restrict__ degree,
                             const float* __restrict__ S, const float* __restrict__ eps2,
                             float* __restrict__ out) {
    int i = blockIdx.x * blockDim.x + threadIdx.x;
    if (i >= NN * 32) return;
    int n = i >> 5;
    float c = 1.f + eps2[0] - degree[n];
    float4 a = reinterpret_cast<const float4*>(node_rep)[i];
    float4 s = reinterpret_cast<const float4*>(S)[i];
    reinterpret_cast<float4*>(out)[i] =
        make_float4(fmaf(c, a.x, s.x), fmaf(c, a.y, s.y), fmaf(c, a.z, s.z), fmaf(c, a.w, s.w));
}

// ---------------- host ----------------
#define SMEM256 (2 * (32768 + 2 * 256 * 128))   // 196608
#define SMEM128 (2 * (32768 + 2 * 128 * 128))   // 131072

extern "C" void kernel_launch(void* const* d_in, const int* in_sizes, int n_in,
                              void* d_out, int out_size) {
    const float* node_rep = (const float*)d_in[0];
    const float* edge_rep = (const float*)d_in[1];
    const float* degree   = (const float*)d_in[2];
    const int*   src      = (const int*)  d_in[3];
    const int*   dst      = (const int*)  d_in[4];
    const float* eps1     = (const float*)d_in[5];
    const float* eps2     = (const float*)d_in[6];
    const float* nW1 = (const float*)d_in[7],  *nG1 = (const float*)d_in[8],  *nB1 = (const float*)d_in[9];
    const float* nW2 = (const float*)d_in[10], *nG2 = (const float*)d_in[11], *nB2 = (const float*)d_in[12];
    const float* e0W1 = (const float*)d_in[13], *e0G1 = (const float*)d_in[14], *e0B1 = (const float*)d_in[15];
    const float* e0W2 = (const float*)d_in[16], *e0G2 = (const float*)d_in[17], *e0B2 = (const float*)d_in[18];
    const float* e1W1 = (const float*)d_in[19], *e1G1 = (const float*)d_in[20], *e1B1 = (const float*)d_in[21];
    const float* e1W2 = (const float*)d_in[22], *e1G2 = (const float*)d_in[23], *e1B2 = (const float*)d_in[24];
    const float* e2W1 = (const float*)d_in[25], *e2G1 = (const float*)d_in[26], *e2B1 = (const float*)d_in[27];
    const float* e2W2 = (const float*)d_in[28], *e2G2 = (const float*)d_in[29], *e2B2 = (const float*)d_in[30];

    float* out_node = (float*)d_out;
    float* out_edge = out_node + (size_t)NN * HH;

    cudaFuncSetAttribute(gemm_mma<256>, cudaFuncAttributeMaxDynamicSharedMemorySize, SMEM256);
    cudaFuncSetAttribute(gemm_mma<128>, cudaFuncAttributeMaxDynamicSharedMemorySize, SMEM128);

    float *S, *X0, *Hb, *EN, *Y, *Y2, *NI;
    __nv_bfloat16 *Whi, *Wlo;
    cudaGetSymbolAddress((void**)&S,  g_S);
    cudaGetSymbolAddress((void**)&X0, g_X0);
    cudaGetSymbolAddress((void**)&Hb, g_Hb);
    cudaGetSymbolAddress((void**)&EN, g_EN);
    cudaGetSymbolAddress((void**)&Y,  g_Y);
    cudaGetSymbolAddress((void**)&Y2, g_Y2);
    cudaGetSymbolAddress((void**)&NI, g_NI);
    cudaGetSymbolAddress((void**)&Whi, g_Whi);
    cudaGetSymbolAddress((void**)&Wlo, g_Wlo);

    const int EV = NE * 32;
    const int NV = NN * 32;
    const float RinvE = 1.0f / (float)NE;
    const float RinvN = 1.0f / (float)NN;
    const unsigned gyE = (unsigned)cdivl(NE, 128);
    const unsigned gyN = (unsigned)cdivl(NN, 128);

    init_all<<<(unsigned)cdivl(INIT_TOTAL, 256), 256>>>(e0W1, e0W2, e1W1, e2W1,
                                                        e1W2, e2W2, nW1, nW2);
    scatter_edge<<<(unsigned)cdivl(EV, 256), 256>>>(edge_rep, src, dst, S);
    build_x0<<<(unsigned)cdivl(EV, 256), 256>>>(node_rep, S, src, dst, X0);

    gemm_mma<256><<<dim3(1, gyE), 512, SMEM256>>>(X0, H2, Whi + OFF_E0W1, Wlo + OFF_E0W1,
                                                  Hb, 512, NE, H2, -1, 0, e0G1, e0B1, RinvE);
    gemm_mma<128><<<dim3(1, gyE), 512, SMEM128>>>(Hb, 512, Whi + OFF_E0W2, Wlo + OFF_E0W2,
                                                  Y, 128, NE, H2, 0, 1, e0G1, e0B1, RinvE);
    make_edge_new<<<(unsigned)cdivl(EV, 256), 256>>>(Y, edge_rep, eps1, 1, e0G2, e0B2,
                                                     RinvE, EN);
    gemm_mma<256><<<dim3(2, gyE), 512, SMEM256>>>(EN, HH, Whi + OFF_E1W1, Wlo + OFF_E1W1,
                                                  Hb, 512, NE, HH, -1, 2, e1G1, e1B1, RinvE);
    gemm_mma<128><<<dim3(1, gyE), 512, SMEM128>>>(Hb, 512, Whi + OFF_E1W2, Wlo + OFF_E1W2,
                                                  Y, 128, NE, H2, 2, 4, e1G1, e1B1, RinvE);
    gemm_mma<128><<<dim3(1, gyE), 512, SMEM128>>>(Hb + 256, 512, Whi + OFF_E2W2, Wlo + OFF_E2W2,
                                                  Y2, 128, NE, H2, 3, 5, e2G1, e2B1, RinvE);
    apply_out<<<(unsigned)cdivl(EV, 256), 256>>>(Y, out_edge, EV, 4, e1G2, e1B2, RinvE);
    zero_f4<<<(unsigned)cdivl((long)NN * HH / 4, 256), 256>>>((float4*)S, NN * HH / 4);
    scatter_bnrelu<<<(unsigned)cdivl(EV, 256), 256>>>(Y2, src, dst, S, 5, e2G2, e2B2, RinvE);
    make_node_in<<<(unsigned)cdivl(NV, 256), 256>>>(node_rep, degree, S, eps2, NI);
    gemm_mma<256><<<dim3(1, gyN), 512, SMEM256>>>(NI, HH, Whi + OFF_NW1, Wlo + OFF_NW1,
                                                  Hb, 512, NN, HH, -1, 6, nG1, nB1, RinvN);
    gemm_mma<128><<<dim3(1, gyN), 512, SMEM128>>>(Hb, 512, Whi + OFF_NW2, Wlo + OFF_NW2,
                                                  Y, 128, NN, H2, 6, 7, nG1, nB1, RinvN);
    apply_out<<<(unsigned)cdivl(NV, 256), 256>>>(Y, out_node, NV, 7, nG2, nB2, RinvN);
}

// round 7
// speedup vs baseline: 2.1846x; 1.0952x over previous
#include <cuda_runtime.h>
#include <cuda_bf16.h>
#include <cstdint>
#include <cstddef>

#define NN 50000
#define NE 400000
#define HH 128
#define H2 256
#define BN_EPS 1e-5f

// ---------------- scratch ----------------
static __device__ float g_S [(size_t)NN * HH];
static __device__ float g_X0[(size_t)NE * H2];
static __device__ float g_Hb[(size_t)NE * 512];
static __device__ float g_EN[(size_t)NE * HH];
static __device__ float g_Y [(size_t)NE * HH];
static __device__ float g_Y2[(size_t)NE * HH];
static __device__ float g_NI[(size_t)NN * HH];
static __device__ float g_stats[8][2][256];
static __device__ __nv_bfloat16 g_Whi[294912];
static __device__ __nv_bfloat16 g_Wlo[294912];

#define OFF_E0W1 0
#define OFF_E0W2 65536
#define OFF_E1W1 98304
#define OFF_E2W1 131072
#define OFF_E1W2 163840
#define OFF_E2W2 196608
#define OFF_NW1  229376
#define OFF_NW2  262144

static inline long cdivl(long a, long b) { return (a + b - 1) / b; }

__device__ __forceinline__ uint32_t smem_to_u32(const void* p) {
    uint32_t a;
    asm("{ .reg .u64 t; cvta.to.shared.u64 t, %1; cvt.u32.u64 %0, t; }" : "=r"(a) : "l"(p));
    return a;
}

#define LDMX4(r, addr) \
    asm volatile("ldmatrix.sync.aligned.m8n8.x4.shared.b16 {%0,%1,%2,%3}, [%4];" \
        : "=r"((r)[0]), "=r"((r)[1]), "=r"((r)[2]), "=r"((r)[3]) : "r"(addr))

#define MMA16816(d, a, b0, b1) \
    asm volatile("mma.sync.aligned.m16n8k16.row.col.f32.bf16.bf16.f32 " \
        "{%0,%1,%2,%3},{%4,%5,%6,%7},{%8,%9},{%0,%1,%2,%3};" \
        : "+f"((d)[0]), "+f"((d)[1]), "+f"((d)[2]), "+f"((d)[3]) \
        : "r"((a)[0]), "r"((a)[1]), "r"((a)[2]), "r"((a)[3]), "r"(b0), "r"(b1))

__device__ __forceinline__ void cp16(uint32_t dst, const void* src) {
    asm volatile("cp.async.cg.shared.global [%0], [%1], 16;" :: "r"(dst), "l"(src));
}
#define CP_COMMIT() asm volatile("cp.async.commit_group;" ::: "memory")
#define CP_WAIT0()  asm volatile("cp.async.wait_group 0;" ::: "memory")

__device__ __forceinline__ void red4(float* p, float a, float b, float c, float d) {
    asm volatile("red.global.add.v4.f32 [%0], {%1,%2,%3,%4};"
                 :: "l"(p), "f"(a), "f"(b), "f"(c), "f"(d) : "memory");
}

// 64B-row swizzle (SW64)
__device__ __forceinline__ uint32_t sw64(uint32_t off) {
    return off ^ ((off >> 3) & 0x30);
}

// ---------------- init ----------------
#define NS4 ((NN * HH) / 4)
#define INIT_TOTAL (NS4 + 1024 + 294912)

__global__ void init_all(const float* w0, const float* w1, const float* w2, const float* w3,
                         const float* w4, const float* w5, const float* w6, const float* w7) {
    int gid = blockIdx.x * blockDim.x + threadIdx.x;
    if (gid < NS4) {
        reinterpret_cast<float4*>(g_S)[gid] = make_float4(0.f, 0.f, 0.f, 0.f);
        return;
    }
    gid -= NS4;
    if (gid < 1024) {
        reinterpret_cast<float4*>(g_stats)[gid] = make_float4(0.f, 0.f, 0.f, 0.f);
        return;
    }
    gid -= 1024;
    if (gid >= 294912) return;
    const float* ws[8] = {w0, w1, w2, w3, w4, w5, w6, w7};
    const int segSize[8] = {65536, 32768, 32768, 32768, 32768, 32768, 32768, 32768};
    const int segK[8]    = {256, 256, 128, 128, 256, 256, 128, 256};
    int seg = 0, base = 0, idx = gid;
#pragma unroll
    for (int s = 0; s < 8; s++) {
        if (idx < segSize[s]) { seg = s; break; }
        idx -= segSize[s];
        base += segSize[s];
    }
    int Kw = segK[seg];
    int Nw = segSize[seg] / Kw;
    int k = idx / Nw, n = idx % Nw;
    float w = ws[seg][idx];
    __nv_bfloat16 h = __float2bfloat16(w);
    __nv_bfloat16 l = __float2bfloat16(w - __bfloat162float(h));
    g_Whi[base + n * Kw + k] = h;
    g_Wlo[base + n * Kw + k] = l;
}

// ---------------- graph kernels ----------------
__global__ void zero_f4(float4* p, int n4) {
    int i = blockIdx.x * blockDim.x + threadIdx.x;
    if (i < n4) p[i] = make_float4(0.f, 0.f, 0.f, 0.f);
}

__global__ void scatter_edge(const float* __restrict__ edge_rep,
                             const int* __restrict__ src, const int* __restrict__ dst,
                             float* __restrict__ S) {
    int tid = blockIdx.x * blockDim.x + threadIdx.x;
    if (tid >= NE * 32) return;
    int e = tid >> 5, q = tid & 31;
    float4 v = reinterpret_cast<const float4*>(edge_rep)[(size_t)e * 32 + q];
    int s = src[e], d = dst[e];
    red4(S + (size_t)s * HH + q * 4, v.x, v.y, v.z, v.w);
    red4(S + (size_t)d * HH + q * 4, v.x, v.y, v.z, v.w);
}

__global__ void build_x0(const float* __restrict__ node_rep, const float* __restrict__ S,
                         const int* __restrict__ src, const int* __restrict__ dst,
                         float* __restrict__ X0) {
    int tid = blockIdx.x * blockDim.x + threadIdx.x;
    if (tid >= NE * 32) return;
    int e = tid >> 5, q = tid & 31;
    int s = src[e], d = dst[e];
    const float4* nr4 = reinterpret_cast<const float4*>(node_rep);
    const float4* S4  = reinterpret_cast<const float4*>(S);
    float4 a0 = nr4[(size_t)s * 32 + q], a1 = nr4[(size_t)d * 32 + q];
    float4 b0 = S4 [(size_t)s * 32 + q], b1 = S4 [(size_t)d * 32 + q];
    float4* X4 = reinterpret_cast<float4*>(X0);
    X4[(size_t)e * 64 + q]      = make_float4(a0.x + a1.x, a0.y + a1.y, a0.z + a1.z, a0.w + a1.w);
    X4[(size_t)e * 64 + 32 + q] = make_float4(b0.x + b1.x, b0.y + b1.y, b0.z + b1.z, b0.w + b1.w);
}

// ---------------- HMMA GEMM (bf16x3): 256 thr, CTA 128x128, BK=32, 2 CTAs/SM ----------------
// stage: Ahi 8K | Alo 8K | Bhi 8K | Blo 8K = 32KB, x2 stages = 64KB dynamic.
#define AHIo 0
#define ALOo 8192
#define BHIo 16384
#define BLOo 24576
#define STG  32768
#define GSMEM (2 * STG)

__global__ void __launch_bounds__(256, 2)
gemm_mma(const float* __restrict__ A, int lda,
         const __nv_bfloat16* __restrict__ Bhi, const __nv_bfloat16* __restrict__ Blo,
         float* __restrict__ C, int ldc, int R, int K,
         int inSlot, int outSlotBase,
         const float* __restrict__ Gp, const float* __restrict__ Bp, float Rinv) {
    extern __shared__ __align__(128) char sm[];
    __shared__ float s_scale[256], s_shift[256];
    __shared__ float s_csum[128], s_css[128];
    const uint32_t uS = smem_to_u32(sm);

    const int tid  = threadIdx.x;
    const int wid  = tid >> 5;
    const int lane = tid & 31;
    const int m0     = blockIdx.y * 128;
    const int bnBase = blockIdx.x * 128;
    const int wm = (wid & 3) * 32;
    const int wn = (wid >> 2) * 64;
    const bool applyBN = (inSlot >= 0);

    if (applyBN) {
        for (int c = tid; c < K; c += 256) {
            float mean = g_stats[inSlot][0][c] * Rinv;
            float var  = g_stats[inSlot][1][c] * Rinv - mean * mean;
            float s    = Gp[c] * rsqrtf(var + BN_EPS);
            s_scale[c] = s;
            s_shift[c] = fmaf(-mean, s, Bp[c]);
        }
    }
    if (tid < 128) { s_csum[tid] = 0.f; s_css[tid] = 0.f; }
    __syncthreads();

    float acc[2][8][4];
#pragma unroll
    for (int mt = 0; mt < 2; mt++)
#pragma unroll
        for (int nt = 0; nt < 8; nt++)
#pragma unroll
            for (int j = 0; j < 4; j++) acc[mt][nt][j] = 0.f;

    const int nchunks = K >> 5;               // BK=32
    const int arow_i = tid >> 1;              // 2 threads per row
    const int acb    = (tid & 1) * 16;        // 16 cols each
    const int agr    = m0 + arow_i;
    float4 areg[4];

    // prologue
    {
#pragma unroll
        for (int j = 0; j < 2; j++) {
            int p = tid + j * 256;             // 512 pieces of 16B per tile
            int n = p >> 2, f = p & 3;
            uint32_t sw = sw64(n * 64 + f * 16);
            cp16(uS + BHIo + sw, Bhi + (size_t)(bnBase + n) * K + f * 8);
            cp16(uS + BLOo + sw, Blo + (size_t)(bnBase + n) * K + f * 8);
        }
        CP_COMMIT();
        const float* ap = A + (size_t)agr * lda + acb;
#pragma unroll
        for (int f = 0; f < 4; f++)
            areg[f] = (agr < R) ? *reinterpret_cast<const float4*>(ap + f * 4)
                                : make_float4(0.f, 0.f, 0.f, 0.f);
    }

    for (int kc = 0; kc < nchunks; kc++) {
        const int s = kc & 1;
        const uint32_t uStage = uS + s * STG;
        // convert A regs -> stage s (BN+ReLU optional)
#pragma unroll
        for (int f = 0; f < 4; f++) {
            float4 v = areg[f];
            if (applyBN && agr < R) {
                int k = kc * 32 + acb + f * 4;
                v.x = fmaxf(0.f, fmaf(v.x, s_scale[k + 0], s_shift[k + 0]));
                v.y = fmaxf(0.f, fmaf(v.y, s_scale[k + 1], s_shift[k + 1]));
                v.z = fmaxf(0.f, fmaf(v.z, s_scale[k + 2], s_shift[k + 2]));
                v.w = fmaxf(0.f, fmaf(v.w, s_scale[k + 3], s_shift[k + 3]));
            }
            __nv_bfloat162 hxy = __floats2bfloat162_rn(v.x, v.y);
            __nv_bfloat162 hzw = __floats2bfloat162_rn(v.z, v.w);
            __nv_bfloat162 lxy = __floats2bfloat162_rn(v.x - __low2float(hxy),
                                                       v.y - __high2float(hxy));
            __nv_bfloat162 lzw = __floats2bfloat162_rn(v.z - __low2float(hzw),
                                                       v.w - __high2float(hzw));
            uint32_t sw = sw64(arow_i * 64 + (acb + f * 4) * 2);
            *reinterpret_cast<uint2*>(sm + s * STG + AHIo + sw) =
                make_uint2(*reinterpret_cast<uint32_t*>(&hxy),
                           *reinterpret_cast<uint32_t*>(&hzw));
            *reinterpret_cast<uint2*>(sm + s * STG + ALOo + sw) =
                make_uint2(*reinterpret_cast<uint32_t*>(&lxy),
                           *reinterpret_cast<uint32_t*>(&lzw));
        }
        // prefetch next A chunk
        if (kc + 1 < nchunks) {
            const float* ap = A + (size_t)agr * lda + (kc + 1) * 32 + acb;
#pragma unroll
            for (int f = 0; f < 4; f++)
                areg[f] = (agr < R) ? *reinterpret_cast<const float4*>(ap + f * 4)
                                    : make_float4(0.f, 0.f, 0.f, 0.f);
        }
        CP_WAIT0();
        __syncthreads();
        // issue B[kc+1] into other stage
        if (kc + 1 < nchunks) {
            const uint32_t uN = uS + (s ^ 1) * STG;
#pragma unroll
            for (int j = 0; j < 2; j++) {
                int p = tid + j * 256;
                int n = p >> 2, f = p & 3;
                uint32_t sw = sw64(n * 64 + f * 16);
                const size_t gsrc = (size_t)(bnBase + n) * K + (kc + 1) * 32 + f * 8;
                cp16(uN + BHIo + sw, Bhi + gsrc);
                cp16(uN + BLOo + sw, Blo + gsrc);
            }
            CP_COMMIT();
        }
        // MMA over 2 k16-steps
#pragma unroll
        for (int st = 0; st < 2; st++) {
            const uint32_t kb = st * 32 + ((lane >> 4) << 4);
            uint32_t ah[2][4], al[2][4];
#pragma unroll
            for (int mt = 0; mt < 2; mt++) {
                uint32_t sw = sw64((wm + mt * 16 + (lane & 15)) * 64 + kb);
                LDMX4(ah[mt], uStage + AHIo + sw);
                LDMX4(al[mt], uStage + ALOo + sw);
            }
            uint32_t bf[4][4];
#pragma unroll
            for (int t = 0; t < 4; t++) {
                uint32_t sw = sw64((wn + t * 16 + (lane & 15)) * 64 + kb);
                LDMX4(bf[t], uStage + BHIo + sw);
            }
#pragma unroll
            for (int mt = 0; mt < 2; mt++)
#pragma unroll
                for (int t = 0; t < 4; t++) {
                    MMA16816(acc[mt][t * 2 + 0], ah[mt], bf[t][0], bf[t][2]);
                    MMA16816(acc[mt][t * 2 + 1], ah[mt], bf[t][1], bf[t][3]);
                    MMA16816(acc[mt][t * 2 + 0], al[mt], bf[t][0], bf[t][2]);
                    MMA16816(acc[mt][t * 2 + 1], al[mt], bf[t][1], bf[t][3]);
                }
#pragma unroll
            for (int t = 0; t < 4; t++) {
                uint32_t sw = sw64((wn + t * 16 + (lane & 15)) * 64 + kb);
                LDMX4(bf[t], uStage + BLOo + sw);
            }
#pragma unroll
            for (int mt = 0; mt < 2; mt++)
#pragma unroll
                for (int t = 0; t < 4; t++) {
                    MMA16816(acc[mt][t * 2 + 0], ah[mt], bf[t][0], bf[t][2]);
                    MMA16816(acc[mt][t * 2 + 1], ah[mt], bf[t][1], bf[t][3]);
                }
        }
    }

    // epilogue: store C + fused column stats
#pragma unroll
    for (int mt = 0; mt < 2; mt++) {
        const int row0 = m0 + wm + mt * 16 + (lane >> 2);
#pragma unroll
        for (int nt = 0; nt < 8; nt++) {
            float c0 = acc[mt][nt][0], c1 = acc[mt][nt][1];
            float c2 = acc[mt][nt][2], c3 = acc[mt][nt][3];
            const int cl = wn + nt * 8 + (lane & 3) * 2;
            if (row0 < R)
                *reinterpret_cast<float2*>(C + (size_t)row0 * ldc + bnBase + cl) =
                    make_float2(c0, c1);
            if (row0 + 8 < R)
                *reinterpret_cast<float2*>(C + (size_t)(row0 + 8) * ldc + bnBase + cl) =
                    make_float2(c2, c3);
            float se = c0 + c2, so = c1 + c3;
            float qe = fmaf(c0, c0, c2 * c2), qo = fmaf(c1, c1, c3 * c3);
#pragma unroll
            for (int off = 16; off >= 4; off >>= 1) {
                se += __shfl_down_sync(0xffffffffu, se, off);
                so += __shfl_down_sync(0xffffffffu, so, off);
                qe += __shfl_down_sync(0xffffffffu, qe, off);
                qo += __shfl_down_sync(0xffffffffu, qo, off);
            }
            if (lane < 4) {
                int c = wn + nt * 8 + lane * 2;
                atomicAdd(&s_csum[c], se); atomicAdd(&s_csum[c + 1], so);
                atomicAdd(&s_css [c], qe); atomicAdd(&s_css [c + 1], qo);
            }
        }
    }
    __syncthreads();
    if (tid < 256) {
        int c = tid & 127;
        int colg = bnBase + c;
        int slot = outSlotBase + (colg >> 8);
        int colIn = colg & 255;
        if (tid < 128) atomicAdd(&g_stats[slot][0][colIn], s_csum[c]);
        else           atomicAdd(&g_stats[slot][1][colIn], s_css[c]);
    }
}

// ---------------- consumers ----------------
__device__ __forceinline__ void bn_prep128(float* sc, float* sh, int slot,
                                           const float* G, const float* B, float Rinv) {
    int t = threadIdx.x;
    if (t < 128) {
        float mean = g_stats[slot][0][t] * Rinv;
        float var  = g_stats[slot][1][t] * Rinv - mean * mean;
        float s    = G[t] * rsqrtf(var + BN_EPS);
        sc[t] = s;
        sh[t] = fmaf(-mean, s, B[t]);
    }
    __syncthreads();
}

__global__ void make_edge_new(const float* __restrict__ Y, const float* __restrict__ edge_rep,
                              const float* __restrict__ eps1, int slot,
                              const float* __restrict__ G, const float* __restrict__ B,
                              float Rinv, float* __restrict__ out) {
    __shared__ float sc[128], sh[128];
    bn_prep128(sc, sh, slot, G, B, Rinv);
    int i = blockIdx.x * 256 + threadIdx.x;
    if (i >= NE * 32) return;
    int h = (i & 31) * 4;
    float c = 1.f + eps1[0];
    float4 y = reinterpret_cast<const float4*>(Y)[i];
    float4 e = reinterpret_cast<const float4*>(edge_rep)[i];
    float4 o;
    o.x = fmaf(c, e.x, fmaxf(0.f, fmaf(y.x, sc[h + 0], sh[h + 0])));
    o.y = fmaf(c, e.y, fmaxf(0.f, fmaf(y.y, sc[h + 1], sh[h + 1])));
    o.z = fmaf(c, e.z, fmaxf(0.f, fmaf(y.z, sc[h + 2], sh[h + 2])));
    o.w = fmaf(c, e.w, fmaxf(0.f, fmaf(y.w, sc[h + 3], sh[h + 3])));
    reinterpret_cast<float4*>(out)[i] = o;
}

__global__ void apply_out(const float* __restrict__ Y, float* __restrict__ out, int nvec,
                          int slot, const float* __restrict__ G, const float* __restrict__ B,
                          float Rinv) {
    __shared__ float sc[128], sh[128];
    bn_prep128(sc, sh, slot, G, B, Rinv);
    int i = blockIdx.x * 256 + threadIdx.x;
    if (i >= nvec) return;
    int h = (i & 31) * 4;
    float4 y = reinterpret_cast<const float4*>(Y)[i];
    float4 o;
    o.x = fmaxf(0.f, fmaf(y.x, sc[h + 0], sh[h + 0]));
    o.y = fmaxf(0.f, fmaf(y.y, sc[h + 1], sh[h + 1]));
    o.z = fmaxf(0.f, fmaf(y.z, sc[h + 2], sh[h + 2]));
    o.w = fmaxf(0.f, fmaf(y.w, sc[h + 3], sh[h + 3]));
    reinterpret_cast<float4*>(out)[i] = o;
}

__global__ void scatter_bnrelu(const float* __restrict__ Y, const int* __restrict__ src,
                               const int* __restrict__ dst, float* __restrict__ S,
                               int slot, const float* __restrict__ G,
                               const float* __restrict__ B, float Rinv) {
    __shared__ float sc[128], sh[128];
    bn_prep128(sc, sh, slot, G, B, Rinv);
    int tid = blockIdx.x * 256 + threadIdx.x;
    if (tid >= NE * 32) return;
    int e = tid >> 5, q = tid & 31;
    int h = q * 4;
    float4 y = reinterpret_cast<const float4*>(Y)[(size_t)e * 32 + q];
    float v0 = fmaxf(0.f, fmaf(y.x, sc[h + 0], sh[h + 0]));
    float v1 = fmaxf(0.f, fmaf(y.y, sc[h + 1], sh[h + 1]));
    float v2 = fmaxf(0.f, fmaf(y.z, sc[h + 2], sh[h + 2]));
    float v3 = fmaxf(0.f, fmaf(y.w, sc[h + 3], sh[h + 3]));
    int s = src[e], d = dst[e];
    red4(S + (size_t)s * HH + h, v0, v1, v2, v3);
    red4(S + (size_t)d * HH + h, v0, v1, v2, v3);
}

__global__ void make_node_in(const float* __restrict__ node_rep, const float* __restrict__ degree,
                             const float* __restrict__ S, const float* __restrict__ eps2,
                             float* __restrict__ out) {
    int i = blockIdx.x * blockDim.x + threadIdx.x;
    if (i >= NN * 32) return;
    int n = i >> 5;
    float c = 1.f + eps2[0] - degree[n];
    float4 a = reinterpret_cast<const float4*>(node_rep)[i];
    float4 s = reinterpret_cast<const float4*>(S)[i];
    reinterpret_cast<float4*>(out)[i] =
        make_float4(fmaf(c, a.x, s.x), fmaf(c, a.y, s.y), fmaf(c, a.z, s.z), fmaf(c, a.w, s.w));
}

// ---------------- host ----------------
extern "C" void kernel_launch(void* const* d_in, const int* in_sizes, int n_in,
                              void* d_out, int out_size) {
    const float* node_rep = (const float*)d_in[0];
    const float* edge_rep = (const float*)d_in[1];
    const float* degree   = (const float*)d_in[2];
    const int*   src      = (const int*)  d_in[3];
    const int*   dst      = (const int*)  d_in[4];
    const float* eps1     = (const float*)d_in[5];
    const float* eps2     = (const float*)d_in[6];
    const float* nW1 = (const float*)d_in[7],  *nG1 = (const float*)d_in[8],  *nB1 = (const float*)d_in[9];
    const float* nW2 = (const float*)d_in[10], *nG2 = (const float*)d_in[11], *nB2 = (const float*)d_in[12];
    const float* e0W1 = (const float*)d_in[13], *e0G1 = (const float*)d_in[14], *e0B1 = (const float*)d_in[15];
    const float* e0W2 = (const float*)d_in[16], *e0G2 = (const float*)d_in[17], *e0B2 = (const float*)d_in[18];
    const float* e1W1 = (const float*)d_in[19], *e1G1 = (const float*)d_in[20], *e1B1 = (const float*)d_in[21];
    const float* e1W2 = (const float*)d_in[22], *e1G2 = (const float*)d_in[23], *e1B2 = (const float*)d_in[24];
    const float* e2W1 = (const float*)d_in[25], *e2G1 = (const float*)d_in[26], *e2B1 = (const float*)d_in[27];
    const float* e2W2 = (const float*)d_in[28], *e2G2 = (const float*)d_in[29], *e2B2 = (const float*)d_in[30];

    float* out_node = (float*)d_out;
    float* out_edge = out_node + (size_t)NN * HH;

    cudaFuncSetAttribute(gemm_mma, cudaFuncAttributeMaxDynamicSharedMemorySize, GSMEM);

    float *S, *X0, *Hb, *EN, *Y, *Y2, *NI;
    __nv_bfloat16 *Whi, *Wlo;
    cudaGetSymbolAddress((void**)&S,  g_S);
    cudaGetSymbolAddress((void**)&X0, g_X0);
    cudaGetSymbolAddress((void**)&Hb, g_Hb);
    cudaGetSymbolAddress((void**)&EN, g_EN);
    cudaGetSymbolAddress((void**)&Y,  g_Y);
    cudaGetSymbolAddress((void**)&Y2, g_Y2);
    cudaGetSymbolAddress((void**)&NI, g_NI);
    cudaGetSymbolAddress((void**)&Whi, g_Whi);
    cudaGetSymbolAddress((void**)&Wlo, g_Wlo);

    const int EV = NE * 32;
    const int NV = NN * 32;
    const float RinvE = 1.0f / (float)NE;
    const float RinvN = 1.0f / (float)NN;
    const unsigned gyE = (unsigned)cdivl(NE, 128);
    const unsigned gyN = (unsigned)cdivl(NN, 128);

    init_all<<<(unsigned)cdivl(INIT_TOTAL, 256), 256>>>(e0W1, e0W2, e1W1, e2W1,
                                                        e1W2, e2W2, nW1, nW2);
    scatter_edge<<<(unsigned)cdivl(EV, 256), 256>>>(edge_rep, src, dst, S);
    build_x0<<<(unsigned)cdivl(EV, 256), 256>>>(node_rep, S, src, dst, X0);

    // e0 L1: X0[NE,256] @ W[256,256] -> Hb[:,0:256], slot 0
    gemm_mma<<<dim3(2, gyE), 256, GSMEM>>>(X0, H2, Whi + OFF_E0W1, Wlo + OFF_E0W1,
                                           Hb, 512, NE, H2, -1, 0, e0G1, e0B1, RinvE);
    // e0 L2: BN(slot0) -> Y, slot 1
    gemm_mma<<<dim3(1, gyE), 256, GSMEM>>>(Hb, 512, Whi + OFF_E0W2, Wlo + OFF_E0W2,
                                           Y, 128, NE, H2, 0, 1, e0G1, e0B1, RinvE);
    make_edge_new<<<(unsigned)cdivl(EV, 256), 256>>>(Y, edge_rep, eps1, 1, e0G2, e0B2,
                                                     RinvE, EN);
    // merged e1L1+e2L1: EN[NE,128] @ Wcat[512x128] -> Hb[:,0:512], slots 2,3
    gemm_mma<<<dim3(4, gyE), 256, GSMEM>>>(EN, HH, Whi + OFF_E1W1, Wlo + OFF_E1W1,
                                           Hb, 512, NE, HH, -1, 2, e1G1, e1B1, RinvE);
    // e1 L2: BN(slot2, Hb[:,0:256]) -> Y, slot 4
    gemm_mma<<<dim3(1, gyE), 256, GSMEM>>>(Hb, 512, Whi + OFF_E1W2, Wlo + OFF_E1W2,
                                           Y, 128, NE, H2, 2, 4, e1G1, e1B1, RinvE);
    // e2 L2: BN(slot3, Hb[:,256:512]) -> Y2, slot 5
    gemm_mma<<<dim3(1, gyE), 256, GSMEM>>>(Hb + 256, 512, Whi + OFF_E2W2, Wlo + OFF_E2W2,
                                           Y2, 128, NE, H2, 3, 5, e2G1, e2B1, RinvE);
    apply_out<<<(unsigned)cdivl(EV, 256), 256>>>(Y, out_edge, EV, 4, e1G2, e1B2, RinvE);
    zero_f4<<<(unsigned)cdivl((long)NN * HH / 4, 256), 256>>>((float4*)S, NN * HH / 4);
    scatter_bnrelu<<<(unsigned)cdivl(EV, 256), 256>>>(Y2, src, dst, S, 5, e2G2, e2B2, RinvE);
    make_node_in<<<(unsigned)cdivl(NV, 256), 256>>>(node_rep, degree, S, eps2, NI);
    // node L1: NI[NN,128] @ W[128,256] -> Hb[:,0:256], slot 6
    gemm_mma<<<dim3(2, gyN), 256, GSMEM>>>(NI, HH, Whi + OFF_NW1, Wlo + OFF_NW1,
                                           Hb, 512, NN, HH, -1, 6, nG1, nB1, RinvN);
    // node L2: BN(slot6) -> Y, slot 7
    gemm_mma<<<dim3(1, gyN), 256, GSMEM>>>(Hb, 512, Whi + OFF_NW2, Wlo + OFF_NW2,
                                           Y, 128, NN, H2, 6, 7, nG1, nB1, RinvN);
    apply_out<<<(unsigned)cdivl(NV, 256), 256>>>(Y, out_node, NV, 7, nG2, nB2, RinvN);
}

// round 8
// speedup vs baseline: 2.3590x; 1.0798x over previous
#include <cuda_runtime.h>
#include <cuda_bf16.h>
#include <cstdint>
#include <cstddef>

#define NN 50000
#define NE 400000
#define HH 128
#define H2 256
#define BN_EPS 1e-5f

// ---------------- scratch ----------------
static __device__ float g_S [(size_t)NN * HH];
static __device__ float g_Hb[(size_t)NE * 512];
static __device__ float g_Y [(size_t)NE * HH];
static __device__ float g_Y2[(size_t)NE * HH];
static __device__ float g_stats[8][2][256];
static __device__ __nv_bfloat16 g_AHI[(size_t)NE * H2];   // layer-1 A, hi plane
static __device__ __nv_bfloat16 g_ALO[(size_t)NE * H2];   // layer-1 A, lo plane
static __device__ __nv_bfloat16 g_Whi[294912];
static __device__ __nv_bfloat16 g_Wlo[294912];

#define OFF_E0W1 0
#define OFF_E0W2 65536
#define OFF_E1W1 98304
#define OFF_E2W1 131072
#define OFF_E1W2 163840
#define OFF_E2W2 196608
#define OFF_NW1  229376
#define OFF_NW2  262144

static inline long cdivl(long a, long b) { return (a + b - 1) / b; }

__device__ __forceinline__ uint32_t smem_to_u32(const void* p) {
    uint32_t a;
    asm("{ .reg .u64 t; cvta.to.shared.u64 t, %1; cvt.u32.u64 %0, t; }" : "=r"(a) : "l"(p));
    return a;
}

#define LDMX4(r, addr) \
    asm volatile("ldmatrix.sync.aligned.m8n8.x4.shared.b16 {%0,%1,%2,%3}, [%4];" \
        : "=r"((r)[0]), "=r"((r)[1]), "=r"((r)[2]), "=r"((r)[3]) : "r"(addr))

#define MMA16816(d, a, b0, b1) \
    asm volatile("mma.sync.aligned.m16n8k16.row.col.f32.bf16.bf16.f32 " \
        "{%0,%1,%2,%3},{%4,%5,%6,%7},{%8,%9},{%0,%1,%2,%3};" \
        : "+f"((d)[0]), "+f"((d)[1]), "+f"((d)[2]), "+f"((d)[3]) \
        : "r"((a)[0]), "r"((a)[1]), "r"((a)[2]), "r"((a)[3]), "r"(b0), "r"(b1))

__device__ __forceinline__ void cp16(uint32_t dst, const void* src) {
    asm volatile("cp.async.cg.shared.global [%0], [%1], 16;" :: "r"(dst), "l"(src));
}
#define CP_COMMIT() asm volatile("cp.async.commit_group;" ::: "memory")
#define CP_WAIT(n)  asm volatile("cp.async.wait_group %0;" :: "n"(n) : "memory")

__device__ __forceinline__ void red4(float* p, float a, float b, float c, float d) {
    asm volatile("red.global.add.v4.f32 [%0], {%1,%2,%3,%4};"
                 :: "l"(p), "f"(a), "f"(b), "f"(c), "f"(d) : "memory");
}

__device__ __forceinline__ uint32_t sw64(uint32_t off) {
    return off ^ ((off >> 3) & 0x30);
}

// split fp32x4 -> hi/lo bf16 planes (8B each)
__device__ __forceinline__ void split_store(__nv_bfloat16* hi, __nv_bfloat16* lo,
                                            size_t idx, float4 v) {
    __nv_bfloat162 hxy = __floats2bfloat162_rn(v.x, v.y);
    __nv_bfloat162 hzw = __floats2bfloat162_rn(v.z, v.w);
    __nv_bfloat162 lxy = __floats2bfloat162_rn(v.x - __low2float(hxy),
                                               v.y - __high2float(hxy));
    __nv_bfloat162 lzw = __floats2bfloat162_rn(v.z - __low2float(hzw),
                                               v.w - __high2float(hzw));
    *reinterpret_cast<uint2*>(hi + idx) =
        make_uint2(*reinterpret_cast<uint32_t*>(&hxy), *reinterpret_cast<uint32_t*>(&hzw));
    *reinterpret_cast<uint2*>(lo + idx) =
        make_uint2(*reinterpret_cast<uint32_t*>(&lxy), *reinterpret_cast<uint32_t*>(&lzw));
}

// ---------------- init ----------------
#define NS4 ((NN * HH) / 4)
#define INIT_TOTAL (NS4 + 1024 + 294912)

__global__ void init_all(const float* w0, const float* w1, const float* w2, const float* w3,
                         const float* w4, const float* w5, const float* w6, const float* w7) {
    int gid = blockIdx.x * blockDim.x + threadIdx.x;
    if (gid < NS4) {
        reinterpret_cast<float4*>(g_S)[gid] = make_float4(0.f, 0.f, 0.f, 0.f);
        return;
    }
    gid -= NS4;
    if (gid < 1024) {
        reinterpret_cast<float4*>(g_stats)[gid] = make_float4(0.f, 0.f, 0.f, 0.f);
        return;
    }
    gid -= 1024;
    if (gid >= 294912) return;
    const float* ws[8] = {w0, w1, w2, w3, w4, w5, w6, w7};
    const int segSize[8] = {65536, 32768, 32768, 32768, 32768, 32768, 32768, 32768};
    const int segK[8]    = {256, 256, 128, 128, 256, 256, 128, 256};
    int seg = 0, base = 0, idx = gid;
#pragma unroll
    for (int s = 0; s < 8; s++) {
        if (idx < segSize[s]) { seg = s; break; }
        idx -= segSize[s];
        base += segSize[s];
    }
    int Kw = segK[seg];
    int Nw = segSize[seg] / Kw;
    int k = idx / Nw, n = idx % Nw;
    float w = ws[seg][idx];
    __nv_bfloat16 h = __float2bfloat16(w);
    __nv_bfloat16 l = __float2bfloat16(w - __bfloat162float(h));
    g_Whi[base + n * Kw + k] = h;
    g_Wlo[base + n * Kw + k] = l;
}

// ---------------- graph kernels ----------------
__global__ void zero_f4(float4* p, int n4) {
    int i = blockIdx.x * blockDim.x + threadIdx.x;
    if (i < n4) p[i] = make_float4(0.f, 0.f, 0.f, 0.f);
}

__global__ void scatter_edge(const float* __restrict__ edge_rep,
                             const int* __restrict__ src, const int* __restrict__ dst,
                             float* __restrict__ S) {
    int tid = blockIdx.x * blockDim.x + threadIdx.x;
    if (tid >= NE * 32) return;
    int e = tid >> 5, q = tid & 31;
    float4 v = reinterpret_cast<const float4*>(edge_rep)[(size_t)e * 32 + q];
    int s = src[e], d = dst[e];
    red4(S + (size_t)s * HH + q * 4, v.x, v.y, v.z, v.w);
    red4(S + (size_t)d * HH + q * 4, v.x, v.y, v.z, v.w);
}

// X0 = [n2e | e2e], written directly as bf16 hi/lo planes [NE,256]
__global__ void build_x0(const float* __restrict__ node_rep, const float* __restrict__ S,
                         const int* __restrict__ src, const int* __restrict__ dst,
                         __nv_bfloat16* __restrict__ Ahi, __nv_bfloat16* __restrict__ Alo) {
    int tid = blockIdx.x * blockDim.x + threadIdx.x;
    if (tid >= NE * 32) return;
    int e = tid >> 5, q = tid & 31;
    int s = src[e], d = dst[e];
    const float4* nr4 = reinterpret_cast<const float4*>(node_rep);
    const float4* S4  = reinterpret_cast<const float4*>(S);
    float4 a0 = nr4[(size_t)s * 32 + q], a1 = nr4[(size_t)d * 32 + q];
    float4 b0 = S4 [(size_t)s * 32 + q], b1 = S4 [(size_t)d * 32 + q];
    float4 a = make_float4(a0.x + a1.x, a0.y + a1.y, a0.z + a1.z, a0.w + a1.w);
    float4 b = make_float4(b0.x + b1.x, b0.y + b1.y, b0.z + b1.z, b0.w + b1.w);
    split_store(Ahi, Alo, (size_t)e * 256 + q * 4, a);
    split_store(Ahi, Alo, (size_t)e * 256 + 128 + q * 4, b);
}

// ---------------- GEMM a16: pre-split bf16 A planes, pure cp.async, 3 stages ----------------
#define AHIo 0
#define ALOo 8192
#define BHIo 16384
#define BLOo 24576
#define STG  32768
#define GSMEM16 (3 * STG)
#define GSMEM32 (2 * STG)

__global__ void __launch_bounds__(256, 2)
gemm_a16(const __nv_bfloat16* __restrict__ Ahi, const __nv_bfloat16* __restrict__ Alo,
         int lda,
         const __nv_bfloat16* __restrict__ Bhi, const __nv_bfloat16* __restrict__ Blo,
         float* __restrict__ C, int ldc, int R, int K, int outSlotBase) {
    extern __shared__ __align__(128) char sm[];
    __shared__ float s_csum[128], s_css[128];
    const uint32_t uS = smem_to_u32(sm);

    const int tid  = threadIdx.x;
    const int wid  = tid >> 5;
    const int lane = tid & 31;
    const int m0     = blockIdx.y * 128;
    const int bnBase = blockIdx.x * 128;
    const int wm = (wid & 3) * 32;
    const int wn = (wid >> 2) * 64;

    if (tid < 128) { s_csum[tid] = 0.f; s_css[tid] = 0.f; }
    __syncthreads();

    float acc[2][8][4];
#pragma unroll
    for (int mt = 0; mt < 2; mt++)
#pragma unroll
        for (int nt = 0; nt < 8; nt++)
#pragma unroll
            for (int j = 0; j < 4; j++) acc[mt][nt][j] = 0.f;

    const int nchunks = K >> 5;

    // per-thread tile piece: 2 (row,f) pairs covering 512 16B-pieces per plane
    const int p0row = tid >> 2,          p0f = tid & 3;
    const int p1row = (tid + 256) >> 2,  p1f = (tid + 256) & 3;
    const uint32_t sw0 = sw64(p0row * 64 + p0f * 16);
    const uint32_t sw1 = sw64(p1row * 64 + p1f * 16);

    auto issue = [&](int kc) {
        uint32_t uDst = uS + (kc % 3) * STG;
        {
            const size_t asrc = (size_t)(m0 + p0row) * lda + kc * 32 + p0f * 8;
            const size_t bsrc = (size_t)(bnBase + p0row) * K + kc * 32 + p0f * 8;
            cp16(uDst + AHIo + sw0, Ahi + asrc);
            cp16(uDst + ALOo + sw0, Alo + asrc);
            cp16(uDst + BHIo + sw0, Bhi + bsrc);
            cp16(uDst + BLOo + sw0, Blo + bsrc);
        }
        {
            const size_t asrc = (size_t)(m0 + p1row) * lda + kc * 32 + p1f * 8;
            const size_t bsrc = (size_t)(bnBase + p1row) * K + kc * 32 + p1f * 8;
            cp16(uDst + AHIo + sw1, Ahi + asrc);
            cp16(uDst + ALOo + sw1, Alo + asrc);
            cp16(uDst + BHIo + sw1, Bhi + bsrc);
            cp16(uDst + BLOo + sw1, Blo + bsrc);
        }
        CP_COMMIT();
    };

    issue(0);
    if (nchunks > 1) issue(1);

    for (int kc = 0; kc < nchunks; kc++) {
        if (kc + 1 < nchunks) { CP_WAIT(1); } else { CP_WAIT(0); }
        __syncthreads();
        if (kc + 2 < nchunks) issue(kc + 2);
        const uint32_t uStage = uS + (kc % 3) * STG;
#pragma unroll
        for (int st = 0; st < 2; st++) {
            const uint32_t kb = st * 32 + ((lane >> 4) << 4);
            uint32_t ah[2][4], al[2][4];
#pragma unroll
            for (int mt = 0; mt < 2; mt++) {
                uint32_t sw = sw64((wm + mt * 16 + (lane & 15)) * 64 + kb);
                LDMX4(ah[mt], uStage + AHIo + sw);
                LDMX4(al[mt], uStage + ALOo + sw);
            }
            uint32_t bf[4][4];
#pragma unroll
            for (int t = 0; t < 4; t++) {
                uint32_t sw = sw64((wn + t * 16 + (lane & 15)) * 64 + kb);
                LDMX4(bf[t], uStage + BHIo + sw);
            }
#pragma unroll
            for (int mt = 0; mt < 2; mt++)
#pragma unroll
                for (int t = 0; t < 4; t++) {
                    MMA16816(acc[mt][t * 2 + 0], ah[mt], bf[t][0], bf[t][2]);
                    MMA16816(acc[mt][t * 2 + 1], ah[mt], bf[t][1], bf[t][3]);
                    MMA16816(acc[mt][t * 2 + 0], al[mt], bf[t][0], bf[t][2]);
                    MMA16816(acc[mt][t * 2 + 1], al[mt], bf[t][1], bf[t][3]);
                }
#pragma unroll
            for (int t = 0; t < 4; t++) {
                uint32_t sw = sw64((wn + t * 16 + (lane & 15)) * 64 + kb);
                LDMX4(bf[t], uStage + BLOo + sw);
            }
#pragma unroll
            for (int mt = 0; mt < 2; mt++)
#pragma unroll
                for (int t = 0; t < 4; t++) {
                    MMA16816(acc[mt][t * 2 + 0], ah[mt], bf[t][0], bf[t][2]);
                    MMA16816(acc[mt][t * 2 + 1], ah[mt], bf[t][1], bf[t][3]);
                }
        }
    }

    // epilogue: store C + fused stats (OOB rows zeroed: A planes hold garbage there)
#pragma unroll
    for (int mt = 0; mt < 2; mt++) {
        const int row0 = m0 + wm + mt * 16 + (lane >> 2);
#pragma unroll
        for (int nt = 0; nt < 8; nt++) {
            float c0 = acc[mt][nt][0], c1 = acc[mt][nt][1];
            float c2 = acc[mt][nt][2], c3 = acc[mt][nt][3];
            const int cl = wn + nt * 8 + (lane & 3) * 2;
            if (row0 < R)
                *reinterpret_cast<float2*>(C + (size_t)row0 * ldc + bnBase + cl) =
                    make_float2(c0, c1);
            else { c0 = 0.f; c1 = 0.f; }
            if (row0 + 8 < R)
                *reinterpret_cast<float2*>(C + (size_t)(row0 + 8) * ldc + bnBase + cl) =
                    make_float2(c2, c3);
            else { c2 = 0.f; c3 = 0.f; }
            float se = c0 + c2, so = c1 + c3;
            float qe = fmaf(c0, c0, c2 * c2), qo = fmaf(c1, c1, c3 * c3);
#pragma unroll
            for (int off = 16; off >= 4; off >>= 1) {
                se += __shfl_down_sync(0xffffffffu, se, off);
                so += __shfl_down_sync(0xffffffffu, so, off);
                qe += __shfl_down_sync(0xffffffffu, qe, off);
                qo += __shfl_down_sync(0xffffffffu, qo, off);
            }
            if (lane < 4) {
                int c = wn + nt * 8 + lane * 2;
                atomicAdd(&s_csum[c], se); atomicAdd(&s_csum[c + 1], so);
                atomicAdd(&s_css [c], qe); atomicAdd(&s_css [c + 1], qo);
            }
        }
    }
    __syncthreads();
    if (tid < 256) {
        int c = tid & 127;
        int colg = bnBase + c;
        int slot = outSlotBase + (colg >> 8);
        int colIn = colg & 255;
        if (tid < 128) atomicAdd(&g_stats[slot][0][colIn], s_csum[c]);
        else           atomicAdd(&g_stats[slot][1][colIn], s_css[c]);
    }
}

// ---------------- GEMM a32: fp32 A + fused BN+ReLU conversion (layer 2) ----------------
__global__ void __launch_bounds__(256, 2)
gemm_a32(const float* __restrict__ A, int lda,
         const __nv_bfloat16* __restrict__ Bhi, const __nv_bfloat16* __restrict__ Blo,
         float* __restrict__ C, int ldc, int R, int K,
         int inSlot, int outSlotBase,
         const float* __restrict__ Gp, const float* __restrict__ Bp, float Rinv) {
    extern __shared__ __align__(128) char sm[];
    __shared__ float s_scale[256], s_shift[256];
    __shared__ float s_csum[128], s_css[128];
    const uint32_t uS = smem_to_u32(sm);

    const int tid  = threadIdx.x;
    const int wid  = tid >> 5;
    const int lane = tid & 31;
    const int m0     = blockIdx.y * 128;
    const int bnBase = blockIdx.x * 128;
    const int wm = (wid & 3) * 32;
    const int wn = (wid >> 2) * 64;

    for (int c = tid; c < K; c += 256) {
        float mean = g_stats[inSlot][0][c] * Rinv;
        float var  = g_stats[inSlot][1][c] * Rinv - mean * mean;
        float s    = Gp[c] * rsqrtf(var + BN_EPS);
        s_scale[c] = s;
        s_shift[c] = fmaf(-mean, s, Bp[c]);
    }
    if (tid < 128) { s_csum[tid] = 0.f; s_css[tid] = 0.f; }
    __syncthreads();

    float acc[2][8][4];
#pragma unroll
    for (int mt = 0; mt < 2; mt++)
#pragma unroll
        for (int nt = 0; nt < 8; nt++)
#pragma unroll
            for (int j = 0; j < 4; j++) acc[mt][nt][j] = 0.f;

    const int nchunks = K >> 5;
    const int arow_i = tid >> 1;
    const int acb    = (tid & 1) * 16;
    const int agr    = m0 + arow_i;
    float4 areg[4];

    {
#pragma unroll
        for (int j = 0; j < 2; j++) {
            int p = tid + j * 256;
            int n = p >> 2, f = p & 3;
            uint32_t sw = sw64(n * 64 + f * 16);
            cp16(uS + BHIo + sw, Bhi + (size_t)(bnBase + n) * K + f * 8);
            cp16(uS + BLOo + sw, Blo + (size_t)(bnBase + n) * K + f * 8);
        }
        CP_COMMIT();
        const float* ap = A + (size_t)agr * lda + acb;
#pragma unroll
        for (int f = 0; f < 4; f++)
            areg[f] = (agr < R) ? *reinterpret_cast<const float4*>(ap + f * 4)
                                : make_float4(0.f, 0.f, 0.f, 0.f);
    }

    for (int kc = 0; kc < nchunks; kc++) {
        const int s = kc & 1;
        const uint32_t uStage = uS + s * STG;
#pragma unroll
        for (int f = 0; f < 4; f++) {
            float4 v = areg[f];
            if (agr < R) {
                int k = kc * 32 + acb + f * 4;
                v.x = fmaxf(0.f, fmaf(v.x, s_scale[k + 0], s_shift[k + 0]));
                v.y = fmaxf(0.f, fmaf(v.y, s_scale[k + 1], s_shift[k + 1]));
                v.z = fmaxf(0.f, fmaf(v.z, s_scale[k + 2], s_shift[k + 2]));
                v.w = fmaxf(0.f, fmaf(v.w, s_scale[k + 3], s_shift[k + 3]));
            }
            __nv_bfloat162 hxy = __floats2bfloat162_rn(v.x, v.y);
            __nv_bfloat162 hzw = __floats2bfloat162_rn(v.z, v.w);
            __nv_bfloat162 lxy = __floats2bfloat162_rn(v.x - __low2float(hxy),
                                                       v.y - __high2float(hxy));
            __nv_bfloat162 lzw = __floats2bfloat162_rn(v.z - __low2float(hzw),
                                                       v.w - __high2float(hzw));
            uint32_t sw = sw64(arow_i * 64 + (acb + f * 4) * 2);
            *reinterpret_cast<uint2*>(sm + s * STG + AHIo + sw) =
                make_uint2(*reinterpret_cast<uint32_t*>(&hxy),
                           *reinterpret_cast<uint32_t*>(&hzw));
            *reinterpret_cast<uint2*>(sm + s * STG + ALOo + sw) =
                make_uint2(*reinterpret_cast<uint32_t*>(&lxy),
                           *reinterpret_cast<uint32_t*>(&lzw));
        }
        if (kc + 1 < nchunks) {
            const float* ap = A + (size_t)agr * lda + (kc + 1) * 32 + acb;
#pragma unroll
            for (int f = 0; f < 4; f++)
                areg[f] = (agr < R) ? *reinterpret_cast<const float4*>(ap + f * 4)
                                    : make_float4(0.f, 0.f, 0.f, 0.f);
        }
        CP_WAIT(0);
        __syncthreads();
        if (kc + 1 < nchunks) {
            const uint32_t uN = uS + (s ^ 1) * STG;
#pragma unroll
            for (int j = 0; j < 2; j++) {
                int p = tid + j * 256;
                int n = p >> 2, f = p & 3;
                uint32_t sw = sw64(n * 64 + f * 16);
                const size_t gsrc = (size_t)(bnBase + n) * K + (kc + 1) * 32 + f * 8;
                cp16(uN + BHIo + sw, Bhi + gsrc);
                cp16(uN + BLOo + sw, Blo + gsrc);
            }
            CP_COMMIT();
        }
#pragma unroll
        for (int st = 0; st < 2; st++) {
            const uint32_t kb = st * 32 + ((lane >> 4) << 4);
            uint32_t ah[2][4], al[2][4];
#pragma unroll
            for (int mt = 0; mt < 2; mt++) {
                uint32_t sw = sw64((wm + mt * 16 + (lane & 15)) * 64 + kb);
                LDMX4(ah[mt], uStage + AHIo + sw);
                LDMX4(al[mt], uStage + ALOo + sw);
            }
            uint32_t bf[4][4];
#pragma unroll
            for (int t = 0; t < 4; t++) {
                uint32_t sw = sw64((wn + t * 16 + (lane & 15)) * 64 + kb);
                LDMX4(bf[t], uStage + BHIo + sw);
            }
#pragma unroll
            for (int mt = 0; mt < 2; mt++)
#pragma unroll
                for (int t = 0; t < 4; t++) {
                    MMA16816(acc[mt][t * 2 + 0], ah[mt], bf[t][0], bf[t][2]);
                    MMA16816(acc[mt][t * 2 + 1], ah[mt], bf[t][1], bf[t][3]);
                    MMA16816(acc[mt][t * 2 + 0], al[mt], bf[t][0], bf[t][2]);
                    MMA16816(acc[mt][t * 2 + 1], al[mt], bf[t][1], bf[t][3]);
                }
#pragma unroll
            for (int t = 0; t < 4; t++) {
                uint32_t sw = sw64((wn + t * 16 + (lane & 15)) * 64 + kb);
                LDMX4(bf[t], uStage + BLOo + sw);
            }
#pragma unroll
            for (int mt = 0; mt < 2; mt++)
#pragma unroll
                for (int t = 0; t < 4; t++) {
                    MMA16816(acc[mt][t * 2 + 0], ah[mt], bf[t][0], bf[t][2]);
                    MMA16816(acc[mt][t * 2 + 1], ah[mt], bf[t][1], bf[t][3]);
                }
        }
    }

#pragma unroll
    for (int mt = 0; mt < 2; mt++) {
        const int row0 = m0 + wm + mt * 16 + (lane >> 2);
#pragma unroll
        for (int nt = 0; nt < 8; nt++) {
            float c0 = acc[mt][nt][0], c1 = acc[mt][nt][1];
            float c2 = acc[mt][nt][2], c3 = acc[mt][nt][3];
            const int cl = wn + nt * 8 + (lane & 3) * 2;
            if (row0 < R)
                *reinterpret_cast<float2*>(C + (size_t)row0 * ldc + bnBase + cl) =
                    make_float2(c0, c1);
            if (row0 + 8 < R)
                *reinterpret_cast<float2*>(C + (size_t)(row0 + 8) * ldc + bnBase + cl) =
                    make_float2(c2, c3);
            float se = c0 + c2, so = c1 + c3;
            float qe = fmaf(c0, c0, c2 * c2), qo = fmaf(c1, c1, c3 * c3);
#pragma unroll
            for (int off = 16; off >= 4; off >>= 1) {
                se += __shfl_down_sync(0xffffffffu, se, off);
                so += __shfl_down_sync(0xffffffffu, so, off);
                qe += __shfl_down_sync(0xffffffffu, qe, off);
                qo += __shfl_down_sync(0xffffffffu, qo, off);
            }
            if (lane < 4) {
                int c = wn + nt * 8 + lane * 2;
                atomicAdd(&s_csum[c], se); atomicAdd(&s_csum[c + 1], so);
                atomicAdd(&s_css [c], qe); atomicAdd(&s_css [c + 1], qo);
            }
        }
    }
    __syncthreads();
    if (tid < 256) {
        int c = tid & 127;
        int colg = bnBase + c;
        int slot = outSlotBase + (colg >> 8);
        int colIn = colg & 255;
        if (tid < 128) atomicAdd(&g_stats[slot][0][colIn], s_csum[c]);
        else           atomicAdd(&g_stats[slot][1][colIn], s_css[c]);
    }
}

// ---------------- consumers ----------------
__device__ __forceinline__ void bn_prep128(float* sc, float* sh, int slot,
                                           const float* G, const float* B, float Rinv) {
    int t = threadIdx.x;
    if (t < 128) {
        float mean = g_stats[slot][0][t] * Rinv;
        float var  = g_stats[slot][1][t] * Rinv - mean * mean;
        float s    = G[t] * rsqrtf(var + BN_EPS);
        sc[t] = s;
        sh[t] = fmaf(-mean, s, B[t]);
    }
    __syncthreads();
}

// edge_new -> bf16 hi/lo planes [NE,128]
__global__ void make_edge_new(const float* __restrict__ Y, const float* __restrict__ edge_rep,
                              const float* __restrict__ eps1, int slot,
                              const float* __restrict__ G, const float* __restrict__ B,
                              float Rinv,
                              __nv_bfloat16* __restrict__ Ahi, __nv_bfloat16* __restrict__ Alo) {
    __shared__ float sc[128], sh[128];
    bn_prep128(sc, sh, slot, G, B, Rinv);
    int i = blockIdx.x * 256 + threadIdx.x;
    if (i >= NE * 32) return;
    int h = (i & 31) * 4;
    float c = 1.f + eps1[0];
    float4 y = reinterpret_cast<const float4*>(Y)[i];
    float4 e = reinterpret_cast<const float4*>(edge_rep)[i];
    float4 o;
    o.x = fmaf(c, e.x, fmaxf(0.f, fmaf(y.x, sc[h + 0], sh[h + 0])));
    o.y = fmaf(c, e.y, fmaxf(0.f, fmaf(y.y, sc[h + 1], sh[h + 1])));
    o.z = fmaf(c, e.z, fmaxf(0.f, fmaf(y.z, sc[h + 2], sh[h + 2])));
    o.w = fmaf(c, e.w, fmaxf(0.f, fmaf(y.w, sc[h + 3], sh[h + 3])));
    split_store(Ahi, Alo, (size_t)i * 4, o);
}

__global__ void apply_out(const float* __restrict__ Y, float* __restrict__ out, int nvec,
                          int slot, const float* __restrict__ G, const float* __restrict__ B,
                          float Rinv) {
    __shared__ float sc[128], sh[128];
    bn_prep128(sc, sh, slot, G, B, Rinv);
    int i = blockIdx.x * 256 + threadIdx.x;
    if (i >= nvec) return;
    int h = (i & 31) * 4;
    float4 y = reinterpret_cast<const float4*>(Y)[i];
    float4 o;
    o.x = fmaxf(0.f, fmaf(y.x, sc[h + 0], sh[h + 0]));
    o.y = fmaxf(0.f, fmaf(y.y, sc[h + 1], sh[h + 1]));
    o.z = fmaxf(0.f, fmaf(y.z, sc[h + 2], sh[h + 2]));
    o.w = fmaxf(0.f, fmaf(y.w, sc[h + 3], sh[h + 3]));
    reinterpret_cast<float4*>(out)[i] = o;
}

__global__ void scatter_bnrelu(const float* __restrict__ Y, const int* __restrict__ src,
                               const int* __restrict__ dst, float* __restrict__ S,
                               int slot, const float* __restrict__ G,
                               const float* __restrict__ B, float Rinv) {
    __shared__ float sc[128], sh[128];
    bn_prep128(sc, sh, slot, G, B, Rinv);
    int tid = blockIdx.x * 256 + threadIdx.x;
    if (tid >= NE * 32) return;
    int e = tid >> 5, q = tid & 31;
    int h = q * 4;
    float4 y = reinterpret_cast<const float4*>(Y)[(size_t)e * 32 + q];
    float v0 = fmaxf(0.f, fmaf(y.x, sc[h + 0], sh[h + 0]));
    float v1 = fmaxf(0.f, fmaf(y.y, sc[h + 1], sh[h + 1]));
    float v2 = fmaxf(0.f, fmaf(y.z, sc[h + 2], sh[h + 2]));
    float v3 = fmaxf(0.f, fmaf(y.w, sc[h + 3], sh[h + 3]));
    int s = src[e], d = dst[e];
    red4(S + (size_t)s * HH + h, v0, v1, v2, v3);
    red4(S + (size_t)d * HH + h, v0, v1, v2, v3);
}

// node_in -> bf16 hi/lo planes [NN,128]
__global__ void make_node_in(const float* __restrict__ node_rep, const float* __restrict__ degree,
                             const float* __restrict__ S, const float* __restrict__ eps2,
                             __nv_bfloat16* __restrict__ Ahi, __nv_bfloat16* __restrict__ Alo) {
    int i = blockIdx.x * blockDim.x + threadIdx.x;
    if (i >= NN * 32) return;
    int n = i >> 5;
    float c = 1.f + eps2[0] - degree[n];
    float4 a = reinterpret_cast<const float4*>(node_rep)[i];
    float4 s = reinterpret_cast<const float4*>(S)[i];
    float4 o = make_float4(fmaf(c, a.x, s.x), fmaf(c, a.y, s.y),
                           fmaf(c, a.z, s.z), fmaf(c, a.w, s.w));
    split_store(Ahi, Alo, (size_t)i * 4, o);
}

// ---------------- host ----------------
extern "C" void kernel_launch(void* const* d_in, const int* in_sizes, int n_in,
                              void* d_out, int out_size) {
    const float* node_rep = (const float*)d_in[0];
    const float* edge_rep = (const float*)d_in[1];
    const float* degree   = (const float*)d_in[2];
    const int*   src      = (const int*)  d_in[3];
    const int*   dst      = (const int*)  d_in[4];
    const float* eps1     = (const float*)d_in[5];
    const float* eps2     = (const float*)d_in[6];
    const float* nW1 = (const float*)d_in[7],  *nG1 = (const float*)d_in[8],  *nB1 = (const float*)d_in[9];
    const float* nW2 = (const float*)d_in[10], *nG2 = (const float*)d_in[11], *nB2 = (const float*)d_in[12];
    const float* e0W1 = (const float*)d_in[13], *e0G1 = (const float*)d_in[14], *e0B1 = (const float*)d_in[15];
    const float* e0W2 = (const float*)d_in[16], *e0G2 = (const float*)d_in[17], *e0B2 = (const float*)d_in[18];
    const float* e1W1 = (const float*)d_in[19], *e1G1 = (const float*)d_in[20], *e1B1 = (const float*)d_in[21];
    const float* e1W2 = (const float*)d_in[22], *e1G2 = (const float*)d_in[23], *e1B2 = (const float*)d_in[24];
    const float* e2W1 = (const float*)d_in[25], *e2G1 = (const float*)d_in[26], *e2B1 = (const float*)d_in[27];
    const float* e2W2 = (const float*)d_in[28], *e2G2 = (const float*)d_in[29], *e2B2 = (const float*)d_in[30];

    float* out_node = (float*)d_out;
    float* out_edge = out_node + (size_t)NN * HH;

    cudaFuncSetAttribute(gemm_a16, cudaFuncAttributeMaxDynamicSharedMemorySize, GSMEM16);
    cudaFuncSetAttribute(gemm_a32, cudaFuncAttributeMaxDynamicSharedMemorySize, GSMEM32);

    float *S, *Hb, *Y, *Y2;
    __nv_bfloat16 *AHI, *ALO, *Whi, *Wlo;
    cudaGetSymbolAddress((void**)&S,  g_S);
    cudaGetSymbolAddress((void**)&Hb, g_Hb);
    cudaGetSymbolAddress((void**)&Y,  g_Y);
    cudaGetSymbolAddress((void**)&Y2, g_Y2);
    cudaGetSymbolAddress((void**)&AHI, g_AHI);
    cudaGetSymbolAddress((void**)&ALO, g_ALO);
    cudaGetSymbolAddress((void**)&Whi, g_Whi);
    cudaGetSymbolAddress((void**)&Wlo, g_Wlo);

    const int EV = NE * 32;
    const int NV = NN * 32;
    const float RinvE = 1.0f / (float)NE;
    const float RinvN = 1.0f / (float)NN;
    const unsigned gyE = (unsigned)cdivl(NE, 128);
    const unsigned gyN = (unsigned)cdivl(NN, 128);

    init_all<<<(unsigned)cdivl(INIT_TOTAL, 256), 256>>>(e0W1, e0W2, e1W1, e2W1,
                                                        e1W2, e2W2, nW1, nW2);
    scatter_edge<<<(unsigned)cdivl(EV, 256), 256>>>(edge_rep, src, dst, S);
    build_x0<<<(unsigned)cdivl(EV, 256), 256>>>(node_rep, S, src, dst, AHI, ALO);

    // e0 L1: X0 planes [NE,256] @ W -> Hb[:,0:256], slot 0
    gemm_a16<<<dim3(2, gyE), 256, GSMEM16>>>(AHI, ALO, H2, Whi + OFF_E0W1, Wlo + OFF_E0W1,
                                             Hb, 512, NE, H2, 0);
    // e0 L2: BN(slot0, Hb) -> Y, slot 1
    gemm_a32<<<dim3(1, gyE), 256, GSMEM32>>>(Hb, 512, Whi + OFF_E0W2, Wlo + OFF_E0W2,
                                             Y, 128, NE, H2, 0, 1, e0G1, e0B1, RinvE);
    // edge_new -> planes [NE,128]
    make_edge_new<<<(unsigned)cdivl(EV, 256), 256>>>(Y, edge_rep, eps1, 1, e0G2, e0B2,
                                                     RinvE, AHI, ALO);
    // merged e1L1+e2L1: EN planes @ Wcat[512x128] -> Hb[:,0:512], slots 2,3
    gemm_a16<<<dim3(4, gyE), 256, GSMEM16>>>(AHI, ALO, HH, Whi + OFF_E1W1, Wlo + OFF_E1W1,
                                             Hb, 512, NE, HH, 2);
    // e1 L2: BN(slot2, Hb[:,0:256]) -> Y, slot 4
    gemm_a32<<<dim3(1, gyE), 256, GSMEM32>>>(Hb, 512, Whi + OFF_E1W2, Wlo + OFF_E1W2,
                                             Y, 128, NE, H2, 2, 4, e1G1, e1B1, RinvE);
    // e2 L2: BN(slot3, Hb[:,256:512]) -> Y2, slot 5
    gemm_a32<<<dim3(1, gyE), 256, GSMEM32>>>(Hb + 256, 512, Whi + OFF_E2W2, Wlo + OFF_E2W2,
                                             Y2, 128, NE, H2, 3, 5, e2G1, e2B1, RinvE);
    apply_out<<<(unsigned)cdivl(EV, 256), 256>>>(Y, out_edge, EV, 4, e1G2, e1B2, RinvE);
    zero_f4<<<(unsigned)cdivl((long)NN * HH / 4, 256), 256>>>((float4*)S, NN * HH / 4);
    scatter_bnrelu<<<(unsigned)cdivl(EV, 256), 256>>>(Y2, src, dst, S, 5, e2G2, e2B2, RinvE);
    // node_in -> planes [NN,128]
    make_node_in<<<(unsigned)cdivl(NV, 256), 256>>>(node_rep, degree, S, eps2, AHI, ALO);
    // node L1: NI planes @ W[128,256] -> Hb[:,0:256], slot 6
    gemm_a16<<<dim3(2, gyN), 256, GSMEM16>>>(AHI, ALO, HH, Whi + OFF_NW1, Wlo + OFF_NW1,
                                             Hb, 512, NN, HH, 6);
    // node L2: BN(slot6) -> Y, slot 7
    gemm_a32<<<dim3(1, gyN), 256, GSMEM32>>>(Hb, 512, Whi + OFF_NW2, Wlo + OFF_NW2,
                                             Y, 128, NN, H2, 6, 7, nG1, nB1, RinvN);
    apply_out<<<(unsigned)cdivl(NV, 256), 256>>>(Y, out_node, NV, 7, nG2, nB2, RinvN);
}

// round 9
// speedup vs baseline: 2.3658x; 1.0029x over previous
#include <cuda_runtime.h>
#include <cuda_bf16.h>
#include <cstdint>
#include <cstddef>

#define NN 50000
#define NE 400000
#define HH 128
#define H2 256
#define BN_EPS 1e-5f

// ---------------- scratch ----------------
static __device__ float g_S [(size_t)NN * HH];
static __device__ float g_Hb[(size_t)NE * 512];
static __device__ float g_Y [(size_t)NE * HH];
static __device__ float g_Y2[(size_t)NE * HH];
static __device__ float g_stats[8][2][256];
static __device__ __nv_bfloat16 g_AHI[(size_t)NE * H2];
static __device__ __nv_bfloat16 g_ALO[(size_t)NE * H2];
static __device__ __nv_bfloat16 g_Whi[294912];
static __device__ __nv_bfloat16 g_Wlo[294912];

#define OFF_E0W1 0
#define OFF_E0W2 65536
#define OFF_E1W1 98304
#define OFF_E2W1 131072
#define OFF_E1W2 163840
#define OFF_E2W2 196608
#define OFF_NW1  229376
#define OFF_NW2  262144

static inline long cdivl(long a, long b) { return (a + b - 1) / b; }

__device__ __forceinline__ uint32_t smem_to_u32(const void* p) {
    uint32_t a;
    asm("{ .reg .u64 t; cvta.to.shared.u64 t, %1; cvt.u32.u64 %0, t; }" : "=r"(a) : "l"(p));
    return a;
}

#define LDMX4(r, addr) \
    asm volatile("ldmatrix.sync.aligned.m8n8.x4.shared.b16 {%0,%1,%2,%3}, [%4];" \
        : "=r"((r)[0]), "=r"((r)[1]), "=r"((r)[2]), "=r"((r)[3]) : "r"(addr))

#define MMA16816(d, a, b0, b1) \
    asm volatile("mma.sync.aligned.m16n8k16.row.col.f32.bf16.bf16.f32 " \
        "{%0,%1,%2,%3},{%4,%5,%6,%7},{%8,%9},{%0,%1,%2,%3};" \
        : "+f"((d)[0]), "+f"((d)[1]), "+f"((d)[2]), "+f"((d)[3]) \
        : "r"((a)[0]), "r"((a)[1]), "r"((a)[2]), "r"((a)[3]), "r"(b0), "r"(b1))

__device__ __forceinline__ void cp16(uint32_t dst, const void* src) {
    asm volatile("cp.async.cg.shared.global [%0], [%1], 16;" :: "r"(dst), "l"(src));
}
#define CP_COMMIT() asm volatile("cp.async.commit_group;" ::: "memory")
#define CP_WAIT(n)  asm volatile("cp.async.wait_group %0;" :: "n"(n) : "memory")

__device__ __forceinline__ void red4(float* p, float a, float b, float c, float d) {
    asm volatile("red.global.add.v4.f32 [%0], {%1,%2,%3,%4};"
                 :: "l"(p), "f"(a), "f"(b), "f"(c), "f"(d) : "memory");
}

__device__ __forceinline__ uint32_t sw64(uint32_t off) {
    return off ^ ((off >> 3) & 0x30);
}

__device__ __forceinline__ void split_store(__nv_bfloat16* hi, __nv_bfloat16* lo,
                                            size_t idx, float4 v) {
    __nv_bfloat162 hxy = __floats2bfloat162_rn(v.x, v.y);
    __nv_bfloat162 hzw = __floats2bfloat162_rn(v.z, v.w);
    __nv_bfloat162 lxy = __floats2bfloat162_rn(v.x - __low2float(hxy),
                                               v.y - __high2float(hxy));
    __nv_bfloat162 lzw = __floats2bfloat162_rn(v.z - __low2float(hzw),
                                               v.w - __high2float(hzw));
    *reinterpret_cast<uint2*>(hi + idx) =
        make_uint2(*reinterpret_cast<uint32_t*>(&hxy), *reinterpret_cast<uint32_t*>(&hzw));
    *reinterpret_cast<uint2*>(lo + idx) =
        make_uint2(*reinterpret_cast<uint32_t*>(&lxy), *reinterpret_cast<uint32_t*>(&lzw));
}

// ---------------- init ----------------
#define NS4 ((NN * HH) / 4)
#define INIT_TOTAL (NS4 + 1024 + 294912)

__global__ void init_all(const float* w0, const float* w1, const float* w2, const float* w3,
                         const float* w4, const float* w5, const float* w6, const float* w7) {
    int gid = blockIdx.x * blockDim.x + threadIdx.x;
    if (gid < NS4) {
        reinterpret_cast<float4*>(g_S)[gid] = make_float4(0.f, 0.f, 0.f, 0.f);
        return;
    }
    gid -= NS4;
    if (gid < 1024) {
        reinterpret_cast<float4*>(g_stats)[gid] = make_float4(0.f, 0.f, 0.f, 0.f);
        return;
    }
    gid -= 1024;
    if (gid >= 294912) return;
    const float* ws[8] = {w0, w1, w2, w3, w4, w5, w6, w7};
    const int segSize[8] = {65536, 32768, 32768, 32768, 32768, 32768, 32768, 32768};
    const int segK[8]    = {256, 256, 128, 128, 256, 256, 128, 256};
    int seg = 0, base = 0, idx = gid;
#pragma unroll
    for (int s = 0; s < 8; s++) {
        if (idx < segSize[s]) { seg = s; break; }
        idx -= segSize[s];
        base += segSize[s];
    }
    int Kw = segK[seg];
    int Nw = segSize[seg] / Kw;
    int k = idx / Nw, n = idx % Nw;
    float w = ws[seg][idx];
    __nv_bfloat16 h = __float2bfloat16(w);
    __nv_bfloat16 l = __float2bfloat16(w - __bfloat162float(h));
    g_Whi[base + n * Kw + k] = h;
    g_Wlo[base + n * Kw + k] = l;
}

// ---------------- graph kernels ----------------
__global__ void zero_f4(float4* p, int n4) {
    int i = blockIdx.x * blockDim.x + threadIdx.x;
    if (i < n4) p[i] = make_float4(0.f, 0.f, 0.f, 0.f);
}

__global__ void scatter_edge(const float* __restrict__ edge_rep,
                             const int* __restrict__ src, const int* __restrict__ dst,
                             float* __restrict__ S) {
    int tid = blockIdx.x * blockDim.x + threadIdx.x;
    if (tid >= NE * 32) return;
    int e = tid >> 5, q = tid & 31;
    float4 v = reinterpret_cast<const float4*>(edge_rep)[(size_t)e * 32 + q];
    int s = src[e], d = dst[e];
    red4(S + (size_t)s * HH + q * 4, v.x, v.y, v.z, v.w);
    red4(S + (size_t)d * HH + q * 4, v.x, v.y, v.z, v.w);
}

__global__ void build_x0(const float* __restrict__ node_rep, const float* __restrict__ S,
                         const int* __restrict__ src, const int* __restrict__ dst,
                         __nv_bfloat16* __restrict__ Ahi, __nv_bfloat16* __restrict__ Alo) {
    int tid = blockIdx.x * blockDim.x + threadIdx.x;
    if (tid >= NE * 32) return;
    int e = tid >> 5, q = tid & 31;
    int s = src[e], d = dst[e];
    const float4* nr4 = reinterpret_cast<const float4*>(node_rep);
    const float4* S4  = reinterpret_cast<const float4*>(S);
    float4 a0 = nr4[(size_t)s * 32 + q], a1 = nr4[(size_t)d * 32 + q];
    float4 b0 = S4 [(size_t)s * 32 + q], b1 = S4 [(size_t)d * 32 + q];
    float4 a = make_float4(a0.x + a1.x, a0.y + a1.y, a0.z + a1.z, a0.w + a1.w);
    float4 b = make_float4(b0.x + b1.x, b0.y + b1.y, b0.z + b1.z, b0.w + b1.w);
    split_store(Ahi, Alo, (size_t)e * 256 + q * 4, a);
    split_store(Ahi, Alo, (size_t)e * 256 + 128 + q * 4, b);
}

// ---------------- shared MMA core: 3 passes, long dependency distance ----------------
// rAoffs[mt], rBoffs[t]: row byte offsets (pre-swizzle); kb in {kb0, kb0+32}.
#define MMA_CHUNK(uStage, acc, rAoff, rBoff, kb)                                   \
    do {                                                                           \
        uint32_t ah[2][4], al[2][4], bb[4][4];                                     \
        _Pragma("unroll")                                                          \
        for (int mt = 0; mt < 2; mt++) {                                           \
            uint32_t sw = sw64(rAoff[mt] + (kb));                                  \
            LDMX4(ah[mt], (uStage) + AHIo + sw);                                   \
            LDMX4(al[mt], (uStage) + ALOo + sw);                                   \
        }                                                                          \
        _Pragma("unroll")                                                          \
        for (int t = 0; t < 4; t++) {                                              \
            uint32_t sw = sw64(rBoff[t] + (kb));                                   \
            LDMX4(bb[t], (uStage) + BHIo + sw);                                    \
        }                                                                          \
        /* pass 1: hi x hi  (16 independent MMAs) */                               \
        _Pragma("unroll")                                                          \
        for (int mt = 0; mt < 2; mt++)                                             \
            _Pragma("unroll")                                                      \
            for (int t = 0; t < 4; t++) {                                          \
                MMA16816(acc[mt][t * 2 + 0], ah[mt], bb[t][0], bb[t][2]);          \
                MMA16816(acc[mt][t * 2 + 1], ah[mt], bb[t][1], bb[t][3]);          \
            }                                                                      \
        /* pass 2: lo x hi (each dep at distance 16) */                            \
        _Pragma("unroll")                                                          \
        for (int mt = 0; mt < 2; mt++)                                             \
            _Pragma("unroll")                                                      \
            for (int t = 0; t < 4; t++) {                                          \
                MMA16816(acc[mt][t * 2 + 0], al[mt], bb[t][0], bb[t][2]);          \
                MMA16816(acc[mt][t * 2 + 1], al[mt], bb[t][1], bb[t][3]);          \
            }                                                                      \
        /* reload B lo */                                                          \
        _Pragma("unroll")                                                          \
        for (int t = 0; t < 4; t++) {                                              \
            uint32_t sw = sw64(rBoff[t] + (kb));                                   \
            LDMX4(bb[t], (uStage) + BLOo + sw);                                    \
        }                                                                          \
        /* pass 3: hi x lo */                                                      \
        _Pragma("unroll")                                                          \
        for (int mt = 0; mt < 2; mt++)                                             \
            _Pragma("unroll")                                                      \
            for (int t = 0; t < 4; t++) {                                          \
                MMA16816(acc[mt][t * 2 + 0], ah[mt], bb[t][0], bb[t][2]);          \
                MMA16816(acc[mt][t * 2 + 1], ah[mt], bb[t][1], bb[t][3]);          \
            }                                                                      \
    } while (0)

#define AHIo 0
#define ALOo 8192
#define BHIo 16384
#define BLOo 24576
#define STG  32768
#define GSMEM16 (3 * STG)
#define GSMEM32 (2 * STG)

// ---------------- GEMM a16: pre-split bf16 A planes, pure cp.async, 3 stages ----------------
__global__ void __launch_bounds__(256, 2)
gemm_a16(const __nv_bfloat16* __restrict__ Ahi, const __nv_bfloat16* __restrict__ Alo,
         int lda,
         const __nv_bfloat16* __restrict__ Bhi, const __nv_bfloat16* __restrict__ Blo,
         float* __restrict__ C, int ldc, int R, int K, int outSlotBase) {
    extern __shared__ __align__(128) char sm[];
    __shared__ float s_csum[128], s_css[128];
    const uint32_t uS = smem_to_u32(sm);

    const int tid  = threadIdx.x;
    const int wid  = tid >> 5;
    const int lane = tid & 31;
    const int m0     = blockIdx.y * 128;
    const int bnBase = blockIdx.x * 128;
    const int wm = (wid & 3) * 32;
    const int wn = (wid >> 2) * 64;

    if (tid < 128) { s_csum[tid] = 0.f; s_css[tid] = 0.f; }
    __syncthreads();

    float acc[2][8][4];
#pragma unroll
    for (int mt = 0; mt < 2; mt++)
#pragma unroll
        for (int nt = 0; nt < 8; nt++)
#pragma unroll
            for (int j = 0; j < 4; j++) acc[mt][nt][j] = 0.f;

    const int nchunks = K >> 5;

    uint32_t rAoff[2], rBoff[4];
#pragma unroll
    for (int mt = 0; mt < 2; mt++) rAoff[mt] = (wm + mt * 16 + (lane & 15)) * 64;
#pragma unroll
    for (int t = 0; t < 4; t++)    rBoff[t]  = (wn + t * 16 + (lane & 15)) * 64;
    const uint32_t kb0 = (lane >> 4) << 4;

    const int p0row = tid >> 2,          p0f = tid & 3;
    const int p1row = (tid + 256) >> 2,  p1f = (tid + 256) & 3;
    const uint32_t sw0 = sw64(p0row * 64 + p0f * 16);
    const uint32_t sw1 = sw64(p1row * 64 + p1f * 16);

    auto issue = [&](int kc) {
        uint32_t uDst = uS + (kc % 3) * STG;
        {
            const size_t asrc = (size_t)(m0 + p0row) * lda + kc * 32 + p0f * 8;
            const size_t bsrc = (size_t)(bnBase + p0row) * K + kc * 32 + p0f * 8;
            cp16(uDst + AHIo + sw0, Ahi + asrc);
            cp16(uDst + ALOo + sw0, Alo + asrc);
            cp16(uDst + BHIo + sw0, Bhi + bsrc);
            cp16(uDst + BLOo + sw0, Blo + bsrc);
        }
        {
            const size_t asrc = (size_t)(m0 + p1row) * lda + kc * 32 + p1f * 8;
            const size_t bsrc = (size_t)(bnBase + p1row) * K + kc * 32 + p1f * 8;
            cp16(uDst + AHIo + sw1, Ahi + asrc);
            cp16(uDst + ALOo + sw1, Alo + asrc);
            cp16(uDst + BHIo + sw1, Bhi + bsrc);
            cp16(uDst + BLOo + sw1, Blo + bsrc);
        }
        CP_COMMIT();
    };

    issue(0);
    if (nchunks > 1) issue(1);

    for (int kc = 0; kc < nchunks; kc++) {
        if (kc + 1 < nchunks) { CP_WAIT(1); } else { CP_WAIT(0); }
        __syncthreads();
        if (kc + 2 < nchunks) issue(kc + 2);
        const uint32_t uStage = uS + (kc % 3) * STG;
        MMA_CHUNK(uStage, acc, rAoff, rBoff, kb0);
        MMA_CHUNK(uStage, acc, rAoff, rBoff, kb0 + 32);
    }

#pragma unroll
    for (int mt = 0; mt < 2; mt++) {
        const int row0 = m0 + wm + mt * 16 + (lane >> 2);
#pragma unroll
        for (int nt = 0; nt < 8; nt++) {
            float c0 = acc[mt][nt][0], c1 = acc[mt][nt][1];
            float c2 = acc[mt][nt][2], c3 = acc[mt][nt][3];
            const int cl = wn + nt * 8 + (lane & 3) * 2;
            if (row0 < R)
                *reinterpret_cast<float2*>(C + (size_t)row0 * ldc + bnBase + cl) =
                    make_float2(c0, c1);
            else { c0 = 0.f; c1 = 0.f; }
            if (row0 + 8 < R)
                *reinterpret_cast<float2*>(C + (size_t)(row0 + 8) * ldc + bnBase + cl) =
                    make_float2(c2, c3);
            else { c2 = 0.f; c3 = 0.f; }
            float se = c0 + c2, so = c1 + c3;
            float qe = fmaf(c0, c0, c2 * c2), qo = fmaf(c1, c1, c3 * c3);
#pragma unroll
            for (int off = 16; off >= 4; off >>= 1) {
                se += __shfl_down_sync(0xffffffffu, se, off);
                so += __shfl_down_sync(0xffffffffu, so, off);
                qe += __shfl_down_sync(0xffffffffu, qe, off);
                qo += __shfl_down_sync(0xffffffffu, qo, off);
            }
            if (lane < 4) {
                int c = wn + nt * 8 + lane * 2;
                atomicAdd(&s_csum[c], se); atomicAdd(&s_csum[c + 1], so);
                atomicAdd(&s_css [c], qe); atomicAdd(&s_css [c + 1], qo);
            }
        }
    }
    __syncthreads();
    if (tid < 256) {
        int c = tid & 127;
        int colg = bnBase + c;
        int slot = outSlotBase + (colg >> 8);
        int colIn = colg & 255;
        if (tid < 128) atomicAdd(&g_stats[slot][0][colIn], s_csum[c]);
        else           atomicAdd(&g_stats[slot][1][colIn], s_css[c]);
    }
}

// ---------------- GEMM a32: fp32 A + fused BN+ReLU conversion (layer 2) ----------------
__global__ void __launch_bounds__(256, 2)
gemm_a32(const float* __restrict__ A, int lda,
         const __nv_bfloat16* __restrict__ Bhi, const __nv_bfloat16* __restrict__ Blo,
         float* __restrict__ C, int ldc, int R, int K,
         int inSlot, int outSlotBase,
         const float* __restrict__ Gp, const float* __restrict__ Bp, float Rinv) {
    extern __shared__ __align__(128) char sm[];
    __shared__ float s_scale[256], s_shift[256];
    __shared__ float s_csum[128], s_css[128];
    const uint32_t uS = smem_to_u32(sm);

    const int tid  = threadIdx.x;
    const int wid  = tid >> 5;
    const int lane = tid & 31;
    const int m0     = blockIdx.y * 128;
    const int bnBase = blockIdx.x * 128;
    const int wm = (wid & 3) * 32;
    const int wn = (wid >> 2) * 64;

    for (int c = tid; c < K; c += 256) {
        float mean = g_stats[inSlot][0][c] * Rinv;
        float var  = g_stats[inSlot][1][c] * Rinv - mean * mean;
        float s    = Gp[c] * rsqrtf(var + BN_EPS);
        s_scale[c] = s;
        s_shift[c] = fmaf(-mean, s, Bp[c]);
    }
    if (tid < 128) { s_csum[tid] = 0.f; s_css[tid] = 0.f; }
    __syncthreads();

    float acc[2][8][4];
#pragma unroll
    for (int mt = 0; mt < 2; mt++)
#pragma unroll
        for (int nt = 0; nt < 8; nt++)
#pragma unroll
            for (int j = 0; j < 4; j++) acc[mt][nt][j] = 0.f;

    const int nchunks = K >> 5;
    const int arow_i = tid >> 1;
    const int acb    = (tid & 1) * 16;
    const int agr    = m0 + arow_i;
    float4 areg[4];

    uint32_t rAoff[2], rBoff[4];
#pragma unroll
    for (int mt = 0; mt < 2; mt++) rAoff[mt] = (wm + mt * 16 + (lane & 15)) * 64;
#pragma unroll
    for (int t = 0; t < 4; t++)    rBoff[t]  = (wn + t * 16 + (lane & 15)) * 64;
    const uint32_t kb0 = (lane >> 4) << 4;

    {
#pragma unroll
        for (int j = 0; j < 2; j++) {
            int p = tid + j * 256;
            int n = p >> 2, f = p & 3;
            uint32_t sw = sw64(n * 64 + f * 16);
            cp16(uS + BHIo + sw, Bhi + (size_t)(bnBase + n) * K + f * 8);
            cp16(uS + BLOo + sw, Blo + (size_t)(bnBase + n) * K + f * 8);
        }
        CP_COMMIT();
        const float* ap = A + (size_t)agr * lda + acb;
#pragma unroll
        for (int f = 0; f < 4; f++)
            areg[f] = (agr < R) ? *reinterpret_cast<const float4*>(ap + f * 4)
                                : make_float4(0.f, 0.f, 0.f, 0.f);
    }

    for (int kc = 0; kc < nchunks; kc++) {
        const int s = kc & 1;
        const uint32_t uStage = uS + s * STG;
#pragma unroll
        for (int f = 0; f < 4; f++) {
            float4 v = areg[f];
            if (agr < R) {
                int k = kc * 32 + acb + f * 4;
                v.x = fmaxf(0.f, fmaf(v.x, s_scale[k + 0], s_shift[k + 0]));
                v.y = fmaxf(0.f, fmaf(v.y, s_scale[k + 1], s_shift[k + 1]));
                v.z = fmaxf(0.f, fmaf(v.z, s_scale[k + 2], s_shift[k + 2]));
                v.w = fmaxf(0.f, fmaf(v.w, s_scale[k + 3], s_shift[k + 3]));
            }
            __nv_bfloat162 hxy = __floats2bfloat162_rn(v.x, v.y);
            __nv_bfloat162 hzw = __floats2bfloat162_rn(v.z, v.w);
            __nv_bfloat162 lxy = __floats2bfloat162_rn(v.x - __low2float(hxy),
                                                       v.y - __high2float(hxy));
            __nv_bfloat162 lzw = __floats2bfloat162_rn(v.z - __low2float(hzw),
                                                       v.w - __high2float(hzw));
            uint32_t sw = sw64(arow_i * 64 + (acb + f * 4) * 2);
            *reinterpret_cast<uint2*>(sm + s * STG + AHIo + sw) =
                make_uint2(*reinterpret_cast<uint32_t*>(&hxy),
                           *reinterpret_cast<uint32_t*>(&hzw));
            *reinterpret_cast<uint2*>(sm + s * STG + ALOo + sw) =
                make_uint2(*reinterpret_cast<uint32_t*>(&lxy),
                           *reinterpret_cast<uint32_t*>(&lzw));
        }
        if (kc + 1 < nchunks) {
            const float* ap = A + (size_t)agr * lda + (kc + 1) * 32 + acb;
#pragma unroll
            for (int f = 0; f < 4; f++)
                areg[f] = (agr < R) ? *reinterpret_cast<const float4*>(ap + f * 4)
                                    : make_float4(0.f, 0.f, 0.f, 0.f);
        }
        CP_WAIT(0);
        __syncthreads();
        if (kc + 1 < nchunks) {
            const uint32_t uN = uS + (s ^ 1) * STG;
#pragma unroll
            for (int j = 0; j < 2; j++) {
                int p = tid + j * 256;
                int n = p >> 2, f = p & 3;
                uint32_t sw = sw64(n * 64 + f * 16);
                const size_t gsrc = (size_t)(bnBase + n) * K + (kc + 1) * 32 + f * 8;
                cp16(uN + BHIo + sw, Bhi + gsrc);
                cp16(uN + BLOo + sw, Blo + gsrc);
            }
            CP_COMMIT();
        }
        MMA_CHUNK(uStage, acc, rAoff, rBoff, kb0);
        MMA_CHUNK(uStage, acc, rAoff, rBoff, kb0 + 32);
    }

#pragma unroll
    for (int mt = 0; mt < 2; mt++) {
        const int row0 = m0 + wm + mt * 16 + (lane >> 2);
#pragma unroll
        for (int nt = 0; nt < 8; nt++) {
            float c0 = acc[mt][nt][0], c1 = acc[mt][nt][1];
            float c2 = acc[mt][nt][2], c3 = acc[mt][nt][3];
            const int cl = wn + nt * 8 + (lane & 3) * 2;
            if (row0 < R)
                *reinterpret_cast<float2*>(C + (size_t)row0 * ldc + bnBase + cl) =
                    make_float2(c0, c1);
            if (row0 + 8 < R)
                *reinterpret_cast<float2*>(C + (size_t)(row0 + 8) * ldc + bnBase + cl) =
                    make_float2(c2, c3);
            float se = c0 + c2, so = c1 + c3;
            float qe = fmaf(c0, c0, c2 * c2), qo = fmaf(c1, c1, c3 * c3);
#pragma unroll
            for (int off = 16; off >= 4; off >>= 1) {
                se += __shfl_down_sync(0xffffffffu, se, off);
                so += __shfl_down_sync(0xffffffffu, so, off);
                qe += __shfl_down_sync(0xffffffffu, qe, off);
                qo += __shfl_down_sync(0xffffffffu, qo, off);
            }
            if (lane < 4) {
                int c = wn + nt * 8 + lane * 2;
                atomicAdd(&s_csum[c], se); atomicAdd(&s_csum[c + 1], so);
                atomicAdd(&s_css [c], qe); atomicAdd(&s_css [c + 1], qo);
            }
        }
    }
    __syncthreads();
    if (tid < 256) {
        int c = tid & 127;
        int colg = bnBase + c;
        int slot = outSlotBase + (colg >> 8);
        int colIn = colg & 255;
        if (tid < 128) atomicAdd(&g_stats[slot][0][colIn], s_csum[c]);
        else           atomicAdd(&g_stats[slot][1][colIn], s_css[c]);
    }
}

// ---------------- consumers ----------------
__device__ __forceinline__ void bn_prep128(float* sc, float* sh, int slot,
                                           const float* G, const float* B, float Rinv) {
    int t = threadIdx.x;
    if (t < 128) {
        float mean = g_stats[slot][0][t] * Rinv;
        float var  = g_stats[slot][1][t] * Rinv - mean * mean;
        float s    = G[t] * rsqrtf(var + BN_EPS);
        sc[t] = s;
        sh[t] = fmaf(-mean, s, B[t]);
    }
    __syncthreads();
}

__global__ void make_edge_new(const float* __restrict__ Y, const float* __restrict__ edge_rep,
                              const float* __restrict__ eps1, int slot,
                              const float* __restrict__ G, const float* __restrict__ B,
                              float Rinv,
                              __nv_bfloat16* __restrict__ Ahi, __nv_bfloat16* __restrict__ Alo) {
    __shared__ float sc[128], sh[128];
    bn_prep128(sc, sh, slot, G, B, Rinv);
    int i = blockIdx.x * 256 + threadIdx.x;
    if (i >= NE * 32) return;
    int h = (i & 31) * 4;
    float c = 1.f + eps1[0];
    float4 y = reinterpret_cast<const float4*>(Y)[i];
    float4 e = reinterpret_cast<const float4*>(edge_rep)[i];
    float4 o;
    o.x = fmaf(c, e.x, fmaxf(0.f, fmaf(y.x, sc[h + 0], sh[h + 0])));
    o.y = fmaf(c, e.y, fmaxf(0.f, fmaf(y.y, sc[h + 1], sh[h + 1])));
    o.z = fmaf(c, e.z, fmaxf(0.f, fmaf(y.z, sc[h + 2], sh[h + 2])));
    o.w = fmaf(c, e.w, fmaxf(0.f, fmaf(y.w, sc[h + 3], sh[h + 3])));
    split_store(Ahi, Alo, (size_t)i * 4, o);
}

__global__ void apply_out(const float* __restrict__ Y, float* __restrict__ out, int nvec,
                          int slot, const float* __restrict__ G, const float* __restrict__ B,
                          float Rinv) {
    __shared__ float sc[128], sh[128];
    bn_prep128(sc, sh, slot, G, B, Rinv);
    int i = blockIdx.x * 256 + threadIdx.x;
    if (i >= nvec) return;
    int h = (i & 31) * 4;
    float4 y = reinterpret_cast<const float4*>(Y)[i];
    float4 o;
    o.x = fmaxf(0.f, fmaf(y.x, sc[h + 0], sh[h + 0]));
    o.y = fmaxf(0.f, fmaf(y.y, sc[h + 1], sh[h + 1]));
    o.z = fmaxf(0.f, fmaf(y.z, sc[h + 2], sh[h + 2]));
    o.w = fmaxf(0.f, fmaf(y.w, sc[h + 3], sh[h + 3]));
    reinterpret_cast<float4*>(out)[i] = o;
}

__global__ void scatter_bnrelu(const float* __restrict__ Y, const int* __restrict__ src,
                               const int* __restrict__ dst, float* __restrict__ S,
                               int slot, const float* __restrict__ G,
                               const float* __restrict__ B, float Rinv) {
    __shared__ float sc[128], sh[128];
    bn_prep128(sc, sh, slot, G, B, Rinv);
    int tid = blockIdx.x * 256 + threadIdx.x;
    if (tid >= NE * 32) return;
    int e = tid >> 5, q = tid & 31;
    int h = q * 4;
    float4 y = reinterpret_cast<const float4*>(Y)[(size_t)e * 32 + q];
    float v0 = fmaxf(0.f, fmaf(y.x, sc[h + 0], sh[h + 0]));
    float v1 = fmaxf(0.f, fmaf(y.y, sc[h + 1], sh[h + 1]));
    float v2 = fmaxf(0.f, fmaf(y.z, sc[h + 2], sh[h + 2]));
    float v3 = fmaxf(0.f, fmaf(y.w, sc[h + 3], sh[h + 3]));
    int s = src[e], d = dst[e];
    red4(S + (size_t)s * HH + h, v0, v1, v2, v3);
    red4(S + (size_t)d * HH + h, v0, v1, v2, v3);
}

__global__ void make_node_in(const float* __restrict__ node_rep, const float* __restrict__ degree,
                             const float* __restrict__ S, const float* __restrict__ eps2,
                             __nv_bfloat16* __restrict__ Ahi, __nv_bfloat16* __restrict__ Alo) {
    int i = blockIdx.x * blockDim.x + threadIdx.x;
    if (i >= NN * 32) return;
    int n = i >> 5;
    float c = 1.f + eps2[0] - degree[n];
    float4 a = reinterpret_cast<const float4*>(node_rep)[i];
    float4 s = reinterpret_cast<const float4*>(S)[i];
    float4 o = make_float4(fmaf(c, a.x, s.x), fmaf(c, a.y, s.y),
                           fmaf(c, a.z, s.z), fmaf(c, a.w, s.w));
    split_store(Ahi, Alo, (size_t)i * 4, o);
}

// ---------------- host ----------------
extern "C" void kernel_launch(void* const* d_in, const int* in_sizes, int n_in,
                              void* d_out, int out_size) {
    const float* node_rep = (const float*)d_in[0];
    const float* edge_rep = (const float*)d_in[1];
    const float* degree   = (const float*)d_in[2];
    const int*   src      = (const int*)  d_in[3];
    const int*   dst      = (const int*)  d_in[4];
    const float* eps1     = (const float*)d_in[5];
    const float* eps2     = (const float*)d_in[6];
    const float* nW1 = (const float*)d_in[7],  *nG1 = (const float*)d_in[8],  *nB1 = (const float*)d_in[9];
    const float* nW2 = (const float*)d_in[10], *nG2 = (const float*)d_in[11], *nB2 = (const float*)d_in[12];
    const float* e0W1 = (const float*)d_in[13], *e0G1 = (const float*)d_in[14], *e0B1 = (const float*)d_in[15];
    const float* e0W2 = (const float*)d_in[16], *e0G2 = (const float*)d_in[17], *e0B2 = (const float*)d_in[18];
    const float* e1W1 = (const float*)d_in[19], *e1G1 = (const float*)d_in[20], *e1B1 = (const float*)d_in[21];
    const float* e1W2 = (const float*)d_in[22], *e1G2 = (const float*)d_in[23], *e1B2 = (const float*)d_in[24];
    const float* e2W1 = (const float*)d_in[25], *e2G1 = (const float*)d_in[26], *e2B1 = (const float*)d_in[27];
    const float* e2W2 = (const float*)d_in[28], *e2G2 = (const float*)d_in[29], *e2B2 = (const float*)d_in[30];

    float* out_node = (float*)d_out;
    float* out_edge = out_node + (size_t)NN * HH;

    cudaFuncSetAttribute(gemm_a16, cudaFuncAttributeMaxDynamicSharedMemorySize, GSMEM16);
    cudaFuncSetAttribute(gemm_a32, cudaFuncAttributeMaxDynamicSharedMemorySize, GSMEM32);

    float *S, *Hb, *Y, *Y2;
    __nv_bfloat16 *AHI, *ALO, *Whi, *Wlo;
    cudaGetSymbolAddress((void**)&S,  g_S);
    cudaGetSymbolAddress((void**)&Hb, g_Hb);
    cudaGetSymbolAddress((void**)&Y,  g_Y);
    cudaGetSymbolAddress((void**)&Y2, g_Y2);
    cudaGetSymbolAddress((void**)&AHI, g_AHI);
    cudaGetSymbolAddress((void**)&ALO, g_ALO);
    cudaGetSymbolAddress((void**)&Whi, g_Whi);
    cudaGetSymbolAddress((void**)&Wlo, g_Wlo);

    const int EV = NE * 32;
    const int NV = NN * 32;
    const float RinvE = 1.0f / (float)NE;
    const float RinvN = 1.0f / (float)NN;
    const unsigned gyE = (unsigned)cdivl(NE, 128);
    const unsigned gyN = (unsigned)cdivl(NN, 128);

    init_all<<<(unsigned)cdivl(INIT_TOTAL, 256), 256>>>(e0W1, e0W2, e1W1, e2W1,
                                                        e1W2, e2W2, nW1, nW2);
    scatter_edge<<<(unsigned)cdivl(EV, 256), 256>>>(edge_rep, src, dst, S);
    build_x0<<<(unsigned)cdivl(EV, 256), 256>>>(node_rep, S, src, dst, AHI, ALO);

    gemm_a16<<<dim3(2, gyE), 256, GSMEM16>>>(AHI, ALO, H2, Whi + OFF_E0W1, Wlo + OFF_E0W1,
                                             Hb, 512, NE, H2, 0);
    gemm_a32<<<dim3(1, gyE), 256, GSMEM32>>>(Hb, 512, Whi + OFF_E0W2, Wlo + OFF_E0W2,
                                             Y, 128, NE, H2, 0, 1, e0G1, e0B1, RinvE);
    make_edge_new<<<(unsigned)cdivl(EV, 256), 256>>>(Y, edge_rep, eps1, 1, e0G2, e0B2,
                                                     RinvE, AHI, ALO);
    gemm_a16<<<dim3(4, gyE), 256, GSMEM16>>>(AHI, ALO, HH, Whi + OFF_E1W1, Wlo + OFF_E1W1,
                                             Hb, 512, NE, HH, 2);
    gemm_a32<<<dim3(1, gyE), 256, GSMEM32>>>(Hb, 512, Whi + OFF_E1W2, Wlo + OFF_E1W2,
                                             Y, 128, NE, H2, 2, 4, e1G1, e1B1, RinvE);
    gemm_a32<<<dim3(1, gyE), 256, GSMEM32>>>(Hb + 256, 512, Whi + OFF_E2W2, Wlo + OFF_E2W2,
                                             Y2, 128, NE, H2, 3, 5, e2G1, e2B1, RinvE);
    apply_out<<<(unsigned)cdivl(EV, 256), 256>>>(Y, out_edge, EV, 4, e1G2, e1B2, RinvE);
    zero_f4<<<(unsigned)cdivl((long)NN * HH / 4, 256), 256>>>((float4*)S, NN * HH / 4);
    scatter_bnrelu<<<(unsigned)cdivl(EV, 256), 256>>>(Y2, src, dst, S, 5, e2G2, e2B2, RinvE);
    make_node_in<<<(unsigned)cdivl(NV, 256), 256>>>(node_rep, degree, S, eps2, AHI, ALO);
    gemm_a16<<<dim3(2, gyN), 256, GSMEM16>>>(AHI, ALO, HH, Whi + OFF_NW1, Wlo + OFF_NW1,
                                             Hb, 512, NN, HH, 6);
    gemm_a32<<<dim3(1, gyN), 256, GSMEM32>>>(Hb, 512, Whi + OFF_NW2, Wlo + OFF_NW2,
                                             Y, 128, NN, H2, 6, 7, nG1, nB1, RinvN);
    apply_out<<<(unsigned)cdivl(NV, 256), 256>>>(Y, out_node, NV, 7, nG2, nB2, RinvN);
}